// round 7
// baseline (speedup 1.0000x reference)
#include <cuda_runtime.h>
#include <cuda_bf16.h>
#include <cstdint>

// ---------------------------------------------------------------------------
// Problem constants
// ---------------------------------------------------------------------------
#define B_  2
#define S_  1024
#define D_  768
#define H_  12
#define DH_ 64
#define M_  64
#define DFF_ 3072
#define NT_ (B_ * S_)          // 2048 tokens
#define QKV_ (3 * D_)          // 2304
#define NCH 8                  // scan chunks
#define CHL (S_ / NCH)         // 128 steps per chunk

typedef __nv_bfloat16 bf16;

// ---------------------------------------------------------------------------
// Scratch (__device__ globals; no allocation allowed)
// ---------------------------------------------------------------------------
__device__ bf16  g_a_hi [NT_ * D_];
__device__ bf16  g_a_lo [NT_ * D_];
__device__ float g_qkv  [NT_ * QKV_];
__device__ float g_phiq [B_ * H_ * S_ * M_];
__device__ float g_phik [B_ * H_ * S_ * M_];
__device__ bf16  g_at_hi[NT_ * D_];
__device__ bf16  g_at_lo[NT_ * D_];
__device__ float g_x1   [NT_ * D_];
__device__ bf16  g_h_hi [NT_ * D_];
__device__ bf16  g_h_lo [NT_ * D_];
__device__ bf16  g_ff_hi[NT_ * DFF_];
__device__ bf16  g_ff_lo[NT_ * DFF_];
// split-K partial buffers
__device__ float g_sp0  [NT_ * D_];
__device__ float g_sp1  [NT_ * D_];
// scan chunk totals
__device__ float g_kvt  [B_ * H_ * NCH * M_ * DH_];
__device__ float g_kst  [B_ * H_ * NCH * M_];
// transposed, split weights: Wt[n][k] = W[k][n]
__device__ bf16  g_wA_hi[QKV_ * D_];
__device__ bf16  g_wA_lo[QKV_ * D_];
__device__ bf16  g_wP_hi[D_ * D_];
__device__ bf16  g_wP_lo[D_ * D_];
__device__ bf16  g_wF_hi[DFF_ * D_];
__device__ bf16  g_wF_lo[DFF_ * D_];
__device__ bf16  g_wO_hi[D_ * DFF_];
__device__ bf16  g_wO_lo[D_ * DFF_];

// ---------------------------------------------------------------------------
// Small helpers
// ---------------------------------------------------------------------------
__device__ __forceinline__ uint32_t smem_to_u32(const void* p) {
    uint32_t a;
    asm("{ .reg .u64 t; cvta.to.shared.u64 t, %1; cvt.u32.u64 %0, t; }"
        : "=r"(a) : "l"(p));
    return a;
}

__device__ __forceinline__ void split_bf16(float v, bf16& hi, bf16& lo) {
    hi = __float2bfloat16(v);
    lo = __float2bfloat16(v - __bfloat162float(hi));
}

__device__ __forceinline__ float gelu_tanh(float x)
{
    float x3 = x * x * x;
    float u  = 0.7978845608028654f * (x + 0.044715f * x3);
    return 0.5f * x * (1.0f + tanhf(u));
}

__device__ __forceinline__ void cp_async16(uint32_t saddr, const void* gaddr) {
    asm volatile("cp.async.cg.shared.global [%0], [%1], 16;"
                 :: "r"(saddr), "l"(gaddr));
}
__device__ __forceinline__ void cp_commit() {
    asm volatile("cp.async.commit_group;");
}
template<int N>
__device__ __forceinline__ void cp_wait() {
    asm volatile("cp.async.wait_group %0;" :: "n"(N));
}

__device__ __forceinline__ void ldmx4(uint32_t* r, uint32_t addr) {
    asm volatile("ldmatrix.sync.aligned.m8n8.x4.shared.b16 {%0,%1,%2,%3}, [%4];"
                 : "=r"(r[0]), "=r"(r[1]), "=r"(r[2]), "=r"(r[3]) : "r"(addr));
}

__device__ __forceinline__ void mma16816(float* c, const uint32_t* a,
                                         uint32_t b0, uint32_t b1) {
    asm volatile(
        "mma.sync.aligned.m16n8k16.row.col.f32.bf16.bf16.f32 "
        "{%0,%1,%2,%3}, {%4,%5,%6,%7}, {%8,%9}, {%0,%1,%2,%3};"
        : "+f"(c[0]), "+f"(c[1]), "+f"(c[2]), "+f"(c[3])
        : "r"(a[0]), "r"(a[1]), "r"(a[2]), "r"(a[3]), "r"(b0), "r"(b1));
}

// ---------------------------------------------------------------------------
// LayerNorm -> bf16 hi/lo split output
// ---------------------------------------------------------------------------
__global__ void ln_kernel(const float* __restrict__ x,
                          const float* __restrict__ g,
                          const float* __restrict__ b,
                          bf16* __restrict__ ohi, bf16* __restrict__ olo)
{
    int row = blockIdx.x;
    int t   = threadIdx.x;
    const float* xr = x + (size_t)row * D_;

    float v0 = xr[t], v1 = xr[t + 256], v2 = xr[t + 512];
    float s  = v0 + v1 + v2;
    float sq = v0 * v0 + v1 * v1 + v2 * v2;

    #pragma unroll
    for (int off = 16; off; off >>= 1) {
        s  += __shfl_xor_sync(0xffffffffu, s,  off);
        sq += __shfl_xor_sync(0xffffffffu, sq, off);
    }
    __shared__ float red[16];
    int w = t >> 5, l = t & 31;
    if (l == 0) { red[w] = s; red[w + 8] = sq; }
    __syncthreads();
    s = 0.f; sq = 0.f;
    #pragma unroll
    for (int i = 0; i < 8; i++) { s += red[i]; sq += red[8 + i]; }

    const float inv = 1.0f / (float)D_;
    float mean = s * inv;
    float var  = sq * inv - mean * mean;
    float rs   = rsqrtf(var + 1e-5f);

    size_t base = (size_t)row * D_;
    float vv[3] = {v0, v1, v2};
    #pragma unroll
    for (int i = 0; i < 3; i++) {
        int c = t + i * 256;
        float v = (vv[i] - mean) * rs * g[c] + b[c];
        bf16 hi, lo; split_bf16(v, hi, lo);
        ohi[base + c] = hi; olo[base + c] = lo;
    }
}

// ---------------------------------------------------------------------------
// Weight transpose + bf16 split:  T[n][k] = W[k][n]
// ---------------------------------------------------------------------------
__global__ void wconv_kernel(const float* __restrict__ W,
                             bf16* __restrict__ Thi, bf16* __restrict__ Tlo,
                             int K, int N)
{
    __shared__ float tile[32][33];
    int n0 = blockIdx.x * 32, k0 = blockIdx.y * 32;
    int tx = threadIdx.x, ty = threadIdx.y;
    #pragma unroll
    for (int i = 0; i < 4; i++)
        tile[ty + i * 8][tx] = W[(size_t)(k0 + ty + i * 8) * N + n0 + tx];
    __syncthreads();
    #pragma unroll
    for (int i = 0; i < 4; i++) {
        float v = tile[tx][ty + i * 8];
        size_t idx = (size_t)(n0 + ty + i * 8) * K + k0 + tx;
        bf16 hi, lo; split_bf16(v, hi, lo);
        Thi[idx] = hi; Tlo[idx] = lo;
    }
}

// ---------------------------------------------------------------------------
// HMMA 3xBF16-split GEMM. CTA 128x128, BKC=64 slab, double-buffered.
// SPLITK=2: blockIdx.z selects K half; raw f32 partials to Cp0/Cp1.
// ---------------------------------------------------------------------------
#define BM 128
#define BN 128
#define BKC 64
#define LDT 72                          // padded row (bf16) = 144B
#define TILE_BYTES (BM * LDT * 2)       // 18432
#define STAGE_BYTES (4 * TILE_BYTES)    // 73728
#define GEMM_SMEM (2 * STAGE_BYTES)     // 147456

template<int RES, int GELU, int OUTBF, int SPLITK>
__global__ void __launch_bounds__(256)
gemm_mma(const bf16* __restrict__ Ahi, const bf16* __restrict__ Alo,
         const bf16* __restrict__ Bhi, const bf16* __restrict__ Blo,
         const float* __restrict__ bias, const float* __restrict__ res,
         float* __restrict__ Cf, float* __restrict__ Cp1,
         bf16* __restrict__ Chi, bf16* __restrict__ Clo,
         int K, int N)
{
    extern __shared__ char smem[];
    const uint32_t sbase = smem_to_u32(smem);

    const int tid  = threadIdx.x;
    const int lane = tid & 31;
    const int w    = tid >> 5;
    const int wr   = w & 3;
    const int wc   = w >> 2;
    const int bm   = blockIdx.x * BM;
    const int bn   = blockIdx.y * BN;
    const int Keff = K / SPLITK;
    const int kbase = (SPLITK > 1) ? (int)blockIdx.z * Keff : 0;

    float acc[2][8][4];
    #pragma unroll
    for (int i = 0; i < 2; i++)
        #pragma unroll
        for (int j = 0; j < 8; j++)
            #pragma unroll
            for (int q = 0; q < 4; q++) acc[i][j][q] = 0.f;

    const int NC = Keff / BKC;

    const int lrow = tid >> 1;                 // 0..127
    const int lcolb = (tid & 1) * 64;          // byte offset within 128B row
    const uint32_t lsm = (uint32_t)(lrow * LDT * 2) + (uint32_t)lcolb;

    auto issue = [&](int c, int st) {
        int k0 = kbase + c * BKC + (tid & 1) * 32;
        const bf16* srcs[4] = {
            Ahi + (size_t)(bm + lrow) * K + k0,
            Alo + (size_t)(bm + lrow) * K + k0,
            Bhi + (size_t)(bn + lrow) * K + k0,
            Blo + (size_t)(bn + lrow) * K + k0 };
        uint32_t sb = sbase + (uint32_t)st * STAGE_BYTES + lsm;
        #pragma unroll
        for (int i = 0; i < 4; i++) {
            uint32_t base = sb + (uint32_t)i * TILE_BYTES;
            #pragma unroll
            for (int j = 0; j < 4; j++)
                cp_async16(base + (uint32_t)j * 16u, srcs[i] + j * 8);
        }
    };

    issue(0, 0);
    cp_commit();

    const uint32_t aoff = (uint32_t)((wr * 32 + (lane & 15)) * LDT + (lane >> 4) * 8) * 2u;
    const uint32_t boff = (uint32_t)((wc * 64 + (lane & 7) + ((lane >> 4) & 1) * 8) * LDT
                                     + ((lane >> 3) & 1) * 8) * 2u;

    for (int c = 0; c < NC; c++) {
        if (c + 1 < NC) { issue(c + 1, (c + 1) & 1); cp_commit(); cp_wait<1>(); }
        else            { cp_wait<0>(); }
        __syncthreads();

        const uint32_t st = sbase + (uint32_t)(c & 1) * STAGE_BYTES;
        #pragma unroll
        for (int ks = 0; ks < 4; ks++) {
            const uint32_t ko = (uint32_t)(ks * 16) * 2u;
            uint32_t ah[2][4], al[2][4], bh[4][4], bl[4][4];
            #pragma unroll
            for (int mt = 0; mt < 2; mt++) {
                uint32_t ro = aoff + (uint32_t)(mt * 16 * LDT) * 2u + ko;
                ldmx4(ah[mt], st + ro);
                ldmx4(al[mt], st + TILE_BYTES + ro);
            }
            #pragma unroll
            for (int np = 0; np < 4; np++) {
                uint32_t ro = boff + (uint32_t)(np * 16 * LDT) * 2u + ko;
                ldmx4(bh[np], st + 2u * TILE_BYTES + ro);
                ldmx4(bl[np], st + 3u * TILE_BYTES + ro);
            }
            #pragma unroll
            for (int mt = 0; mt < 2; mt++)
                #pragma unroll
                for (int nt = 0; nt < 8; nt++) {
                    const int np = nt >> 1, half = (nt & 1) * 2;
                    mma16816(acc[mt][nt], ah[mt], bh[np][half], bh[np][half + 1]);
                    mma16816(acc[mt][nt], ah[mt], bl[np][half], bl[np][half + 1]);
                    mma16816(acc[mt][nt], al[mt], bh[np][half], bh[np][half + 1]);
                }
        }
        __syncthreads();
    }

    // epilogue
    const int g  = lane >> 2;
    const int tg = lane & 3;
    float* Cpart = (SPLITK > 1) ? (blockIdx.z ? Cp1 : Cf) : Cf;
    #pragma unroll
    for (int mt = 0; mt < 2; mt++) {
        #pragma unroll
        for (int nt = 0; nt < 8; nt++) {
            int col = bn + wc * 64 + nt * 8 + tg * 2;
            float2 bv = (SPLITK > 1) ? make_float2(0.f, 0.f)
                                     : *(const float2*)(bias + col);
            #pragma unroll
            for (int half = 0; half < 2; half++) {
                int row = bm + wr * 32 + mt * 16 + g + half * 8;
                float v0 = acc[mt][nt][half * 2 + 0] + bv.x;
                float v1 = acc[mt][nt][half * 2 + 1] + bv.y;
                size_t idx = (size_t)row * N + col;
                if (RES && SPLITK == 1) {
                    float2 rv = *(const float2*)(res + idx);
                    v0 += rv.x; v1 += rv.y;
                }
                if (GELU) { v0 = gelu_tanh(v0); v1 = gelu_tanh(v1); }
                if (OUTBF) {
                    bf16 h0, l0, h1, l1;
                    split_bf16(v0, h0, l0); split_bf16(v1, h1, l1);
                    *(__nv_bfloat162*)(Chi + idx) = __nv_bfloat162{h0, h1};
                    *(__nv_bfloat162*)(Clo + idx) = __nv_bfloat162{l0, l1};
                } else {
                    *(float2*)(Cpart + idx) = make_float2(v0, v1);
                }
            }
        }
    }
}

// ---------------------------------------------------------------------------
// Split-K reduction: out = p0 + p1 + bias + res   (f32, N = 768 cols)
// ---------------------------------------------------------------------------
__global__ void addred_kernel(const float* __restrict__ p0,
                              const float* __restrict__ p1,
                              const float* __restrict__ bias,
                              const float* __restrict__ res,
                              float* __restrict__ o)
{
    int i = (blockIdx.x * 256 + threadIdx.x);          // float4 index
    int col4 = i % (D_ / 4);
    float4 a = ((const float4*)p0)[i];
    float4 b = ((const float4*)p1)[i];
    float4 c = ((const float4*)bias)[col4];
    float4 r = ((const float4*)res)[i];
    float4 v;
    v.x = a.x + b.x + c.x + r.x;
    v.y = a.y + b.y + c.y + r.y;
    v.z = a.z + b.z + c.z + r.z;
    v.w = a.w + b.w + c.w + r.w;
    ((float4*)o)[i] = v;
}

// ---------------------------------------------------------------------------
// FAVOR+ features (fp32, reads qkv)
// ---------------------------------------------------------------------------
__global__ void phi_kernel(const float* __restrict__ qkv,
                           const float* __restrict__ wfeat,
                           float* __restrict__ phiq,
                           float* __restrict__ phik)
{
    const int sc = blockIdx.x;
    const int hy = blockIdx.y;
    const int b  = blockIdx.z;
    const int h  = hy % H_;
    const int qk = hy / H_;

    __shared__ float wfT[64][65];
    __shared__ float xs[32][64];
    __shared__ float sqs[32];

    const int t = threadIdx.x;

    #pragma unroll
    for (int i = 0; i < 16; i++) {
        int idx = t + i * 256;
        wfT[idx & 63][idx >> 6] = wfeat[idx];
    }

    const float scale = 0.3535533905932738f;
    const int s0   = sc * 32;
    const int col0 = qk * D_ + h * DH_;

    #pragma unroll
    for (int i = 0; i < 8; i++) {
        int idx = t + i * 256;
        int sl = idx >> 6, d = idx & 63;
        xs[sl][d] = qkv[(size_t)(b * S_ + s0 + sl) * QKV_ + col0 + d] * scale;
    }
    __syncthreads();

    {
        int sl = t >> 3, p = t & 7;
        float acc = 0.f;
        #pragma unroll
        for (int dd = 0; dd < 8; dd++) {
            float xv = xs[sl][p * 8 + dd];
            acc = fmaf(xv, xv, acc);
        }
        acc += __shfl_xor_sync(0xffffffffu, acc, 1);
        acc += __shfl_xor_sync(0xffffffffu, acc, 2);
        acc += __shfl_xor_sync(0xffffffffu, acc, 4);
        if (p == 0) sqs[sl] = 0.5f * acc;
    }
    __syncthreads();

    float* dst = qk ? phik : phiq;
    #pragma unroll
    for (int i = 0; i < 8; i++) {
        int idx = t + i * 256;
        int sl = idx >> 6, m = idx & 63;
        float acc = 0.f;
        #pragma unroll
        for (int d = 0; d < 64; d++)
            acc = fmaf(xs[sl][d], wfT[d][m], acc);
        float ph = __expf(acc - sqs[sl]) * 0.125f + 1e-6f;
        dst[(size_t)((b * H_ + h) * S_ + s0 + sl) * M_ + m] = ph;
    }
}

// ---------------------------------------------------------------------------
// Scan pass 1: per-(bh, chunk) totals of phik (x) v and phik.
// ---------------------------------------------------------------------------
__global__ void scan_tot_kernel(const float* __restrict__ qkv,
                                const float* __restrict__ phik,
                                float* __restrict__ kvt,
                                float* __restrict__ kst)
{
    const int bc = blockIdx.x;
    const int bh = bc / NCH;
    const int ch = bc % NCH;
    const int b  = bh / H_;
    const int h  = bh % H_;
    const int t  = threadIdx.x;
    const int d  = t >> 2;
    const int mg = t & 3;

    float kv[16], ks[16];
    #pragma unroll
    for (int i = 0; i < 16; i++) { kv[i] = 0.f; ks[i] = 0.f; }

    const int s0 = ch * CHL;
    const float* pk = phik + (size_t)bh * S_ * M_ + (size_t)s0 * M_ + mg * 16;
    const float* pv = qkv  + (size_t)(b * S_ + s0) * QKV_ + 2 * D_ + h * DH_ + d;

    for (int s = 0; s < CHL; s++) {
        const float4* pk4 = (const float4*)pk;
        float kr[16];
        ((float4*)kr)[0] = pk4[0]; ((float4*)kr)[1] = pk4[1];
        ((float4*)kr)[2] = pk4[2]; ((float4*)kr)[3] = pk4[3];
        float vv = *pv;
        #pragma unroll
        for (int i = 0; i < 16; i++) {
            kv[i] = fmaf(kr[i], vv, kv[i]);
            ks[i] += kr[i];
        }
        pk += M_; pv += QKV_;
    }

    size_t base = (size_t)bc * M_ + mg * 16;
    #pragma unroll
    for (int i = 0; i < 16; i++) {
        kvt[(base + i) * DH_ + d] = kv[i];
        if (d == 0) kst[base + i] = ks[i];
    }
}

// ---------------------------------------------------------------------------
// Scan pass 2: local inclusive scan per (bh, chunk), seeded by totals of
// preceding chunks. Output bf16 hi/lo.
// ---------------------------------------------------------------------------
__global__ void scan_kernel(const float* __restrict__ qkv,
                            const float* __restrict__ phiq,
                            const float* __restrict__ phik,
                            const float* __restrict__ kvt,
                            const float* __restrict__ kst,
                            bf16* __restrict__ ahi, bf16* __restrict__ alo)
{
    const int bc = blockIdx.x;
    const int bh = bc / NCH;
    const int ch = bc % NCH;
    const int b  = bh / H_;
    const int h  = bh % H_;
    const int t  = threadIdx.x;
    const int d  = t >> 2;
    const int mg = t & 3;

    float kv[16], ks[16];
    #pragma unroll
    for (int i = 0; i < 16; i++) { kv[i] = 0.f; ks[i] = 0.f; }

    for (int pc = 0; pc < ch; pc++) {
        size_t base = (size_t)(bh * NCH + pc) * M_ + mg * 16;
        #pragma unroll
        for (int i = 0; i < 16; i++) {
            kv[i] += kvt[(base + i) * DH_ + d];
            ks[i] += kst[base + i];
        }
    }

    const int s0 = ch * CHL;
    const float* pq = phiq + (size_t)bh * S_ * M_ + (size_t)s0 * M_ + mg * 16;
    const float* pk = phik + (size_t)bh * S_ * M_ + (size_t)s0 * M_ + mg * 16;
    const float* pv = qkv  + (size_t)(b * S_ + s0) * QKV_ + 2 * D_ + h * DH_ + d;
    size_t obase = (size_t)(b * S_ + s0) * D_ + h * DH_ + d;

    for (int s = 0; s < CHL; s++) {
        const float4* pk4 = (const float4*)pk;
        const float4* pq4 = (const float4*)pq;
        float kr[16], qr[16];
        ((float4*)kr)[0] = pk4[0]; ((float4*)kr)[1] = pk4[1];
        ((float4*)kr)[2] = pk4[2]; ((float4*)kr)[3] = pk4[3];
        ((float4*)qr)[0] = pq4[0]; ((float4*)qr)[1] = pq4[1];
        ((float4*)qr)[2] = pq4[2]; ((float4*)qr)[3] = pq4[3];
        float vv = *pv;

        float num = 0.f, den = 0.f;
        #pragma unroll
        for (int i = 0; i < 16; i++) {
            kv[i] = fmaf(kr[i], vv, kv[i]);
            ks[i] += kr[i];
            num = fmaf(qr[i], kv[i], num);
            den = fmaf(qr[i], ks[i], den);
        }
        num += __shfl_xor_sync(0xffffffffu, num, 1);
        den += __shfl_xor_sync(0xffffffffu, den, 1);
        num += __shfl_xor_sync(0xffffffffu, num, 2);
        den += __shfl_xor_sync(0xffffffffu, den, 2);

        if (mg == 0) {
            float v = num / den;
            bf16 hi, lo; split_bf16(v, hi, lo);
            ahi[obase] = hi;
            alo[obase] = lo;
        }
        pq += M_; pk += M_; pv += QKV_; obase += D_;
    }
}

// ---------------------------------------------------------------------------
// Launch
// ---------------------------------------------------------------------------
extern "C" void kernel_launch(void* const* d_in, const int* in_sizes, int n_in,
                              void* d_out, int out_size)
{
    const float* x      = (const float*)d_in[0];
    const float* ln1_g  = (const float*)d_in[1];
    const float* ln1_b  = (const float*)d_in[2];
    const float* w_attn = (const float*)d_in[3];
    const float* b_attn = (const float*)d_in[4];
    const float* w_feat = (const float*)d_in[5];
    const float* w_proj = (const float*)d_in[6];
    const float* b_proj = (const float*)d_in[7];
    const float* ln2_g  = (const float*)d_in[8];
    const float* ln2_b  = (const float*)d_in[9];
    const float* w_fc   = (const float*)d_in[10];
    const float* b_fc   = (const float*)d_in[11];
    const float* w_out  = (const float*)d_in[12];
    const float* b_out  = (const float*)d_in[13];
    float* out = (float*)d_out;

    bf16 *a_hi, *a_lo, *at_hi, *at_lo, *h_hi, *h_lo, *ff_hi, *ff_lo;
    bf16 *wA_hi, *wA_lo, *wP_hi, *wP_lo, *wF_hi, *wF_lo, *wO_hi, *wO_lo;
    float *qkv, *phiq, *phik, *x1, *kvt, *kst, *sp0, *sp1;
    cudaGetSymbolAddress((void**)&a_hi,  g_a_hi);
    cudaGetSymbolAddress((void**)&a_lo,  g_a_lo);
    cudaGetSymbolAddress((void**)&qkv,   g_qkv);
    cudaGetSymbolAddress((void**)&phiq,  g_phiq);
    cudaGetSymbolAddress((void**)&phik,  g_phik);
    cudaGetSymbolAddress((void**)&at_hi, g_at_hi);
    cudaGetSymbolAddress((void**)&at_lo, g_at_lo);
    cudaGetSymbolAddress((void**)&x1,    g_x1);
    cudaGetSymbolAddress((void**)&h_hi,  g_h_hi);
    cudaGetSymbolAddress((void**)&h_lo,  g_h_lo);
    cudaGetSymbolAddress((void**)&ff_hi, g_ff_hi);
    cudaGetSymbolAddress((void**)&ff_lo, g_ff_lo);
    cudaGetSymbolAddress((void**)&sp0,   g_sp0);
    cudaGetSymbolAddress((void**)&sp1,   g_sp1);
    cudaGetSymbolAddress((void**)&kvt,   g_kvt);
    cudaGetSymbolAddress((void**)&kst,   g_kst);
    cudaGetSymbolAddress((void**)&wA_hi, g_wA_hi);
    cudaGetSymbolAddress((void**)&wA_lo, g_wA_lo);
    cudaGetSymbolAddress((void**)&wP_hi, g_wP_hi);
    cudaGetSymbolAddress((void**)&wP_lo, g_wP_lo);
    cudaGetSymbolAddress((void**)&wF_hi, g_wF_hi);
    cudaGetSymbolAddress((void**)&wF_lo, g_wF_lo);
    cudaGetSymbolAddress((void**)&wO_hi, g_wO_hi);
    cudaGetSymbolAddress((void**)&wO_lo, g_wO_lo);

    cudaFuncSetAttribute(gemm_mma<0,0,0,1>, cudaFuncAttributeMaxDynamicSharedMemorySize, GEMM_SMEM);
    cudaFuncSetAttribute(gemm_mma<1,0,0,2>, cudaFuncAttributeMaxDynamicSharedMemorySize, GEMM_SMEM);
    cudaFuncSetAttribute(gemm_mma<0,1,1,1>, cudaFuncAttributeMaxDynamicSharedMemorySize, GEMM_SMEM);

    dim3 wblk(32, 8);
    wconv_kernel<<<dim3(QKV_/32, D_/32),  wblk>>>(w_attn, wA_hi, wA_lo, D_,  QKV_);
    wconv_kernel<<<dim3(D_/32,   D_/32),  wblk>>>(w_proj, wP_hi, wP_lo, D_,  D_);
    wconv_kernel<<<dim3(DFF_/32, D_/32),  wblk>>>(w_fc,   wF_hi, wF_lo, D_,  DFF_);
    wconv_kernel<<<dim3(D_/32,  DFF_/32), wblk>>>(w_out,  wO_hi, wO_lo, DFF_, D_);

    // 1. LN1 -> a (hi/lo)
    ln_kernel<<<NT_, 256>>>(x, ln1_g, ln1_b, a_hi, a_lo);

    // 2. qkv = a @ w_attn + b_attn   [2048 x 2304], f32 out
    gemm_mma<0,0,0,1><<<dim3(NT_/BM, QKV_/BN), 256, GEMM_SMEM>>>(
        a_hi, a_lo, wA_hi, wA_lo, b_attn, nullptr, qkv, nullptr, nullptr, nullptr, D_, QKV_);

    // 3. FAVOR+ features
    phi_kernel<<<dim3(S_/32, H_*2, B_), 256>>>(qkv, w_feat, phiq, phik);

    // 4. chunked causal scan -> attn (hi/lo)
    scan_tot_kernel<<<B_*H_*NCH, 256>>>(qkv, phik, kvt, kst);
    scan_kernel<<<B_*H_*NCH, 256>>>(qkv, phiq, phik, kvt, kst, at_hi, at_lo);

    // 5. x1 = x + attn @ w_proj + b_proj  (split-K2 + reduce)
    gemm_mma<1,0,0,2><<<dim3(NT_/BM, D_/BN, 2), 256, GEMM_SMEM>>>(
        at_hi, at_lo, wP_hi, wP_lo, b_proj, x, sp0, sp1, nullptr, nullptr, D_, D_);
    addred_kernel<<<(NT_*D_/4)/256, 256>>>(sp0, sp1, b_proj, x, x1);

    // 6. LN2 -> h (hi/lo)
    ln_kernel<<<NT_, 256>>>(x1, ln2_g, ln2_b, h_hi, h_lo);

    // 7. ff = gelu(h @ w_fc + b_fc)   [2048 x 3072], bf16 hi/lo out
    gemm_mma<0,1,1,1><<<dim3(NT_/BM, DFF_/BN), 256, GEMM_SMEM>>>(
        h_hi, h_lo, wF_hi, wF_lo, b_fc, nullptr, nullptr, nullptr, ff_hi, ff_lo, D_, DFF_);

    // 8. out = x1 + ff @ w_out + b_out  (split-K2 + reduce)
    gemm_mma<1,0,0,2><<<dim3(NT_/BM, D_/BN, 2), 256, GEMM_SMEM>>>(
        ff_hi, ff_lo, wO_hi, wO_lo, b_out, x1, sp0, sp1, nullptr, nullptr, DFF_, D_);
    addred_kernel<<<(NT_*D_/4)/256, 256>>>(sp0, sp1, b_out, x1, out);
}

// round 8
// speedup vs baseline: 1.1901x; 1.1901x over previous
#include <cuda_runtime.h>
#include <cuda_bf16.h>
#include <cstdint>

// ---------------------------------------------------------------------------
// Problem constants
// ---------------------------------------------------------------------------
#define B_  2
#define S_  1024
#define D_  768
#define H_  12
#define DH_ 64
#define M_  64
#define DFF_ 3072
#define NT_ (B_ * S_)          // 2048 tokens
#define QKV_ (3 * D_)          // 2304
#define NCH 8                  // scan chunks
#define CHL (S_ / NCH)         // 128 steps per chunk

typedef __nv_bfloat16 bf16;

// ---------------------------------------------------------------------------
// Scratch (__device__ globals; no allocation allowed)
// ---------------------------------------------------------------------------
__device__ bf16  g_a_hi [NT_ * D_];
__device__ bf16  g_a_lo [NT_ * D_];
__device__ float g_qkv  [NT_ * QKV_];
__device__ float g_phiq [B_ * H_ * S_ * M_];
__device__ float g_phik [B_ * H_ * S_ * M_];
__device__ bf16  g_at_hi[NT_ * D_];
__device__ bf16  g_at_lo[NT_ * D_];
__device__ float g_x1   [NT_ * D_];
__device__ bf16  g_h_hi [NT_ * D_];
__device__ bf16  g_h_lo [NT_ * D_];
__device__ bf16  g_ff_hi[NT_ * DFF_];
__device__ bf16  g_ff_lo[NT_ * DFF_];
// split-K partial buffers
__device__ float g_sp0  [NT_ * D_];
__device__ float g_sp1  [NT_ * D_];
__device__ float g_sp2  [NT_ * D_];
// scan chunk totals
__device__ float g_kvt  [B_ * H_ * NCH * M_ * DH_];
__device__ float g_kst  [B_ * H_ * NCH * M_];
// transposed, split weights: Wt[n][k] = W[k][n]
__device__ bf16  g_wA_hi[QKV_ * D_];
__device__ bf16  g_wA_lo[QKV_ * D_];
__device__ bf16  g_wP_hi[D_ * D_];
__device__ bf16  g_wP_lo[D_ * D_];
__device__ bf16  g_wF_hi[DFF_ * D_];
__device__ bf16  g_wF_lo[DFF_ * D_];
__device__ bf16  g_wO_hi[D_ * DFF_];
__device__ bf16  g_wO_lo[D_ * DFF_];

// ---------------------------------------------------------------------------
// Small helpers
// ---------------------------------------------------------------------------
__device__ __forceinline__ uint32_t smem_to_u32(const void* p) {
    uint32_t a;
    asm("{ .reg .u64 t; cvta.to.shared.u64 t, %1; cvt.u32.u64 %0, t; }"
        : "=r"(a) : "l"(p));
    return a;
}

__device__ __forceinline__ void split_bf16(float v, bf16& hi, bf16& lo) {
    hi = __float2bfloat16(v);
    lo = __float2bfloat16(v - __bfloat162float(hi));
}

__device__ __forceinline__ float gelu_tanh(float x)
{
    float x3 = x * x * x;
    float u  = 0.7978845608028654f * (x + 0.044715f * x3);
    return 0.5f * x * (1.0f + tanhf(u));
}

__device__ __forceinline__ void cp_async16(uint32_t saddr, const void* gaddr) {
    asm volatile("cp.async.cg.shared.global [%0], [%1], 16;"
                 :: "r"(saddr), "l"(gaddr));
}
__device__ __forceinline__ void cp_commit() {
    asm volatile("cp.async.commit_group;");
}
template<int N>
__device__ __forceinline__ void cp_wait() {
    asm volatile("cp.async.wait_group %0;" :: "n"(N));
}

__device__ __forceinline__ void ldmx4(uint32_t* r, uint32_t addr) {
    asm volatile("ldmatrix.sync.aligned.m8n8.x4.shared.b16 {%0,%1,%2,%3}, [%4];"
                 : "=r"(r[0]), "=r"(r[1]), "=r"(r[2]), "=r"(r[3]) : "r"(addr));
}

__device__ __forceinline__ void mma16816(float* c, const uint32_t* a,
                                         uint32_t b0, uint32_t b1) {
    asm volatile(
        "mma.sync.aligned.m16n8k16.row.col.f32.bf16.bf16.f32 "
        "{%0,%1,%2,%3}, {%4,%5,%6,%7}, {%8,%9}, {%0,%1,%2,%3};"
        : "+f"(c[0]), "+f"(c[1]), "+f"(c[2]), "+f"(c[3])
        : "r"(a[0]), "r"(a[1]), "r"(a[2]), "r"(a[3]), "r"(b0), "r"(b1));
}

// ---------------------------------------------------------------------------
// LayerNorm -> bf16 hi/lo split output
// ---------------------------------------------------------------------------
__global__ void ln_kernel(const float* __restrict__ x,
                          const float* __restrict__ g,
                          const float* __restrict__ b,
                          bf16* __restrict__ ohi, bf16* __restrict__ olo)
{
    int row = blockIdx.x;
    int t   = threadIdx.x;
    const float* xr = x + (size_t)row * D_;

    float v0 = xr[t], v1 = xr[t + 256], v2 = xr[t + 512];
    float s  = v0 + v1 + v2;
    float sq = v0 * v0 + v1 * v1 + v2 * v2;

    #pragma unroll
    for (int off = 16; off; off >>= 1) {
        s  += __shfl_xor_sync(0xffffffffu, s,  off);
        sq += __shfl_xor_sync(0xffffffffu, sq, off);
    }
    __shared__ float red[16];
    int w = t >> 5, l = t & 31;
    if (l == 0) { red[w] = s; red[w + 8] = sq; }
    __syncthreads();
    s = 0.f; sq = 0.f;
    #pragma unroll
    for (int i = 0; i < 8; i++) { s += red[i]; sq += red[8 + i]; }

    const float inv = 1.0f / (float)D_;
    float mean = s * inv;
    float var  = sq * inv - mean * mean;
    float rs   = rsqrtf(var + 1e-5f);

    size_t base = (size_t)row * D_;
    float vv[3] = {v0, v1, v2};
    #pragma unroll
    for (int i = 0; i < 3; i++) {
        int c = t + i * 256;
        float v = (vv[i] - mean) * rs * g[c] + b[c];
        bf16 hi, lo; split_bf16(v, hi, lo);
        ohi[base + c] = hi; olo[base + c] = lo;
    }
}

// ---------------------------------------------------------------------------
// Fused weight transpose + bf16 split for all 4 weights.
// Flattened tile grid; T[n][k] = W[k][n].
// tiles: wA (N=2304,K=768): 72x24=1728 | wP (768,768): 24x24=576
//        wF (N=3072,K=768): 96x24=2304 | wO (N=768,K=3072): 24x96=2304
// ---------------------------------------------------------------------------
__global__ void wconv_all(const float* __restrict__ wA, const float* __restrict__ wP,
                          const float* __restrict__ wF, const float* __restrict__ wO,
                          bf16* __restrict__ Ahi, bf16* __restrict__ Alo,
                          bf16* __restrict__ Phi, bf16* __restrict__ Plo,
                          bf16* __restrict__ Fhi, bf16* __restrict__ Flo,
                          bf16* __restrict__ Ohi, bf16* __restrict__ Olo)
{
    int t = blockIdx.x;
    const float* W; bf16 *Thi, *Tlo; int K, N, nx;
    if (t < 1728)      { W = wA; Thi = Ahi; Tlo = Alo; K = D_;  N = QKV_; nx = 72; }
    else if (t < 2304) { t -= 1728; W = wP; Thi = Phi; Tlo = Plo; K = D_;  N = D_;   nx = 24; }
    else if (t < 4608) { t -= 2304; W = wF; Thi = Fhi; Tlo = Flo; K = D_;  N = DFF_; nx = 96; }
    else               { t -= 4608; W = wO; Thi = Ohi; Tlo = Olo; K = DFF_; N = D_;  nx = 24; }
    int n0 = (t % nx) * 32, k0 = (t / nx) * 32;

    __shared__ float tile[32][33];
    int tx = threadIdx.x, ty = threadIdx.y;
    #pragma unroll
    for (int i = 0; i < 4; i++)
        tile[ty + i * 8][tx] = W[(size_t)(k0 + ty + i * 8) * N + n0 + tx];
    __syncthreads();
    #pragma unroll
    for (int i = 0; i < 4; i++) {
        float v = tile[tx][ty + i * 8];
        size_t idx = (size_t)(n0 + ty + i * 8) * K + k0 + tx;
        bf16 hi, lo; split_bf16(v, hi, lo);
        Thi[idx] = hi; Tlo[idx] = lo;
    }
}

// ---------------------------------------------------------------------------
// HMMA 3xBF16-split GEMM (round-6 core: BKC=32, 80KB smem, 2 CTAs/SM).
// SPLITK>1: blockIdx.z picks K slice; raw f32 partials to Cp[z].
// ---------------------------------------------------------------------------
#define BM 128
#define BN 128
#define BKC 32
#define LDT 40                         // padded row (bf16) = 80B
#define TILE_BYTES (BM * LDT * 2)      // 10240
#define STAGE_BYTES (4 * TILE_BYTES)   // 40960
#define GEMM_SMEM (2 * STAGE_BYTES)    // 81920

template<int RES, int GELU, int OUTBF, int SPLITK>
__global__ void __launch_bounds__(256)
gemm_mma(const bf16* __restrict__ Ahi, const bf16* __restrict__ Alo,
         const bf16* __restrict__ Bhi, const bf16* __restrict__ Blo,
         const float* __restrict__ bias, const float* __restrict__ res,
         float* __restrict__ Cf, float* __restrict__ Cp1, float* __restrict__ Cp2,
         bf16* __restrict__ Chi, bf16* __restrict__ Clo,
         int K, int N)
{
    extern __shared__ char smem[];
    const uint32_t sbase = smem_to_u32(smem);

    const int tid  = threadIdx.x;
    const int lane = tid & 31;
    const int w    = tid >> 5;
    const int wr   = w & 3;
    const int wc   = w >> 2;
    const int bm   = blockIdx.x * BM;
    const int bn   = blockIdx.y * BN;
    const int Keff = K / SPLITK;
    const int kbase = (SPLITK > 1) ? (int)blockIdx.z * Keff : 0;

    float acc[2][8][4];
    #pragma unroll
    for (int i = 0; i < 2; i++)
        #pragma unroll
        for (int j = 0; j < 8; j++)
            #pragma unroll
            for (int q = 0; q < 4; q++) acc[i][j][q] = 0.f;

    const int NC = Keff / BKC;

    const int lrow = tid >> 1;
    const int lseg = (tid & 1) * 2;
    const uint32_t lsm = (uint32_t)(lrow * LDT + lseg * 8) * 2u;

    auto issue = [&](int c, int st) {
        int k0 = kbase + c * BKC;
        const bf16* srcs[4] = {
            Ahi + (size_t)(bm + lrow) * K + k0 + lseg * 8,
            Alo + (size_t)(bm + lrow) * K + k0 + lseg * 8,
            Bhi + (size_t)(bn + lrow) * K + k0 + lseg * 8,
            Blo + (size_t)(bn + lrow) * K + k0 + lseg * 8 };
        uint32_t sb = sbase + (uint32_t)st * STAGE_BYTES + lsm;
        #pragma unroll
        for (int i = 0; i < 4; i++) {
            cp_async16(sb + (uint32_t)i * TILE_BYTES,       srcs[i]);
            cp_async16(sb + (uint32_t)i * TILE_BYTES + 16u, srcs[i] + 8);
        }
    };

    issue(0, 0);
    cp_commit();

    const uint32_t aoff = (uint32_t)((wr * 32 + (lane & 15)) * LDT + (lane >> 4) * 8) * 2u;
    const uint32_t boff = (uint32_t)((wc * 64 + (lane & 7) + ((lane >> 4) & 1) * 8) * LDT
                                     + ((lane >> 3) & 1) * 8) * 2u;

    for (int c = 0; c < NC; c++) {
        if (c + 1 < NC) { issue(c + 1, (c + 1) & 1); cp_commit(); cp_wait<1>(); }
        else            { cp_wait<0>(); }
        __syncthreads();

        const uint32_t st = sbase + (uint32_t)(c & 1) * STAGE_BYTES;
        #pragma unroll
        for (int ks = 0; ks < 2; ks++) {
            const uint32_t ko = (uint32_t)(ks * 16) * 2u;
            uint32_t ah[2][4], al[2][4], bh[4][4], bl[4][4];
            #pragma unroll
            for (int mt = 0; mt < 2; mt++) {
                uint32_t ro = aoff + (uint32_t)(mt * 16 * LDT) * 2u + ko;
                ldmx4(ah[mt], st + ro);
                ldmx4(al[mt], st + TILE_BYTES + ro);
            }
            #pragma unroll
            for (int np = 0; np < 4; np++) {
                uint32_t ro = boff + (uint32_t)(np * 16 * LDT) * 2u + ko;
                ldmx4(bh[np], st + 2u * TILE_BYTES + ro);
                ldmx4(bl[np], st + 3u * TILE_BYTES + ro);
            }
            #pragma unroll
            for (int mt = 0; mt < 2; mt++)
                #pragma unroll
                for (int nt = 0; nt < 8; nt++) {
                    const int np = nt >> 1, half = (nt & 1) * 2;
                    mma16816(acc[mt][nt], ah[mt], bh[np][half], bh[np][half + 1]);
                    mma16816(acc[mt][nt], ah[mt], bl[np][half], bl[np][half + 1]);
                    mma16816(acc[mt][nt], al[mt], bh[np][half], bh[np][half + 1]);
                }
        }
        __syncthreads();
    }

    // epilogue
    const int g  = lane >> 2;
    const int tg = lane & 3;
    float* Cpart = Cf;
    if (SPLITK > 1) Cpart = (blockIdx.z == 0) ? Cf : (blockIdx.z == 1 ? Cp1 : Cp2);
    #pragma unroll
    for (int mt = 0; mt < 2; mt++) {
        #pragma unroll
        for (int nt = 0; nt < 8; nt++) {
            int col = bn + wc * 64 + nt * 8 + tg * 2;
            float2 bv = (SPLITK > 1) ? make_float2(0.f, 0.f)
                                     : *(const float2*)(bias + col);
            #pragma unroll
            for (int half = 0; half < 2; half++) {
                int row = bm + wr * 32 + mt * 16 + g + half * 8;
                float v0 = acc[mt][nt][half * 2 + 0] + bv.x;
                float v1 = acc[mt][nt][half * 2 + 1] + bv.y;
                size_t idx = (size_t)row * N + col;
                if (RES && SPLITK == 1) {
                    float2 rv = *(const float2*)(res + idx);
                    v0 += rv.x; v1 += rv.y;
                }
                if (GELU) { v0 = gelu_tanh(v0); v1 = gelu_tanh(v1); }
                if (OUTBF) {
                    bf16 h0, l0, h1, l1;
                    split_bf16(v0, h0, l0); split_bf16(v1, h1, l1);
                    *(__nv_bfloat162*)(Chi + idx) = __nv_bfloat162{h0, h1};
                    *(__nv_bfloat162*)(Clo + idx) = __nv_bfloat162{l0, l1};
                } else {
                    *(float2*)(Cpart + idx) = make_float2(v0, v1);
                }
            }
        }
    }
}

// ---------------------------------------------------------------------------
// Split-K3 reduction: o = p0 + p1 + p2 + bias + res   (f32, 768 cols)
// ---------------------------------------------------------------------------
__global__ void addred3_kernel(const float* __restrict__ p0,
                               const float* __restrict__ p1,
                               const float* __restrict__ p2,
                               const float* __restrict__ bias,
                               const float* __restrict__ res,
                               float* __restrict__ o)
{
    int i = (blockIdx.x * 256 + threadIdx.x);
    int col4 = i % (D_ / 4);
    float4 a = ((const float4*)p0)[i];
    float4 b = ((const float4*)p1)[i];
    float4 c = ((const float4*)p2)[i];
    float4 d = ((const float4*)bias)[col4];
    float4 r = ((const float4*)res)[i];
    float4 v;
    v.x = a.x + b.x + c.x + d.x + r.x;
    v.y = a.y + b.y + c.y + d.y + r.y;
    v.z = a.z + b.z + c.z + d.z + r.z;
    v.w = a.w + b.w + c.w + d.w + r.w;
    ((float4*)o)[i] = v;
}

// ---------------------------------------------------------------------------
// FAVOR+ features (fp32, reads qkv)
// ---------------------------------------------------------------------------
__global__ void phi_kernel(const float* __restrict__ qkv,
                           const float* __restrict__ wfeat,
                           float* __restrict__ phiq,
                           float* __restrict__ phik)
{
    const int sc = blockIdx.x;
    const int hy = blockIdx.y;
    const int b  = blockIdx.z;
    const int h  = hy % H_;
    const int qk = hy / H_;

    __shared__ float wfT[64][65];
    __shared__ float xs[32][64];
    __shared__ float sqs[32];

    const int t = threadIdx.x;

    #pragma unroll
    for (int i = 0; i < 16; i++) {
        int idx = t + i * 256;
        wfT[idx & 63][idx >> 6] = wfeat[idx];
    }

    const float scale = 0.3535533905932738f;
    const int s0   = sc * 32;
    const int col0 = qk * D_ + h * DH_;

    #pragma unroll
    for (int i = 0; i < 8; i++) {
        int idx = t + i * 256;
        int sl = idx >> 6, d = idx & 63;
        xs[sl][d] = qkv[(size_t)(b * S_ + s0 + sl) * QKV_ + col0 + d] * scale;
    }
    __syncthreads();

    {
        int sl = t >> 3, p = t & 7;
        float acc = 0.f;
        #pragma unroll
        for (int dd = 0; dd < 8; dd++) {
            float xv = xs[sl][p * 8 + dd];
            acc = fmaf(xv, xv, acc);
        }
        acc += __shfl_xor_sync(0xffffffffu, acc, 1);
        acc += __shfl_xor_sync(0xffffffffu, acc, 2);
        acc += __shfl_xor_sync(0xffffffffu, acc, 4);
        if (p == 0) sqs[sl] = 0.5f * acc;
    }
    __syncthreads();

    float* dst = qk ? phik : phiq;
    #pragma unroll
    for (int i = 0; i < 8; i++) {
        int idx = t + i * 256;
        int sl = idx >> 6, m = idx & 63;
        float acc = 0.f;
        #pragma unroll
        for (int d = 0; d < 64; d++)
            acc = fmaf(xs[sl][d], wfT[d][m], acc);
        float ph = __expf(acc - sqs[sl]) * 0.125f + 1e-6f;
        dst[(size_t)((b * H_ + h) * S_ + s0 + sl) * M_ + m] = ph;
    }
}

// ---------------------------------------------------------------------------
// Scan pass 1: per-(bh, chunk) totals of phik (x) v and phik.
// ---------------------------------------------------------------------------
__global__ void scan_tot_kernel(const float* __restrict__ qkv,
                                const float* __restrict__ phik,
                                float* __restrict__ kvt,
                                float* __restrict__ kst)
{
    const int bc = blockIdx.x;
    const int bh = bc / NCH;
    const int ch = bc % NCH;
    const int b  = bh / H_;
    const int h  = bh % H_;
    const int t  = threadIdx.x;
    const int d  = t >> 2;
    const int mg = t & 3;

    float kv[16], ks[16];
    #pragma unroll
    for (int i = 0; i < 16; i++) { kv[i] = 0.f; ks[i] = 0.f; }

    const int s0 = ch * CHL;
    const float* pk = phik + (size_t)bh * S_ * M_ + (size_t)s0 * M_ + mg * 16;
    const float* pv = qkv  + (size_t)(b * S_ + s0) * QKV_ + 2 * D_ + h * DH_ + d;

    for (int s = 0; s < CHL; s++) {
        const float4* pk4 = (const float4*)pk;
        float kr[16];
        ((float4*)kr)[0] = pk4[0]; ((float4*)kr)[1] = pk4[1];
        ((float4*)kr)[2] = pk4[2]; ((float4*)kr)[3] = pk4[3];
        float vv = *pv;
        #pragma unroll
        for (int i = 0; i < 16; i++) {
            kv[i] = fmaf(kr[i], vv, kv[i]);
            ks[i] += kr[i];
        }
        pk += M_; pv += QKV_;
    }

    size_t base = (size_t)bc * M_ + mg * 16;
    #pragma unroll
    for (int i = 0; i < 16; i++) {
        kvt[(base + i) * DH_ + d] = kv[i];
        if (d == 0) kst[base + i] = ks[i];
    }
}

// ---------------------------------------------------------------------------
// Scan pass 2: local inclusive scan per (bh, chunk), seeded by totals of
// preceding chunks. Output bf16 hi/lo.
// ---------------------------------------------------------------------------
__global__ void scan_kernel(const float* __restrict__ qkv,
                            const float* __restrict__ phiq,
                            const float* __restrict__ phik,
                            const float* __restrict__ kvt,
                            const float* __restrict__ kst,
                            bf16* __restrict__ ahi, bf16* __restrict__ alo)
{
    const int bc = blockIdx.x;
    const int bh = bc / NCH;
    const int ch = bc % NCH;
    const int b  = bh / H_;
    const int h  = bh % H_;
    const int t  = threadIdx.x;
    const int d  = t >> 2;
    const int mg = t & 3;

    float kv[16], ks[16];
    #pragma unroll
    for (int i = 0; i < 16; i++) { kv[i] = 0.f; ks[i] = 0.f; }

    for (int pc = 0; pc < ch; pc++) {
        size_t base = (size_t)(bh * NCH + pc) * M_ + mg * 16;
        #pragma unroll
        for (int i = 0; i < 16; i++) {
            kv[i] += kvt[(base + i) * DH_ + d];
            ks[i] += kst[base + i];
        }
    }

    const int s0 = ch * CHL;
    const float* pq = phiq + (size_t)bh * S_ * M_ + (size_t)s0 * M_ + mg * 16;
    const float* pk = phik + (size_t)bh * S_ * M_ + (size_t)s0 * M_ + mg * 16;
    const float* pv = qkv  + (size_t)(b * S_ + s0) * QKV_ + 2 * D_ + h * DH_ + d;
    size_t obase = (size_t)(b * S_ + s0) * D_ + h * DH_ + d;

    for (int s = 0; s < CHL; s++) {
        const float4* pk4 = (const float4*)pk;
        const float4* pq4 = (const float4*)pq;
        float kr[16], qr[16];
        ((float4*)kr)[0] = pk4[0]; ((float4*)kr)[1] = pk4[1];
        ((float4*)kr)[2] = pk4[2]; ((float4*)kr)[3] = pk4[3];
        ((float4*)qr)[0] = pq4[0]; ((float4*)qr)[1] = pq4[1];
        ((float4*)qr)[2] = pq4[2]; ((float4*)qr)[3] = pq4[3];
        float vv = *pv;

        float num = 0.f, den = 0.f;
        #pragma unroll
        for (int i = 0; i < 16; i++) {
            kv[i] = fmaf(kr[i], vv, kv[i]);
            ks[i] += kr[i];
            num = fmaf(qr[i], kv[i], num);
            den = fmaf(qr[i], ks[i], den);
        }
        num += __shfl_xor_sync(0xffffffffu, num, 1);
        den += __shfl_xor_sync(0xffffffffu, den, 1);
        num += __shfl_xor_sync(0xffffffffu, num, 2);
        den += __shfl_xor_sync(0xffffffffu, den, 2);

        if (mg == 0) {
            float v = num / den;
            bf16 hi, lo; split_bf16(v, hi, lo);
            ahi[obase] = hi;
            alo[obase] = lo;
        }
        pq += M_; pk += M_; pv += QKV_; obase += D_;
    }
}

// ---------------------------------------------------------------------------
// Launch
// ---------------------------------------------------------------------------
extern "C" void kernel_launch(void* const* d_in, const int* in_sizes, int n_in,
                              void* d_out, int out_size)
{
    const float* x      = (const float*)d_in[0];
    const float* ln1_g  = (const float*)d_in[1];
    const float* ln1_b  = (const float*)d_in[2];
    const float* w_attn = (const float*)d_in[3];
    const float* b_attn = (const float*)d_in[4];
    const float* w_feat = (const float*)d_in[5];
    const float* w_proj = (const float*)d_in[6];
    const float* b_proj = (const float*)d_in[7];
    const float* ln2_g  = (const float*)d_in[8];
    const float* ln2_b  = (const float*)d_in[9];
    const float* w_fc   = (const float*)d_in[10];
    const float* b_fc   = (const float*)d_in[11];
    const float* w_out  = (const float*)d_in[12];
    const float* b_out  = (const float*)d_in[13];
    float* out = (float*)d_out;

    bf16 *a_hi, *a_lo, *at_hi, *at_lo, *h_hi, *h_lo, *ff_hi, *ff_lo;
    bf16 *wA_hi, *wA_lo, *wP_hi, *wP_lo, *wF_hi, *wF_lo, *wO_hi, *wO_lo;
    float *qkv, *phiq, *phik, *x1, *kvt, *kst, *sp0, *sp1, *sp2;
    cudaGetSymbolAddress((void**)&a_hi,  g_a_hi);
    cudaGetSymbolAddress((void**)&a_lo,  g_a_lo);
    cudaGetSymbolAddress((void**)&qkv,   g_qkv);
    cudaGetSymbolAddress((void**)&phiq,  g_phiq);
    cudaGetSymbolAddress((void**)&phik,  g_phik);
    cudaGetSymbolAddress((void**)&at_hi, g_at_hi);
    cudaGetSymbolAddress((void**)&at_lo, g_at_lo);
    cudaGetSymbolAddress((void**)&x1,    g_x1);
    cudaGetSymbolAddress((void**)&h_hi,  g_h_hi);
    cudaGetSymbolAddress((void**)&h_lo,  g_h_lo);
    cudaGetSymbolAddress((void**)&ff_hi, g_ff_hi);
    cudaGetSymbolAddress((void**)&ff_lo, g_ff_lo);
    cudaGetSymbolAddress((void**)&sp0,   g_sp0);
    cudaGetSymbolAddress((void**)&sp1,   g_sp1);
    cudaGetSymbolAddress((void**)&sp2,   g_sp2);
    cudaGetSymbolAddress((void**)&kvt,   g_kvt);
    cudaGetSymbolAddress((void**)&kst,   g_kst);
    cudaGetSymbolAddress((void**)&wA_hi, g_wA_hi);
    cudaGetSymbolAddress((void**)&wA_lo, g_wA_lo);
    cudaGetSymbolAddress((void**)&wP_hi, g_wP_hi);
    cudaGetSymbolAddress((void**)&wP_lo, g_wP_lo);
    cudaGetSymbolAddress((void**)&wF_hi, g_wF_hi);
    cudaGetSymbolAddress((void**)&wF_lo, g_wF_lo);
    cudaGetSymbolAddress((void**)&wO_hi, g_wO_hi);
    cudaGetSymbolAddress((void**)&wO_lo, g_wO_lo);

    cudaFuncSetAttribute(gemm_mma<0,0,0,1>, cudaFuncAttributeMaxDynamicSharedMemorySize, GEMM_SMEM);
    cudaFuncSetAttribute(gemm_mma<0,0,0,3>, cudaFuncAttributeMaxDynamicSharedMemorySize, GEMM_SMEM);
    cudaFuncSetAttribute(gemm_mma<0,1,1,1>, cudaFuncAttributeMaxDynamicSharedMemorySize, GEMM_SMEM);

    // 0. fused weight transpose+split (all four weights, one launch)
    wconv_all<<<6912, dim3(32, 8)>>>(w_attn, w_proj, w_fc, w_out,
                                     wA_hi, wA_lo, wP_hi, wP_lo,
                                     wF_hi, wF_lo, wO_hi, wO_lo);

    // 1. LN1 -> a (hi/lo)
    ln_kernel<<<NT_, 256>>>(x, ln1_g, ln1_b, a_hi, a_lo);

    // 2. qkv = a @ w_attn + b_attn   [2048 x 2304], f32 out
    gemm_mma<0,0,0,1><<<dim3(NT_/BM, QKV_/BN), 256, GEMM_SMEM>>>(
        a_hi, a_lo, wA_hi, wA_lo, b_attn, nullptr, qkv, nullptr, nullptr,
        nullptr, nullptr, D_, QKV_);

    // 3. FAVOR+ features
    phi_kernel<<<dim3(S_/32, H_*2, B_), 256>>>(qkv, w_feat, phiq, phik);

    // 4. chunked causal scan -> attn (hi/lo)
    scan_tot_kernel<<<B_*H_*NCH, 256>>>(qkv, phik, kvt, kst);
    scan_kernel<<<B_*H_*NCH, 256>>>(qkv, phiq, phik, kvt, kst, at_hi, at_lo);

    // 5. x1 = x + attn @ w_proj + b_proj  (split-K3 + reduce)
    gemm_mma<0,0,0,3><<<dim3(NT_/BM, D_/BN, 3), 256, GEMM_SMEM>>>(
        at_hi, at_lo, wP_hi, wP_lo, b_proj, nullptr, sp0, sp1, sp2,
        nullptr, nullptr, D_, D_);
    addred3_kernel<<<(NT_*D_/4)/256, 256>>>(sp0, sp1, sp2, b_proj, x, x1);

    // 6. LN2 -> h (hi/lo)
    ln_kernel<<<NT_, 256>>>(x1, ln2_g, ln2_b, h_hi, h_lo);

    // 7. ff = gelu(h @ w_fc + b_fc)   [2048 x 3072], bf16 hi/lo out
    gemm_mma<0,1,1,1><<<dim3(NT_/BM, DFF_/BN), 256, GEMM_SMEM>>>(
        h_hi, h_lo, wF_hi, wF_lo, b_fc, nullptr, nullptr, nullptr, nullptr,
        ff_hi, ff_lo, D_, DFF_);

    // 8. out = x1 + ff @ w_out + b_out  (split-K3 + reduce)
    gemm_mma<0,0,0,3><<<dim3(NT_/BM, D_/BN, 3), 256, GEMM_SMEM>>>(
        ff_hi, ff_lo, wO_hi, wO_lo, b_out, nullptr, sp0, sp1, sp2,
        nullptr, nullptr, DFF_, D_);
    addred3_kernel<<<(NT_*D_/4)/256, 256>>>(sp0, sp1, sp2, b_out, x1, out);
}

// round 9
// speedup vs baseline: 1.2862x; 1.0807x over previous
#include <cuda_runtime.h>
#include <cuda_bf16.h>
#include <cstdint>

// ---------------------------------------------------------------------------
// Problem constants
// ---------------------------------------------------------------------------
#define B_  2
#define S_  1024
#define D_  768
#define H_  12
#define DH_ 64
#define M_  64
#define DFF_ 3072
#define NT_ (B_ * S_)          // 2048 tokens
#define QKV_ (3 * D_)          // 2304
#define NCH 16                 // scan chunks
#define CHL (S_ / NCH)         // 64 steps per chunk

typedef __nv_bfloat16 bf16;

// ---------------------------------------------------------------------------
// Scratch (__device__ globals; no allocation allowed)
// ---------------------------------------------------------------------------
__device__ bf16  g_a_hi [NT_ * D_];
__device__ bf16  g_a_lo [NT_ * D_];
__device__ float g_qkv  [NT_ * QKV_];
__device__ float g_phiq [B_ * H_ * S_ * M_];
__device__ float g_phik [B_ * H_ * S_ * M_];
__device__ bf16  g_at_hi[NT_ * D_];
__device__ bf16  g_at_lo[NT_ * D_];
__device__ float g_x1   [NT_ * D_];
__device__ bf16  g_h_hi [NT_ * D_];
__device__ bf16  g_h_lo [NT_ * D_];
__device__ bf16  g_ff_hi[NT_ * DFF_];
__device__ bf16  g_ff_lo[NT_ * DFF_];
// split-K partial buffers
__device__ float g_sp0  [NT_ * D_];
__device__ float g_sp1  [NT_ * D_];
__device__ float g_sp2  [NT_ * D_];
// scan chunk totals (pass1) -> exclusive prefixes (after scan_pfx)
__device__ float g_kvt  [B_ * H_ * NCH * M_ * DH_];
__device__ float g_kst  [B_ * H_ * NCH * M_];
// transposed, split weights: Wt[n][k] = W[k][n]
__device__ bf16  g_wA_hi[QKV_ * D_];
__device__ bf16  g_wA_lo[QKV_ * D_];
__device__ bf16  g_wP_hi[D_ * D_];
__device__ bf16  g_wP_lo[D_ * D_];
__device__ bf16  g_wF_hi[DFF_ * D_];
__device__ bf16  g_wF_lo[DFF_ * D_];
__device__ bf16  g_wO_hi[D_ * DFF_];
__device__ bf16  g_wO_lo[D_ * DFF_];

// ---------------------------------------------------------------------------
// Small helpers
// ---------------------------------------------------------------------------
__device__ __forceinline__ uint32_t smem_to_u32(const void* p) {
    uint32_t a;
    asm("{ .reg .u64 t; cvta.to.shared.u64 t, %1; cvt.u32.u64 %0, t; }"
        : "=r"(a) : "l"(p));
    return a;
}

__device__ __forceinline__ void split_bf16(float v, bf16& hi, bf16& lo) {
    hi = __float2bfloat16(v);
    lo = __float2bfloat16(v - __bfloat162float(hi));
}

__device__ __forceinline__ float gelu_tanh(float x)
{
    float x3 = x * x * x;
    float u  = 0.7978845608028654f * (x + 0.044715f * x3);
    return 0.5f * x * (1.0f + tanhf(u));
}

__device__ __forceinline__ void cp_async16(uint32_t saddr, const void* gaddr) {
    asm volatile("cp.async.cg.shared.global [%0], [%1], 16;"
                 :: "r"(saddr), "l"(gaddr));
}
__device__ __forceinline__ void cp_commit() {
    asm volatile("cp.async.commit_group;");
}
template<int N>
__device__ __forceinline__ void cp_wait() {
    asm volatile("cp.async.wait_group %0;" :: "n"(N));
}

__device__ __forceinline__ void ldmx4(uint32_t* r, uint32_t addr) {
    asm volatile("ldmatrix.sync.aligned.m8n8.x4.shared.b16 {%0,%1,%2,%3}, [%4];"
                 : "=r"(r[0]), "=r"(r[1]), "=r"(r[2]), "=r"(r[3]) : "r"(addr));
}

__device__ __forceinline__ void mma16816(float* c, const uint32_t* a,
                                         uint32_t b0, uint32_t b1) {
    asm volatile(
        "mma.sync.aligned.m16n8k16.row.col.f32.bf16.bf16.f32 "
        "{%0,%1,%2,%3}, {%4,%5,%6,%7}, {%8,%9}, {%0,%1,%2,%3};"
        : "+f"(c[0]), "+f"(c[1]), "+f"(c[2]), "+f"(c[3])
        : "r"(a[0]), "r"(a[1]), "r"(a[2]), "r"(a[3]), "r"(b0), "r"(b1));
}

// ---------------------------------------------------------------------------
// LayerNorm -> bf16 hi/lo split output
// ---------------------------------------------------------------------------
__global__ void ln_kernel(const float* __restrict__ x,
                          const float* __restrict__ g,
                          const float* __restrict__ b,
                          bf16* __restrict__ ohi, bf16* __restrict__ olo)
{
    int row = blockIdx.x;
    int t   = threadIdx.x;
    const float* xr = x + (size_t)row * D_;

    float v0 = xr[t], v1 = xr[t + 256], v2 = xr[t + 512];
    float s  = v0 + v1 + v2;
    float sq = v0 * v0 + v1 * v1 + v2 * v2;

    #pragma unroll
    for (int off = 16; off; off >>= 1) {
        s  += __shfl_xor_sync(0xffffffffu, s,  off);
        sq += __shfl_xor_sync(0xffffffffu, sq, off);
    }
    __shared__ float red[16];
    int w = t >> 5, l = t & 31;
    if (l == 0) { red[w] = s; red[w + 8] = sq; }
    __syncthreads();
    s = 0.f; sq = 0.f;
    #pragma unroll
    for (int i = 0; i < 8; i++) { s += red[i]; sq += red[8 + i]; }

    const float inv = 1.0f / (float)D_;
    float mean = s * inv;
    float var  = sq * inv - mean * mean;
    float rs   = rsqrtf(var + 1e-5f);

    size_t base = (size_t)row * D_;
    float vv[3] = {v0, v1, v2};
    #pragma unroll
    for (int i = 0; i < 3; i++) {
        int c = t + i * 256;
        float v = (vv[i] - mean) * rs * g[c] + b[c];
        bf16 hi, lo; split_bf16(v, hi, lo);
        ohi[base + c] = hi; olo[base + c] = lo;
    }
}

// ---------------------------------------------------------------------------
// Fused split-K3 reduce + residual + bias + LayerNorm -> x1 (f32) + h (hi/lo)
// ---------------------------------------------------------------------------
__global__ void addln_kernel(const float* __restrict__ p0,
                             const float* __restrict__ p1,
                             const float* __restrict__ p2,
                             const float* __restrict__ bias,
                             const float* __restrict__ res,
                             const float* __restrict__ g,
                             const float* __restrict__ b,
                             float* __restrict__ x1,
                             bf16* __restrict__ ohi, bf16* __restrict__ olo)
{
    int row = blockIdx.x;
    int t   = threadIdx.x;
    size_t base = (size_t)row * D_;

    float vv[3];
    #pragma unroll
    for (int i = 0; i < 3; i++) {
        int c = t + i * 256;
        size_t idx = base + c;
        vv[i] = p0[idx] + p1[idx] + p2[idx] + bias[c] + res[idx];
        x1[idx] = vv[i];
    }

    float s  = vv[0] + vv[1] + vv[2];
    float sq = vv[0]*vv[0] + vv[1]*vv[1] + vv[2]*vv[2];
    #pragma unroll
    for (int off = 16; off; off >>= 1) {
        s  += __shfl_xor_sync(0xffffffffu, s,  off);
        sq += __shfl_xor_sync(0xffffffffu, sq, off);
    }
    __shared__ float red[16];
    int w = t >> 5, l = t & 31;
    if (l == 0) { red[w] = s; red[w + 8] = sq; }
    __syncthreads();
    s = 0.f; sq = 0.f;
    #pragma unroll
    for (int i = 0; i < 8; i++) { s += red[i]; sq += red[8 + i]; }

    const float inv = 1.0f / (float)D_;
    float mean = s * inv;
    float var  = sq * inv - mean * mean;
    float rs   = rsqrtf(var + 1e-5f);

    #pragma unroll
    for (int i = 0; i < 3; i++) {
        int c = t + i * 256;
        float v = (vv[i] - mean) * rs * g[c] + b[c];
        bf16 hi, lo; split_bf16(v, hi, lo);
        ohi[base + c] = hi; olo[base + c] = lo;
    }
}

// ---------------------------------------------------------------------------
// Fused weight transpose + bf16 split for all 4 weights.
// ---------------------------------------------------------------------------
__global__ void wconv_all(const float* __restrict__ wA, const float* __restrict__ wP,
                          const float* __restrict__ wF, const float* __restrict__ wO,
                          bf16* __restrict__ Ahi, bf16* __restrict__ Alo,
                          bf16* __restrict__ Phi, bf16* __restrict__ Plo,
                          bf16* __restrict__ Fhi, bf16* __restrict__ Flo,
                          bf16* __restrict__ Ohi, bf16* __restrict__ Olo)
{
    int t = blockIdx.x;
    const float* W; bf16 *Thi, *Tlo; int K, N, nx;
    if (t < 1728)      { W = wA; Thi = Ahi; Tlo = Alo; K = D_;  N = QKV_; nx = 72; }
    else if (t < 2304) { t -= 1728; W = wP; Thi = Phi; Tlo = Plo; K = D_;  N = D_;   nx = 24; }
    else if (t < 4608) { t -= 2304; W = wF; Thi = Fhi; Tlo = Flo; K = D_;  N = DFF_; nx = 96; }
    else               { t -= 4608; W = wO; Thi = Ohi; Tlo = Olo; K = DFF_; N = D_;  nx = 24; }
    int n0 = (t % nx) * 32, k0 = (t / nx) * 32;

    __shared__ float tile[32][33];
    int tx = threadIdx.x, ty = threadIdx.y;
    #pragma unroll
    for (int i = 0; i < 4; i++)
        tile[ty + i * 8][tx] = W[(size_t)(k0 + ty + i * 8) * N + n0 + tx];
    __syncthreads();
    #pragma unroll
    for (int i = 0; i < 4; i++) {
        float v = tile[tx][ty + i * 8];
        size_t idx = (size_t)(n0 + ty + i * 8) * K + k0 + tx;
        bf16 hi, lo; split_bf16(v, hi, lo);
        Thi[idx] = hi; Tlo[idx] = lo;
    }
}

// ---------------------------------------------------------------------------
// HMMA 3xBF16-split GEMM (BKC=32, 80KB smem, 2 CTAs/SM, single-sync loop).
// SPLITK>1: blockIdx.z picks K slice; raw f32 partials to Cp[z].
// ---------------------------------------------------------------------------
#define BM 128
#define BN 128
#define BKC 32
#define LDT 40                         // padded row (bf16) = 80B
#define TILE_BYTES (BM * LDT * 2)      // 10240
#define STAGE_BYTES (4 * TILE_BYTES)   // 40960
#define GEMM_SMEM (2 * STAGE_BYTES)    // 81920

template<int RES, int GELU, int OUTBF, int SPLITK>
__global__ void __launch_bounds__(256)
gemm_mma(const bf16* __restrict__ Ahi, const bf16* __restrict__ Alo,
         const bf16* __restrict__ Bhi, const bf16* __restrict__ Blo,
         const float* __restrict__ bias, const float* __restrict__ res,
         float* __restrict__ Cf, float* __restrict__ Cp1, float* __restrict__ Cp2,
         bf16* __restrict__ Chi, bf16* __restrict__ Clo,
         int K, int N)
{
    extern __shared__ char smem[];
    const uint32_t sbase = smem_to_u32(smem);

    const int tid  = threadIdx.x;
    const int lane = tid & 31;
    const int w    = tid >> 5;
    const int wr   = w & 3;
    const int wc   = w >> 2;
    const int bm   = blockIdx.x * BM;
    const int bn   = blockIdx.y * BN;
    const int Keff = K / SPLITK;
    const int kbase = (SPLITK > 1) ? (int)blockIdx.z * Keff : 0;

    float acc[2][8][4];
    #pragma unroll
    for (int i = 0; i < 2; i++)
        #pragma unroll
        for (int j = 0; j < 8; j++)
            #pragma unroll
            for (int q = 0; q < 4; q++) acc[i][j][q] = 0.f;

    const int NC = Keff / BKC;

    const int lrow = tid >> 1;
    const int lseg = (tid & 1) * 2;
    const uint32_t lsm = (uint32_t)(lrow * LDT + lseg * 8) * 2u;

    auto issue = [&](int c, int st) {
        int k0 = kbase + c * BKC;
        const bf16* srcs[4] = {
            Ahi + (size_t)(bm + lrow) * K + k0 + lseg * 8,
            Alo + (size_t)(bm + lrow) * K + k0 + lseg * 8,
            Bhi + (size_t)(bn + lrow) * K + k0 + lseg * 8,
            Blo + (size_t)(bn + lrow) * K + k0 + lseg * 8 };
        uint32_t sb = sbase + (uint32_t)st * STAGE_BYTES + lsm;
        #pragma unroll
        for (int i = 0; i < 4; i++) {
            cp_async16(sb + (uint32_t)i * TILE_BYTES,       srcs[i]);
            cp_async16(sb + (uint32_t)i * TILE_BYTES + 16u, srcs[i] + 8);
        }
    };

    issue(0, 0);
    cp_commit();

    const uint32_t aoff = (uint32_t)((wr * 32 + (lane & 15)) * LDT + (lane >> 4) * 8) * 2u;
    const uint32_t boff = (uint32_t)((wc * 64 + (lane & 7) + ((lane >> 4) & 1) * 8) * LDT
                                     + ((lane >> 3) & 1) * 8) * 2u;

    for (int c = 0; c < NC; c++) {
        cp_wait<0>();
        __syncthreads();
        if (c + 1 < NC) { issue(c + 1, (c + 1) & 1); cp_commit(); }

        const uint32_t st = sbase + (uint32_t)(c & 1) * STAGE_BYTES;
        #pragma unroll
        for (int ks = 0; ks < 2; ks++) {
            const uint32_t ko = (uint32_t)(ks * 16) * 2u;
            uint32_t ah[2][4], al[2][4], bh[4][4], bl[4][4];
            #pragma unroll
            for (int mt = 0; mt < 2; mt++) {
                uint32_t ro = aoff + (uint32_t)(mt * 16 * LDT) * 2u + ko;
                ldmx4(ah[mt], st + ro);
                ldmx4(al[mt], st + TILE_BYTES + ro);
            }
            #pragma unroll
            for (int np = 0; np < 4; np++) {
                uint32_t ro = boff + (uint32_t)(np * 16 * LDT) * 2u + ko;
                ldmx4(bh[np], st + 2u * TILE_BYTES + ro);
                ldmx4(bl[np], st + 3u * TILE_BYTES + ro);
            }
            #pragma unroll
            for (int mt = 0; mt < 2; mt++)
                #pragma unroll
                for (int nt = 0; nt < 8; nt++) {
                    const int np = nt >> 1, half = (nt & 1) * 2;
                    mma16816(acc[mt][nt], ah[mt], bh[np][half], bh[np][half + 1]);
                    mma16816(acc[mt][nt], ah[mt], bl[np][half], bl[np][half + 1]);
                    mma16816(acc[mt][nt], al[mt], bh[np][half], bh[np][half + 1]);
                }
        }
    }

    // epilogue
    const int g  = lane >> 2;
    const int tg = lane & 3;
    float* Cpart = Cf;
    if (SPLITK > 1) Cpart = (blockIdx.z == 0) ? Cf : (blockIdx.z == 1 ? Cp1 : Cp2);
    #pragma unroll
    for (int mt = 0; mt < 2; mt++) {
        #pragma unroll
        for (int nt = 0; nt < 8; nt++) {
            int col = bn + wc * 64 + nt * 8 + tg * 2;
            float2 bv = (SPLITK > 1) ? make_float2(0.f, 0.f)
                                     : *(const float2*)(bias + col);
            #pragma unroll
            for (int half = 0; half < 2; half++) {
                int row = bm + wr * 32 + mt * 16 + g + half * 8;
                float v0 = acc[mt][nt][half * 2 + 0] + bv.x;
                float v1 = acc[mt][nt][half * 2 + 1] + bv.y;
                size_t idx = (size_t)row * N + col;
                if (RES && SPLITK == 1) {
                    float2 rv = *(const float2*)(res + idx);
                    v0 += rv.x; v1 += rv.y;
                }
                if (GELU) { v0 = gelu_tanh(v0); v1 = gelu_tanh(v1); }
                if (OUTBF) {
                    bf16 h0, l0, h1, l1;
                    split_bf16(v0, h0, l0); split_bf16(v1, h1, l1);
                    *(__nv_bfloat162*)(Chi + idx) = __nv_bfloat162{h0, h1};
                    *(__nv_bfloat162*)(Clo + idx) = __nv_bfloat162{l0, l1};
                } else {
                    *(float2*)(Cpart + idx) = make_float2(v0, v1);
                }
            }
        }
    }
}

// ---------------------------------------------------------------------------
// Split-K3 reduction: o = p0 + p1 + p2 + bias + res   (f32, 768 cols)
// ---------------------------------------------------------------------------
__global__ void addred3_kernel(const float* __restrict__ p0,
                               const float* __restrict__ p1,
                               const float* __restrict__ p2,
                               const float* __restrict__ bias,
                               const float* __restrict__ res,
                               float* __restrict__ o)
{
    int i = (blockIdx.x * 256 + threadIdx.x);
    int col4 = i % (D_ / 4);
    float4 a = ((const float4*)p0)[i];
    float4 b = ((const float4*)p1)[i];
    float4 c = ((const float4*)p2)[i];
    float4 d = ((const float4*)bias)[col4];
    float4 r = ((const float4*)res)[i];
    float4 v;
    v.x = a.x + b.x + c.x + d.x + r.x;
    v.y = a.y + b.y + c.y + d.y + r.y;
    v.z = a.z + b.z + c.z + d.z + r.z;
    v.w = a.w + b.w + c.w + d.w + r.w;
    ((float4*)o)[i] = v;
}

// ---------------------------------------------------------------------------
// FAVOR+ features. Thread owns one m (t&63) and 8 rows (sl = t>>6 + 4j).
// Per d: 1 LDS for wfT[d][m] + 8 broadcast LDS for xs rows.
// ---------------------------------------------------------------------------
__global__ void phi_kernel(const float* __restrict__ qkv,
                           const float* __restrict__ wfeat,
                           float* __restrict__ phiq,
                           float* __restrict__ phik)
{
    const int sc = blockIdx.x;
    const int hy = blockIdx.y;
    const int b  = blockIdx.z;
    const int h  = hy % H_;
    const int qk = hy / H_;

    __shared__ float wfT[64][65];
    __shared__ float xs[32][64];
    __shared__ float sqs[32];

    const int t = threadIdx.x;

    #pragma unroll
    for (int i = 0; i < 16; i++) {
        int idx = t + i * 256;
        wfT[idx & 63][idx >> 6] = wfeat[idx];
    }

    const float scale = 0.3535533905932738f;
    const int s0   = sc * 32;
    const int col0 = qk * D_ + h * DH_;

    #pragma unroll
    for (int i = 0; i < 8; i++) {
        int idx = t + i * 256;
        int sl = idx >> 6, d = idx & 63;
        xs[sl][d] = qkv[(size_t)(b * S_ + s0 + sl) * QKV_ + col0 + d] * scale;
    }
    __syncthreads();

    {
        int sl = t >> 3, p = t & 7;
        float acc = 0.f;
        #pragma unroll
        for (int dd = 0; dd < 8; dd++) {
            float xv = xs[sl][p * 8 + dd];
            acc = fmaf(xv, xv, acc);
        }
        acc += __shfl_xor_sync(0xffffffffu, acc, 1);
        acc += __shfl_xor_sync(0xffffffffu, acc, 2);
        acc += __shfl_xor_sync(0xffffffffu, acc, 4);
        if (p == 0) sqs[sl] = 0.5f * acc;
    }
    __syncthreads();

    const int m   = t & 63;
    const int sl0 = t >> 6;          // 0..3
    float acc[8];
    #pragma unroll
    for (int j = 0; j < 8; j++) acc[j] = 0.f;

    #pragma unroll 8
    for (int d = 0; d < 64; d++) {
        float wf = wfT[d][m];
        #pragma unroll
        for (int j = 0; j < 8; j++)
            acc[j] = fmaf(xs[sl0 + 4 * j][d], wf, acc[j]);
    }

    float* dst = qk ? phik : phiq;
    #pragma unroll
    for (int j = 0; j < 8; j++) {
        int sl = sl0 + 4 * j;
        float ph = __expf(acc[j] - sqs[sl]) * 0.125f + 1e-6f;
        dst[(size_t)((b * H_ + h) * S_ + s0 + sl) * M_ + m] = ph;
    }
}

// ---------------------------------------------------------------------------
// Scan pass 1: per-(bh, chunk) totals of phik (x) v and phik.
// ---------------------------------------------------------------------------
__global__ void scan_tot_kernel(const float* __restrict__ qkv,
                                const float* __restrict__ phik,
                                float* __restrict__ kvt,
                                float* __restrict__ kst)
{
    const int bc = blockIdx.x;
    const int bh = bc / NCH;
    const int ch = bc % NCH;
    const int b  = bh / H_;
    const int h  = bh % H_;
    const int t  = threadIdx.x;
    const int d  = t >> 2;
    const int mg = t & 3;

    float kv[16], ks[16];
    #pragma unroll
    for (int i = 0; i < 16; i++) { kv[i] = 0.f; ks[i] = 0.f; }

    const int s0 = ch * CHL;
    const float* pk = phik + (size_t)bh * S_ * M_ + (size_t)s0 * M_ + mg * 16;
    const float* pv = qkv  + (size_t)(b * S_ + s0) * QKV_ + 2 * D_ + h * DH_ + d;

    for (int s = 0; s < CHL; s++) {
        const float4* pk4 = (const float4*)pk;
        float kr[16];
        ((float4*)kr)[0] = pk4[0]; ((float4*)kr)[1] = pk4[1];
        ((float4*)kr)[2] = pk4[2]; ((float4*)kr)[3] = pk4[3];
        float vv = *pv;
        #pragma unroll
        for (int i = 0; i < 16; i++) {
            kv[i] = fmaf(kr[i], vv, kv[i]);
            ks[i] += kr[i];
        }
        pk += M_; pv += QKV_;
    }

    size_t base = (size_t)bc * M_ + mg * 16;
    #pragma unroll
    for (int i = 0; i < 16; i++) {
        kvt[(base + i) * DH_ + d] = kv[i];
        if (d == 0) kst[base + i] = ks[i];
    }
}

// ---------------------------------------------------------------------------
// Scan prefix: in-place exclusive prefix over chunks per bh. grid = B*H.
// ---------------------------------------------------------------------------
__global__ void scan_pfx_kernel(float* __restrict__ kvt, float* __restrict__ kst)
{
    const int bh = blockIdx.x;
    const int t  = threadIdx.x;

    for (int e = t; e < M_ * DH_; e += 256) {
        float run = 0.f;
        #pragma unroll
        for (int ch = 0; ch < NCH; ch++) {
            size_t idx = ((size_t)(bh * NCH + ch)) * (M_ * DH_) + e;
            float v = kvt[idx];
            kvt[idx] = run;
            run += v;
        }
    }
    if (t < M_) {
        float run = 0.f;
        #pragma unroll
        for (int ch = 0; ch < NCH; ch++) {
            size_t idx = ((size_t)(bh * NCH + ch)) * M_ + t;
            float v = kst[idx];
            kst[idx] = run;
            run += v;
        }
    }
}

// ---------------------------------------------------------------------------
// Scan pass 2: local inclusive scan per (bh, chunk), seeded by exclusive
// prefix totals. Output bf16 hi/lo.
// ---------------------------------------------------------------------------
__global__ void scan_kernel(const float* __restrict__ qkv,
                            const float* __restrict__ phiq,
                            const float* __restrict__ phik,
                            const float* __restrict__ kvt,
                            const float* __restrict__ kst,
                            bf16* __restrict__ ahi, bf16* __restrict__ alo)
{
    const int bc = blockIdx.x;
    const int bh = bc / NCH;
    const int ch = bc % NCH;
    const int b  = bh / H_;
    const int h  = bh % H_;
    const int t  = threadIdx.x;
    const int d  = t >> 2;
    const int mg = t & 3;

    float kv[16], ks[16];
    size_t sbase = (size_t)bc * M_ + mg * 16;
    #pragma unroll
    for (int i = 0; i < 16; i++) {
        kv[i] = kvt[(sbase + i) * DH_ + d];
        ks[i] = kst[sbase + i];
    }

    const int s0 = ch * CHL;
    const float* pq = phiq + (size_t)bh * S_ * M_ + (size_t)s0 * M_ + mg * 16;
    const float* pk = phik + (size_t)bh * S_ * M_ + (size_t)s0 * M_ + mg * 16;
    const float* pv = qkv  + (size_t)(b * S_ + s0) * QKV_ + 2 * D_ + h * DH_ + d;
    size_t obase = (size_t)(b * S_ + s0) * D_ + h * DH_ + d;

    for (int s = 0; s < CHL; s++) {
        const float4* pk4 = (const float4*)pk;
        const float4* pq4 = (const float4*)pq;
        float kr[16], qr[16];
        ((float4*)kr)[0] = pk4[0]; ((float4*)kr)[1] = pk4[1];
        ((float4*)kr)[2] = pk4[2]; ((float4*)kr)[3] = pk4[3];
        ((float4*)qr)[0] = pq4[0]; ((float4*)qr)[1] = pq4[1];
        ((float4*)qr)[2] = pq4[2]; ((float4*)qr)[3] = pq4[3];
        float vv = *pv;

        float num = 0.f, den = 0.f;
        #pragma unroll
        for (int i = 0; i < 16; i++) {
            kv[i] = fmaf(kr[i], vv, kv[i]);
            ks[i] += kr[i];
            num = fmaf(qr[i], kv[i], num);
            den = fmaf(qr[i], ks[i], den);
        }
        num += __shfl_xor_sync(0xffffffffu, num, 1);
        den += __shfl_xor_sync(0xffffffffu, den, 1);
        num += __shfl_xor_sync(0xffffffffu, num, 2);
        den += __shfl_xor_sync(0xffffffffu, den, 2);

        if (mg == 0) {
            float v = num / den;
            bf16 hi, lo; split_bf16(v, hi, lo);
            ahi[obase] = hi;
            alo[obase] = lo;
        }
        pq += M_; pk += M_; pv += QKV_; obase += D_;
    }
}

// ---------------------------------------------------------------------------
// Launch
// ---------------------------------------------------------------------------
extern "C" void kernel_launch(void* const* d_in, const int* in_sizes, int n_in,
                              void* d_out, int out_size)
{
    const float* x      = (const float*)d_in[0];
    const float* ln1_g  = (const float*)d_in[1];
    const float* ln1_b  = (const float*)d_in[2];
    const float* w_attn = (const float*)d_in[3];
    const float* b_attn = (const float*)d_in[4];
    const float* w_feat = (const float*)d_in[5];
    const float* w_proj = (const float*)d_in[6];
    const float* b_proj = (const float*)d_in[7];
    const float* ln2_g  = (const float*)d_in[8];
    const float* ln2_b  = (const float*)d_in[9];
    const float* w_fc   = (const float*)d_in[10];
    const float* b_fc   = (const float*)d_in[11];
    const float* w_out  = (const float*)d_in[12];
    const float* b_out  = (const float*)d_in[13];
    float* out = (float*)d_out;

    bf16 *a_hi, *a_lo, *at_hi, *at_lo, *h_hi, *h_lo, *ff_hi, *ff_lo;
    bf16 *wA_hi, *wA_lo, *wP_hi, *wP_lo, *wF_hi, *wF_lo, *wO_hi, *wO_lo;
    float *qkv, *phiq, *phik, *x1, *kvt, *kst, *sp0, *sp1, *sp2;
    cudaGetSymbolAddress((void**)&a_hi,  g_a_hi);
    cudaGetSymbolAddress((void**)&a_lo,  g_a_lo);
    cudaGetSymbolAddress((void**)&qkv,   g_qkv);
    cudaGetSymbolAddress((void**)&phiq,  g_phiq);
    cudaGetSymbolAddress((void**)&phik,  g_phik);
    cudaGetSymbolAddress((void**)&at_hi, g_at_hi);
    cudaGetSymbolAddress((void**)&at_lo, g_at_lo);
    cudaGetSymbolAddress((void**)&x1,    g_x1);
    cudaGetSymbolAddress((void**)&h_hi,  g_h_hi);
    cudaGetSymbolAddress((void**)&h_lo,  g_h_lo);
    cudaGetSymbolAddress((void**)&ff_hi, g_ff_hi);
    cudaGetSymbolAddress((void**)&ff_lo, g_ff_lo);
    cudaGetSymbolAddress((void**)&sp0,   g_sp0);
    cudaGetSymbolAddress((void**)&sp1,   g_sp1);
    cudaGetSymbolAddress((void**)&sp2,   g_sp2);
    cudaGetSymbolAddress((void**)&kvt,   g_kvt);
    cudaGetSymbolAddress((void**)&kst,   g_kst);
    cudaGetSymbolAddress((void**)&wA_hi, g_wA_hi);
    cudaGetSymbolAddress((void**)&wA_lo, g_wA_lo);
    cudaGetSymbolAddress((void**)&wP_hi, g_wP_hi);
    cudaGetSymbolAddress((void**)&wP_lo, g_wP_lo);
    cudaGetSymbolAddress((void**)&wF_hi, g_wF_hi);
    cudaGetSymbolAddress((void**)&wF_lo, g_wF_lo);
    cudaGetSymbolAddress((void**)&wO_hi, g_wO_hi);
    cudaGetSymbolAddress((void**)&wO_lo, g_wO_lo);

    cudaFuncSetAttribute(gemm_mma<0,0,0,1>, cudaFuncAttributeMaxDynamicSharedMemorySize, GEMM_SMEM);
    cudaFuncSetAttribute(gemm_mma<0,0,0,3>, cudaFuncAttributeMaxDynamicSharedMemorySize, GEMM_SMEM);
    cudaFuncSetAttribute(gemm_mma<0,1,1,1>, cudaFuncAttributeMaxDynamicSharedMemorySize, GEMM_SMEM);

    // 0. fused weight transpose+split
    wconv_all<<<6912, dim3(32, 8)>>>(w_attn, w_proj, w_fc, w_out,
                                     wA_hi, wA_lo, wP_hi, wP_lo,
                                     wF_hi, wF_lo, wO_hi, wO_lo);

    // 1. LN1 -> a (hi/lo)
    ln_kernel<<<NT_, 256>>>(x, ln1_g, ln1_b, a_hi, a_lo);

    // 2. qkv = a @ w_attn + b_attn   [2048 x 2304], f32 out
    gemm_mma<0,0,0,1><<<dim3(NT_/BM, QKV_/BN), 256, GEMM_SMEM>>>(
        a_hi, a_lo, wA_hi, wA_lo, b_attn, nullptr, qkv, nullptr, nullptr,
        nullptr, nullptr, D_, QKV_);

    // 3. FAVOR+ features
    phi_kernel<<<dim3(S_/32, H_*2, B_), 256>>>(qkv, w_feat, phiq, phik);

    // 4. chunked causal scan (totals -> exclusive prefix -> seeded local scan)
    scan_tot_kernel<<<B_*H_*NCH, 256>>>(qkv, phik, kvt, kst);
    scan_pfx_kernel<<<B_*H_, 256>>>(kvt, kst);
    scan_kernel<<<B_*H_*NCH, 256>>>(qkv, phiq, phik, kvt, kst, at_hi, at_lo);

    // 5. x1 = x + attn @ w_proj + b_proj  (split-K3, reduce fused with LN2)
    gemm_mma<0,0,0,3><<<dim3(NT_/BM, D_/BN, 3), 256, GEMM_SMEM>>>(
        at_hi, at_lo, wP_hi, wP_lo, b_proj, nullptr, sp0, sp1, sp2,
        nullptr, nullptr, D_, D_);

    // 6. fused: x1 = p0+p1+p2+bias+x ; h = LN2(x1) (hi/lo)
    addln_kernel<<<NT_, 256>>>(sp0, sp1, sp2, b_proj, x, ln2_g, ln2_b,
                               x1, h_hi, h_lo);

    // 7. ff = gelu(h @ w_fc + b_fc)   [2048 x 3072], bf16 hi/lo out
    gemm_mma<0,1,1,1><<<dim3(NT_/BM, DFF_/BN), 256, GEMM_SMEM>>>(
        h_hi, h_lo, wF_hi, wF_lo, b_fc, nullptr, nullptr, nullptr, nullptr,
        ff_hi, ff_lo, D_, DFF_);

    // 8. out = x1 + ff @ w_out + b_out  (split-K3 + reduce)
    gemm_mma<0,0,0,3><<<dim3(NT_/BM, D_/BN, 3), 256, GEMM_SMEM>>>(
        ff_hi, ff_lo, wO_hi, wO_lo, b_out, nullptr, sp0, sp1, sp2,
        nullptr, nullptr, DFF_, D_);
    addred3_kernel<<<(NT_*D_/4)/256, 256>>>(sp0, sp1, sp2, b_out, x1, out);
}

// round 10
// speedup vs baseline: 1.6756x; 1.3027x over previous
#include <cuda_runtime.h>
#include <cuda_fp16.h>
#include <cstdint>

// ---------------------------------------------------------------------------
// Problem constants
// ---------------------------------------------------------------------------
#define B_  2
#define S_  1024
#define D_  768
#define H_  12
#define DH_ 64
#define M_  64
#define DFF_ 3072
#define NT_ (B_ * S_)          // 2048 tokens
#define QKV_ (3 * D_)          // 2304
#define NCH 16                 // scan chunks
#define CHL (S_ / NCH)         // 64 steps per chunk

typedef __half fp16;

// ---------------------------------------------------------------------------
// Scratch (__device__ globals; no allocation allowed)
// ---------------------------------------------------------------------------
__device__ fp16  g_a   [NT_ * D_];        // LN1 out (fp16)
__device__ float g_qkv [NT_ * QKV_];
__device__ float g_phiq[B_ * H_ * S_ * M_];
__device__ float g_phik[B_ * H_ * S_ * M_];
__device__ fp16  g_at  [NT_ * D_];        // attention out (fp16)
__device__ float g_x1  [NT_ * D_];
__device__ fp16  g_h   [NT_ * D_];        // LN2 out (fp16)
__device__ fp16  g_ff  [NT_ * DFF_];      // gelu out (fp16)
// split-K partial buffers
__device__ float g_sp0 [NT_ * D_];
__device__ float g_sp1 [NT_ * D_];
__device__ float g_sp2 [NT_ * D_];
// scan chunk totals -> exclusive prefixes
__device__ float g_kvt [B_ * H_ * NCH * M_ * DH_];
__device__ float g_kst [B_ * H_ * NCH * M_];
// transposed fp16 hi/lo weights: Wt[n][k] = W[k][n]
__device__ fp16  g_wA_hi[QKV_ * D_];
__device__ fp16  g_wA_lo[QKV_ * D_];
__device__ fp16  g_wP_hi[D_ * D_];
__device__ fp16  g_wP_lo[D_ * D_];
__device__ fp16  g_wF_hi[DFF_ * D_];
__device__ fp16  g_wF_lo[DFF_ * D_];
__device__ fp16  g_wO_hi[D_ * DFF_];
__device__ fp16  g_wO_lo[D_ * DFF_];

// ---------------------------------------------------------------------------
// Small helpers
// ---------------------------------------------------------------------------
__device__ __forceinline__ uint32_t smem_to_u32(const void* p) {
    uint32_t a;
    asm("{ .reg .u64 t; cvta.to.shared.u64 t, %1; cvt.u32.u64 %0, t; }"
        : "=r"(a) : "l"(p));
    return a;
}

__device__ __forceinline__ void split_h(float v, fp16& hi, fp16& lo) {
    hi = __float2half_rn(v);
    lo = __float2half_rn(v - __half2float(hi));
}

__device__ __forceinline__ float gelu_tanh(float x)
{
    float x3 = x * x * x;
    float u  = 0.7978845608028654f * (x + 0.044715f * x3);
    return 0.5f * x * (1.0f + tanhf(u));
}

__device__ __forceinline__ void cp_async16(uint32_t saddr, const void* gaddr) {
    asm volatile("cp.async.cg.shared.global [%0], [%1], 16;"
                 :: "r"(saddr), "l"(gaddr));
}
__device__ __forceinline__ void cp_commit() {
    asm volatile("cp.async.commit_group;");
}
template<int N>
__device__ __forceinline__ void cp_wait() {
    asm volatile("cp.async.wait_group %0;" :: "n"(N));
}

__device__ __forceinline__ void ldmx4(uint32_t* r, uint32_t addr) {
    asm volatile("ldmatrix.sync.aligned.m8n8.x4.shared.b16 {%0,%1,%2,%3}, [%4];"
                 : "=r"(r[0]), "=r"(r[1]), "=r"(r[2]), "=r"(r[3]) : "r"(addr));
}

// mma.sync m16n8k16 row.col f32 += f16*f16
__device__ __forceinline__ void mma16816(float* c, const uint32_t* a,
                                         uint32_t b0, uint32_t b1) {
    asm volatile(
        "mma.sync.aligned.m16n8k16.row.col.f32.f16.f16.f32 "
        "{%0,%1,%2,%3}, {%4,%5,%6,%7}, {%8,%9}, {%0,%1,%2,%3};"
        : "+f"(c[0]), "+f"(c[1]), "+f"(c[2]), "+f"(c[3])
        : "r"(a[0]), "r"(a[1]), "r"(a[2]), "r"(a[3]), "r"(b0), "r"(b1));
}

// ---------------------------------------------------------------------------
// LayerNorm -> fp16 output
// ---------------------------------------------------------------------------
__global__ void ln_kernel(const float* __restrict__ x,
                          const float* __restrict__ g,
                          const float* __restrict__ b,
                          fp16* __restrict__ o)
{
    int row = blockIdx.x;
    int t   = threadIdx.x;
    const float* xr = x + (size_t)row * D_;

    float v0 = xr[t], v1 = xr[t + 256], v2 = xr[t + 512];
    float s  = v0 + v1 + v2;
    float sq = v0 * v0 + v1 * v1 + v2 * v2;

    #pragma unroll
    for (int off = 16; off; off >>= 1) {
        s  += __shfl_xor_sync(0xffffffffu, s,  off);
        sq += __shfl_xor_sync(0xffffffffu, sq, off);
    }
    __shared__ float red[16];
    int w = t >> 5, l = t & 31;
    if (l == 0) { red[w] = s; red[w + 8] = sq; }
    __syncthreads();
    s = 0.f; sq = 0.f;
    #pragma unroll
    for (int i = 0; i < 8; i++) { s += red[i]; sq += red[8 + i]; }

    const float inv = 1.0f / (float)D_;
    float mean = s * inv;
    float var  = sq * inv - mean * mean;
    float rs   = rsqrtf(var + 1e-5f);

    size_t base = (size_t)row * D_;
    float vv[3] = {v0, v1, v2};
    #pragma unroll
    for (int i = 0; i < 3; i++) {
        int c = t + i * 256;
        o[base + c] = __float2half_rn((vv[i] - mean) * rs * g[c] + b[c]);
    }
}

// ---------------------------------------------------------------------------
// Fused split-K3 reduce + residual + bias + LayerNorm -> x1 (f32) + h (fp16)
// ---------------------------------------------------------------------------
__global__ void addln_kernel(const float* __restrict__ p0,
                             const float* __restrict__ p1,
                             const float* __restrict__ p2,
                             const float* __restrict__ bias,
                             const float* __restrict__ res,
                             const float* __restrict__ g,
                             const float* __restrict__ b,
                             float* __restrict__ x1,
                             fp16* __restrict__ o)
{
    int row = blockIdx.x;
    int t   = threadIdx.x;
    size_t base = (size_t)row * D_;

    float vv[3];
    #pragma unroll
    for (int i = 0; i < 3; i++) {
        int c = t + i * 256;
        size_t idx = base + c;
        vv[i] = p0[idx] + p1[idx] + p2[idx] + bias[c] + res[idx];
        x1[idx] = vv[i];
    }

    float s  = vv[0] + vv[1] + vv[2];
    float sq = vv[0]*vv[0] + vv[1]*vv[1] + vv[2]*vv[2];
    #pragma unroll
    for (int off = 16; off; off >>= 1) {
        s  += __shfl_xor_sync(0xffffffffu, s,  off);
        sq += __shfl_xor_sync(0xffffffffu, sq, off);
    }
    __shared__ float red[16];
    int w = t >> 5, l = t & 31;
    if (l == 0) { red[w] = s; red[w + 8] = sq; }
    __syncthreads();
    s = 0.f; sq = 0.f;
    #pragma unroll
    for (int i = 0; i < 8; i++) { s += red[i]; sq += red[8 + i]; }

    const float inv = 1.0f / (float)D_;
    float mean = s * inv;
    float var  = sq * inv - mean * mean;
    float rs   = rsqrtf(var + 1e-5f);

    #pragma unroll
    for (int i = 0; i < 3; i++) {
        int c = t + i * 256;
        o[base + c] = __float2half_rn((vv[i] - mean) * rs * g[c] + b[c]);
    }
}

// ---------------------------------------------------------------------------
// Fused weight transpose + fp16 hi/lo split for all 4 weights.
// ---------------------------------------------------------------------------
__global__ void wconv_all(const float* __restrict__ wA, const float* __restrict__ wP,
                          const float* __restrict__ wF, const float* __restrict__ wO,
                          fp16* __restrict__ Ahi, fp16* __restrict__ Alo,
                          fp16* __restrict__ Phi, fp16* __restrict__ Plo,
                          fp16* __restrict__ Fhi, fp16* __restrict__ Flo,
                          fp16* __restrict__ Ohi, fp16* __restrict__ Olo)
{
    int t = blockIdx.x;
    const float* W; fp16 *Thi, *Tlo; int K, N, nx;
    if (t < 1728)      { W = wA; Thi = Ahi; Tlo = Alo; K = D_;  N = QKV_; nx = 72; }
    else if (t < 2304) { t -= 1728; W = wP; Thi = Phi; Tlo = Plo; K = D_;  N = D_;   nx = 24; }
    else if (t < 4608) { t -= 2304; W = wF; Thi = Fhi; Tlo = Flo; K = D_;  N = DFF_; nx = 96; }
    else               { t -= 4608; W = wO; Thi = Ohi; Tlo = Olo; K = DFF_; N = D_;  nx = 24; }
    int n0 = (t % nx) * 32, k0 = (t / nx) * 32;

    __shared__ float tile[32][33];
    int tx = threadIdx.x, ty = threadIdx.y;
    #pragma unroll
    for (int i = 0; i < 4; i++)
        tile[ty + i * 8][tx] = W[(size_t)(k0 + ty + i * 8) * N + n0 + tx];
    __syncthreads();
    #pragma unroll
    for (int i = 0; i < 4; i++) {
        float v = tile[tx][ty + i * 8];
        size_t idx = (size_t)(n0 + ty + i * 8) * K + k0 + tx;
        fp16 hi, lo; split_h(v, hi, lo);
        Thi[idx] = hi; Tlo[idx] = lo;
    }
}

// ---------------------------------------------------------------------------
// HMMA fp16 2-term GEMM: C = A @ (Whi + Wlo)^T, A single fp16.
// CTA 128x128, BKC=32, 3 tiles/stage (A, Whi, Wlo), 2 stages = 60KB smem.
// SPLITK>1: blockIdx.z picks K slice; raw f32 partials.
// ---------------------------------------------------------------------------
#define BM 128
#define BN 128
#define BKC 32
#define LDT 40                         // padded row (fp16) = 80B
#define TILE_BYTES (BM * LDT * 2)      // 10240
#define STAGE_BYTES (3 * TILE_BYTES)   // 30720
#define GEMM_SMEM (2 * STAGE_BYTES)    // 61440

template<int GELU, int OUTH, int SPLITK>
__global__ void __launch_bounds__(256)
gemm_mma(const fp16* __restrict__ A,
         const fp16* __restrict__ Bhi, const fp16* __restrict__ Blo,
         const float* __restrict__ bias,
         float* __restrict__ Cf, float* __restrict__ Cp1, float* __restrict__ Cp2,
         fp16* __restrict__ Ch,
         int K, int N)
{
    extern __shared__ char smem[];
    const uint32_t sbase = smem_to_u32(smem);

    const int tid  = threadIdx.x;
    const int lane = tid & 31;
    const int w    = tid >> 5;
    const int wr   = w & 3;
    const int wc   = w >> 2;
    const int bm   = blockIdx.x * BM;
    const int bn   = blockIdx.y * BN;
    const int Keff = K / SPLITK;
    const int kbase = (SPLITK > 1) ? (int)blockIdx.z * Keff : 0;

    float acc[2][8][4];
    #pragma unroll
    for (int i = 0; i < 2; i++)
        #pragma unroll
        for (int j = 0; j < 8; j++)
            #pragma unroll
            for (int q = 0; q < 4; q++) acc[i][j][q] = 0.f;

    const int NC = Keff / BKC;

    const int lrow = tid >> 1;
    const int lseg = (tid & 1) * 2;
    const uint32_t lsm = (uint32_t)(lrow * LDT + lseg * 8) * 2u;

    auto issue = [&](int c, int st) {
        int k0 = kbase + c * BKC;
        const fp16* srcs[3] = {
            A   + (size_t)(bm + lrow) * K + k0 + lseg * 8,
            Bhi + (size_t)(bn + lrow) * K + k0 + lseg * 8,
            Blo + (size_t)(bn + lrow) * K + k0 + lseg * 8 };
        uint32_t sb = sbase + (uint32_t)st * STAGE_BYTES + lsm;
        #pragma unroll
        for (int i = 0; i < 3; i++) {
            cp_async16(sb + (uint32_t)i * TILE_BYTES,       srcs[i]);
            cp_async16(sb + (uint32_t)i * TILE_BYTES + 16u, srcs[i] + 8);
        }
    };

    issue(0, 0);
    cp_commit();

    const uint32_t aoff = (uint32_t)((wr * 32 + (lane & 15)) * LDT + (lane >> 4) * 8) * 2u;
    const uint32_t boff = (uint32_t)((wc * 64 + (lane & 7) + ((lane >> 4) & 1) * 8) * LDT
                                     + ((lane >> 3) & 1) * 8) * 2u;

    for (int c = 0; c < NC; c++) {
        cp_wait<0>();
        __syncthreads();
        if (c + 1 < NC) { issue(c + 1, (c + 1) & 1); cp_commit(); }

        const uint32_t st = sbase + (uint32_t)(c & 1) * STAGE_BYTES;
        #pragma unroll
        for (int ks = 0; ks < 2; ks++) {
            const uint32_t ko = (uint32_t)(ks * 16) * 2u;
            uint32_t av[2][4], bh[4][4], bl[4][4];
            #pragma unroll
            for (int mt = 0; mt < 2; mt++) {
                uint32_t ro = aoff + (uint32_t)(mt * 16 * LDT) * 2u + ko;
                ldmx4(av[mt], st + ro);
            }
            #pragma unroll
            for (int np = 0; np < 4; np++) {
                uint32_t ro = boff + (uint32_t)(np * 16 * LDT) * 2u + ko;
                ldmx4(bh[np], st + TILE_BYTES + ro);
                ldmx4(bl[np], st + 2u * TILE_BYTES + ro);
            }
            #pragma unroll
            for (int mt = 0; mt < 2; mt++)
                #pragma unroll
                for (int nt = 0; nt < 8; nt++) {
                    const int np = nt >> 1, half = (nt & 1) * 2;
                    mma16816(acc[mt][nt], av[mt], bh[np][half], bh[np][half + 1]);
                    mma16816(acc[mt][nt], av[mt], bl[np][half], bl[np][half + 1]);
                }
        }
    }

    // epilogue
    const int g  = lane >> 2;
    const int tg = lane & 3;
    float* Cpart = Cf;
    if (SPLITK > 1) Cpart = (blockIdx.z == 0) ? Cf : (blockIdx.z == 1 ? Cp1 : Cp2);
    #pragma unroll
    for (int mt = 0; mt < 2; mt++) {
        #pragma unroll
        for (int nt = 0; nt < 8; nt++) {
            int col = bn + wc * 64 + nt * 8 + tg * 2;
            float2 bv = (SPLITK > 1) ? make_float2(0.f, 0.f)
                                     : *(const float2*)(bias + col);
            #pragma unroll
            for (int half = 0; half < 2; half++) {
                int row = bm + wr * 32 + mt * 16 + g + half * 8;
                float v0 = acc[mt][nt][half * 2 + 0] + bv.x;
                float v1 = acc[mt][nt][half * 2 + 1] + bv.y;
                size_t idx = (size_t)row * N + col;
                if (GELU) { v0 = gelu_tanh(v0); v1 = gelu_tanh(v1); }
                if (OUTH) {
                    *(__half2*)(Ch + idx) = __floats2half2_rn(v0, v1);
                } else {
                    *(float2*)(Cpart + idx) = make_float2(v0, v1);
                }
            }
        }
    }
}

// ---------------------------------------------------------------------------
// Split-K3 reduction: o = p0 + p1 + p2 + bias + res   (f32, 768 cols)
// ---------------------------------------------------------------------------
__global__ void addred3_kernel(const float* __restrict__ p0,
                               const float* __restrict__ p1,
                               const float* __restrict__ p2,
                               const float* __restrict__ bias,
                               const float* __restrict__ res,
                               float* __restrict__ o)
{
    int i = (blockIdx.x * 256 + threadIdx.x);
    int col4 = i % (D_ / 4);
    float4 a = ((const float4*)p0)[i];
    float4 b = ((const float4*)p1)[i];
    float4 c = ((const float4*)p2)[i];
    float4 d = ((const float4*)bias)[col4];
    float4 r = ((const float4*)res)[i];
    float4 v;
    v.x = a.x + b.x + c.x + d.x + r.x;
    v.y = a.y + b.y + c.y + d.y + r.y;
    v.z = a.z + b.z + c.z + d.z + r.z;
    v.w = a.w + b.w + c.w + d.w + r.w;
    ((float4*)o)[i] = v;
}

// ---------------------------------------------------------------------------
// FAVOR+ features. Thread owns one m (t&63) and 8 rows.
// ---------------------------------------------------------------------------
__global__ void phi_kernel(const float* __restrict__ qkv,
                           const float* __restrict__ wfeat,
                           float* __restrict__ phiq,
                           float* __restrict__ phik)
{
    const int sc = blockIdx.x;
    const int hy = blockIdx.y;
    const int b  = blockIdx.z;
    const int h  = hy % H_;
    const int qk = hy / H_;

    __shared__ float wfT[64][65];
    __shared__ float xs[32][64];
    __shared__ float sqs[32];

    const int t = threadIdx.x;

    #pragma unroll
    for (int i = 0; i < 16; i++) {
        int idx = t + i * 256;
        wfT[idx & 63][idx >> 6] = wfeat[idx];
    }

    const float scale = 0.3535533905932738f;
    const int s0   = sc * 32;
    const int col0 = qk * D_ + h * DH_;

    #pragma unroll
    for (int i = 0; i < 8; i++) {
        int idx = t + i * 256;
        int sl = idx >> 6, d = idx & 63;
        xs[sl][d] = qkv[(size_t)(b * S_ + s0 + sl) * QKV_ + col0 + d] * scale;
    }
    __syncthreads();

    {
        int sl = t >> 3, p = t & 7;
        float acc = 0.f;
        #pragma unroll
        for (int dd = 0; dd < 8; dd++) {
            float xv = xs[sl][p * 8 + dd];
            acc = fmaf(xv, xv, acc);
        }
        acc += __shfl_xor_sync(0xffffffffu, acc, 1);
        acc += __shfl_xor_sync(0xffffffffu, acc, 2);
        acc += __shfl_xor_sync(0xffffffffu, acc, 4);
        if (p == 0) sqs[sl] = 0.5f * acc;
    }
    __syncthreads();

    const int m   = t & 63;
    const int sl0 = t >> 6;          // 0..3
    float acc[8];
    #pragma unroll
    for (int j = 0; j < 8; j++) acc[j] = 0.f;

    #pragma unroll 8
    for (int d = 0; d < 64; d++) {
        float wf = wfT[d][m];
        #pragma unroll
        for (int j = 0; j < 8; j++)
            acc[j] = fmaf(xs[sl0 + 4 * j][d], wf, acc[j]);
    }

    float* dst = qk ? phik : phiq;
    #pragma unroll
    for (int j = 0; j < 8; j++) {
        int sl = sl0 + 4 * j;
        float ph = __expf(acc[j] - sqs[sl]) * 0.125f + 1e-6f;
        dst[(size_t)((b * H_ + h) * S_ + s0 + sl) * M_ + m] = ph;
    }
}

// ---------------------------------------------------------------------------
// Scan pass 1: per-(bh, chunk) totals of phik (x) v and phik.
// ---------------------------------------------------------------------------
__global__ void scan_tot_kernel(const float* __restrict__ qkv,
                                const float* __restrict__ phik,
                                float* __restrict__ kvt,
                                float* __restrict__ kst)
{
    const int bc = blockIdx.x;
    const int bh = bc / NCH;
    const int ch = bc % NCH;
    const int b  = bh / H_;
    const int h  = bh % H_;
    const int t  = threadIdx.x;
    const int d  = t >> 2;
    const int mg = t & 3;

    float kv[16], ks[16];
    #pragma unroll
    for (int i = 0; i < 16; i++) { kv[i] = 0.f; ks[i] = 0.f; }

    const int s0 = ch * CHL;
    const float* pk = phik + (size_t)bh * S_ * M_ + (size_t)s0 * M_ + mg * 16;
    const float* pv = qkv  + (size_t)(b * S_ + s0) * QKV_ + 2 * D_ + h * DH_ + d;

    for (int s = 0; s < CHL; s++) {
        const float4* pk4 = (const float4*)pk;
        float kr[16];
        ((float4*)kr)[0] = pk4[0]; ((float4*)kr)[1] = pk4[1];
        ((float4*)kr)[2] = pk4[2]; ((float4*)kr)[3] = pk4[3];
        float vv = *pv;
        #pragma unroll
        for (int i = 0; i < 16; i++) {
            kv[i] = fmaf(kr[i], vv, kv[i]);
            ks[i] += kr[i];
        }
        pk += M_; pv += QKV_;
    }

    size_t base = (size_t)bc * M_ + mg * 16;
    #pragma unroll
    for (int i = 0; i < 16; i++) {
        kvt[(base + i) * DH_ + d] = kv[i];
        if (d == 0) kst[base + i] = ks[i];
    }
}

// ---------------------------------------------------------------------------
// Scan prefix: in-place exclusive prefix over chunks per bh. grid = B*H.
// ---------------------------------------------------------------------------
__global__ void scan_pfx_kernel(float* __restrict__ kvt, float* __restrict__ kst)
{
    const int bh = blockIdx.x;
    const int t  = threadIdx.x;

    for (int e = t; e < M_ * DH_; e += 256) {
        float run = 0.f;
        #pragma unroll
        for (int ch = 0; ch < NCH; ch++) {
            size_t idx = ((size_t)(bh * NCH + ch)) * (M_ * DH_) + e;
            float v = kvt[idx];
            kvt[idx] = run;
            run += v;
        }
    }
    if (t < M_) {
        float run = 0.f;
        #pragma unroll
        for (int ch = 0; ch < NCH; ch++) {
            size_t idx = ((size_t)(bh * NCH + ch)) * M_ + t;
            float v = kst[idx];
            kst[idx] = run;
            run += v;
        }
    }
}

// ---------------------------------------------------------------------------
// Scan pass 2: local inclusive scan per (bh, chunk), seeded by exclusive
// prefix totals. Output fp16.
// ---------------------------------------------------------------------------
__global__ void scan_kernel(const float* __restrict__ qkv,
                            const float* __restrict__ phiq,
                            const float* __restrict__ phik,
                            const float* __restrict__ kvt,
                            const float* __restrict__ kst,
                            fp16* __restrict__ ao)
{
    const int bc = blockIdx.x;
    const int bh = bc / NCH;
    const int ch = bc % NCH;
    const int b  = bh / H_;
    const int h  = bh % H_;
    const int t  = threadIdx.x;
    const int d  = t >> 2;
    const int mg = t & 3;

    float kv[16], ks[16];
    size_t sbase = (size_t)bc * M_ + mg * 16;
    #pragma unroll
    for (int i = 0; i < 16; i++) {
        kv[i] = kvt[(sbase + i) * DH_ + d];
        ks[i] = kst[sbase + i];
    }

    const int s0 = ch * CHL;
    const float* pq = phiq + (size_t)bh * S_ * M_ + (size_t)s0 * M_ + mg * 16;
    const float* pk = phik + (size_t)bh * S_ * M_ + (size_t)s0 * M_ + mg * 16;
    const float* pv = qkv  + (size_t)(b * S_ + s0) * QKV_ + 2 * D_ + h * DH_ + d;
    size_t obase = (size_t)(b * S_ + s0) * D_ + h * DH_ + d;

    for (int s = 0; s < CHL; s++) {
        const float4* pk4 = (const float4*)pk;
        const float4* pq4 = (const float4*)pq;
        float kr[16], qr[16];
        ((float4*)kr)[0] = pk4[0]; ((float4*)kr)[1] = pk4[1];
        ((float4*)kr)[2] = pk4[2]; ((float4*)kr)[3] = pk4[3];
        ((float4*)qr)[0] = pq4[0]; ((float4*)qr)[1] = pq4[1];
        ((float4*)qr)[2] = pq4[2]; ((float4*)qr)[3] = pq4[3];
        float vv = *pv;

        float num = 0.f, den = 0.f;
        #pragma unroll
        for (int i = 0; i < 16; i++) {
            kv[i] = fmaf(kr[i], vv, kv[i]);
            ks[i] += kr[i];
            num = fmaf(qr[i], kv[i], num);
            den = fmaf(qr[i], ks[i], den);
        }
        num += __shfl_xor_sync(0xffffffffu, num, 1);
        den += __shfl_xor_sync(0xffffffffu, den, 1);
        num += __shfl_xor_sync(0xffffffffu, num, 2);
        den += __shfl_xor_sync(0xffffffffu, den, 2);

        if (mg == 0) ao[obase] = __float2half_rn(num / den);

        pq += M_; pk += M_; pv += QKV_; obase += D_;
    }
}

// ---------------------------------------------------------------------------
// Launch
// ---------------------------------------------------------------------------
extern "C" void kernel_launch(void* const* d_in, const int* in_sizes, int n_in,
                              void* d_out, int out_size)
{
    const float* x      = (const float*)d_in[0];
    const float* ln1_g  = (const float*)d_in[1];
    const float* ln1_b  = (const float*)d_in[2];
    const float* w_attn = (const float*)d_in[3];
    const float* b_attn = (const float*)d_in[4];
    const float* w_feat = (const float*)d_in[5];
    const float* w_proj = (const float*)d_in[6];
    const float* b_proj = (const float*)d_in[7];
    const float* ln2_g  = (const float*)d_in[8];
    const float* ln2_b  = (const float*)d_in[9];
    const float* w_fc   = (const float*)d_in[10];
    const float* b_fc   = (const float*)d_in[11];
    const float* w_out  = (const float*)d_in[12];
    const float* b_out  = (const float*)d_in[13];
    float* out = (float*)d_out;

    fp16 *a, *at, *hh, *ff;
    fp16 *wA_hi, *wA_lo, *wP_hi, *wP_lo, *wF_hi, *wF_lo, *wO_hi, *wO_lo;
    float *qkv, *phiq, *phik, *x1, *kvt, *kst, *sp0, *sp1, *sp2;
    cudaGetSymbolAddress((void**)&a,     g_a);
    cudaGetSymbolAddress((void**)&qkv,   g_qkv);
    cudaGetSymbolAddress((void**)&phiq,  g_phiq);
    cudaGetSymbolAddress((void**)&phik,  g_phik);
    cudaGetSymbolAddress((void**)&at,    g_at);
    cudaGetSymbolAddress((void**)&x1,    g_x1);
    cudaGetSymbolAddress((void**)&hh,    g_h);
    cudaGetSymbolAddress((void**)&ff,    g_ff);
    cudaGetSymbolAddress((void**)&sp0,   g_sp0);
    cudaGetSymbolAddress((void**)&sp1,   g_sp1);
    cudaGetSymbolAddress((void**)&sp2,   g_sp2);
    cudaGetSymbolAddress((void**)&kvt,   g_kvt);
    cudaGetSymbolAddress((void**)&kst,   g_kst);
    cudaGetSymbolAddress((void**)&wA_hi, g_wA_hi);
    cudaGetSymbolAddress((void**)&wA_lo, g_wA_lo);
    cudaGetSymbolAddress((void**)&wP_hi, g_wP_hi);
    cudaGetSymbolAddress((void**)&wP_lo, g_wP_lo);
    cudaGetSymbolAddress((void**)&wF_hi, g_wF_hi);
    cudaGetSymbolAddress((void**)&wF_lo, g_wF_lo);
    cudaGetSymbolAddress((void**)&wO_hi, g_wO_hi);
    cudaGetSymbolAddress((void**)&wO_lo, g_wO_lo);

    cudaFuncSetAttribute(gemm_mma<0,0,1>, cudaFuncAttributeMaxDynamicSharedMemorySize, GEMM_SMEM);
    cudaFuncSetAttribute(gemm_mma<0,0,3>, cudaFuncAttributeMaxDynamicSharedMemorySize, GEMM_SMEM);
    cudaFuncSetAttribute(gemm_mma<1,1,1>, cudaFuncAttributeMaxDynamicSharedMemorySize, GEMM_SMEM);

    // 0. fused weight transpose+split
    wconv_all<<<6912, dim3(32, 8)>>>(w_attn, w_proj, w_fc, w_out,
                                     wA_hi, wA_lo, wP_hi, wP_lo,
                                     wF_hi, wF_lo, wO_hi, wO_lo);

    // 1. LN1 -> a (fp16)
    ln_kernel<<<NT_, 256>>>(x, ln1_g, ln1_b, a);

    // 2. qkv = a @ w_attn + b_attn   [2048 x 2304], f32 out
    gemm_mma<0,0,1><<<dim3(NT_/BM, QKV_/BN), 256, GEMM_SMEM>>>(
        a, wA_hi, wA_lo, b_attn, qkv, nullptr, nullptr, nullptr, D_, QKV_);

    // 3. FAVOR+ features
    phi_kernel<<<dim3(S_/32, H_*2, B_), 256>>>(qkv, w_feat, phiq, phik);

    // 4. chunked causal scan
    scan_tot_kernel<<<B_*H_*NCH, 256>>>(qkv, phik, kvt, kst);
    scan_pfx_kernel<<<B_*H_, 256>>>(kvt, kst);
    scan_kernel<<<B_*H_*NCH, 256>>>(qkv, phiq, phik, kvt, kst, at);

    // 5. attn @ w_proj  (split-K3, reduce fused with LN2)
    gemm_mma<0,0,3><<<dim3(NT_/BM, D_/BN, 3), 256, GEMM_SMEM>>>(
        at, wP_hi, wP_lo, b_proj, sp0, sp1, sp2, nullptr, D_, D_);

    // 6. fused: x1 = p0+p1+p2+bias+x ; h = LN2(x1) (fp16)
    addln_kernel<<<NT_, 256>>>(sp0, sp1, sp2, b_proj, x, ln2_g, ln2_b, x1, hh);

    // 7. ff = gelu(h @ w_fc + b_fc)   [2048 x 3072], fp16 out
    gemm_mma<1,1,1><<<dim3(NT_/BM, DFF_/BN), 256, GEMM_SMEM>>>(
        hh, wF_hi, wF_lo, b_fc, nullptr, nullptr, nullptr, ff, D_, DFF_);

    // 8. out = x1 + ff @ w_out + b_out  (split-K3 + reduce)
    gemm_mma<0,0,3><<<dim3(NT_/BM, D_/BN, 3), 256, GEMM_SMEM>>>(
        ff, wO_hi, wO_lo, b_out, sp0, sp1, sp2, nullptr, DFF_, D_);
    addred3_kernel<<<(NT_*D_/4)/256, 256>>>(sp0, sp1, sp2, b_out, x1, out);
}

// round 11
// speedup vs baseline: 2.1528x; 1.2848x over previous
#include <cuda_runtime.h>
#include <cuda_fp16.h>
#include <cstdint>

// ---------------------------------------------------------------------------
// Problem constants
// ---------------------------------------------------------------------------
#define B_  2
#define S_  1024
#define D_  768
#define H_  12
#define DH_ 64
#define M_  64
#define DFF_ 3072
#define NT_ (B_ * S_)          // 2048 tokens
#define QKV_ (3 * D_)          // 2304
#define NCH 16                 // scan chunks
#define CHL (S_ / NCH)         // 64 steps per chunk

typedef __half fp16;

// ---------------------------------------------------------------------------
// Scratch (__device__ globals; no allocation allowed)
// ---------------------------------------------------------------------------
__device__ fp16  g_a   [NT_ * D_];        // LN1 out (fp16)
__device__ float g_qkv [NT_ * QKV_];
__device__ float g_phiq[B_ * H_ * S_ * M_];
__device__ float g_phik[B_ * H_ * S_ * M_];
__device__ fp16  g_at  [NT_ * D_];        // attention out (fp16)
__device__ float g_x1  [NT_ * D_];
__device__ fp16  g_h   [NT_ * D_];        // LN2 out (fp16)
__device__ fp16  g_ff  [NT_ * DFF_];      // gelu out (fp16)
// split-K partial buffers
__device__ float g_sp0 [NT_ * D_];
__device__ float g_sp1 [NT_ * D_];
__device__ float g_sp2 [NT_ * D_];
// scan chunk totals -> exclusive prefixes
__device__ float g_kvt [B_ * H_ * NCH * M_ * DH_];
__device__ float g_kst [B_ * H_ * NCH * M_];
// transposed fp16 weights: Wt[n][k] = W[k][n]
__device__ fp16  g_wA [QKV_ * D_];
__device__ fp16  g_wP [D_ * D_];
__device__ fp16  g_wF [DFF_ * D_];
__device__ fp16  g_wO [D_ * DFF_];

// ---------------------------------------------------------------------------
// Small helpers
// ---------------------------------------------------------------------------
__device__ __forceinline__ uint32_t smem_to_u32(const void* p) {
    uint32_t a;
    asm("{ .reg .u64 t; cvta.to.shared.u64 t, %1; cvt.u32.u64 %0, t; }"
        : "=r"(a) : "l"(p));
    return a;
}

__device__ __forceinline__ float gelu_tanh(float x)
{
    float x3 = x * x * x;
    float u  = 0.7978845608028654f * (x + 0.044715f * x3);
    return 0.5f * x * (1.0f + tanhf(u));
}

__device__ __forceinline__ void cp_async16(uint32_t saddr, const void* gaddr) {
    asm volatile("cp.async.cg.shared.global [%0], [%1], 16;"
                 :: "r"(saddr), "l"(gaddr));
}
__device__ __forceinline__ void cp_commit() {
    asm volatile("cp.async.commit_group;");
}
template<int N>
__device__ __forceinline__ void cp_wait() {
    asm volatile("cp.async.wait_group %0;" :: "n"(N));
}

__device__ __forceinline__ void ldmx4(uint32_t* r, uint32_t addr) {
    asm volatile("ldmatrix.sync.aligned.m8n8.x4.shared.b16 {%0,%1,%2,%3}, [%4];"
                 : "=r"(r[0]), "=r"(r[1]), "=r"(r[2]), "=r"(r[3]) : "r"(addr));
}

// mma.sync m16n8k16 row.col f32 += f16*f16
__device__ __forceinline__ void mma16816(float* c, const uint32_t* a,
                                         uint32_t b0, uint32_t b1) {
    asm volatile(
        "mma.sync.aligned.m16n8k16.row.col.f32.f16.f16.f32 "
        "{%0,%1,%2,%3}, {%4,%5,%6,%7}, {%8,%9}, {%0,%1,%2,%3};"
        : "+f"(c[0]), "+f"(c[1]), "+f"(c[2]), "+f"(c[3])
        : "r"(a[0]), "r"(a[1]), "r"(a[2]), "r"(a[3]), "r"(b0), "r"(b1));
}

// ---------------------------------------------------------------------------
// LayerNorm -> fp16 output
// ---------------------------------------------------------------------------
__global__ void ln_kernel(const float* __restrict__ x,
                          const float* __restrict__ g,
                          const float* __restrict__ b,
                          fp16* __restrict__ o)
{
    int row = blockIdx.x;
    int t   = threadIdx.x;
    const float* xr = x + (size_t)row * D_;

    float v0 = xr[t], v1 = xr[t + 256], v2 = xr[t + 512];
    float s  = v0 + v1 + v2;
    float sq = v0 * v0 + v1 * v1 + v2 * v2;

    #pragma unroll
    for (int off = 16; off; off >>= 1) {
        s  += __shfl_xor_sync(0xffffffffu, s,  off);
        sq += __shfl_xor_sync(0xffffffffu, sq, off);
    }
    __shared__ float red[16];
    int w = t >> 5, l = t & 31;
    if (l == 0) { red[w] = s; red[w + 8] = sq; }
    __syncthreads();
    s = 0.f; sq = 0.f;
    #pragma unroll
    for (int i = 0; i < 8; i++) { s += red[i]; sq += red[8 + i]; }

    const float inv = 1.0f / (float)D_;
    float mean = s * inv;
    float var  = sq * inv - mean * mean;
    float rs   = rsqrtf(var + 1e-5f);

    size_t base = (size_t)row * D_;
    float vv[3] = {v0, v1, v2};
    #pragma unroll
    for (int i = 0; i < 3; i++) {
        int c = t + i * 256;
        o[base + c] = __float2half_rn((vv[i] - mean) * rs * g[c] + b[c]);
    }
}

// ---------------------------------------------------------------------------
// Fused split-K3 reduce + residual + bias + LayerNorm -> x1 (f32) + h (fp16)
// ---------------------------------------------------------------------------
__global__ void addln_kernel(const float* __restrict__ p0,
                             const float* __restrict__ p1,
                             const float* __restrict__ p2,
                             const float* __restrict__ bias,
                             const float* __restrict__ res,
                             const float* __restrict__ g,
                             const float* __restrict__ b,
                             float* __restrict__ x1,
                             fp16* __restrict__ o)
{
    int row = blockIdx.x;
    int t   = threadIdx.x;
    size_t base = (size_t)row * D_;

    float vv[3];
    #pragma unroll
    for (int i = 0; i < 3; i++) {
        int c = t + i * 256;
        size_t idx = base + c;
        vv[i] = p0[idx] + p1[idx] + p2[idx] + bias[c] + res[idx];
        x1[idx] = vv[i];
    }

    float s  = vv[0] + vv[1] + vv[2];
    float sq = vv[0]*vv[0] + vv[1]*vv[1] + vv[2]*vv[2];
    #pragma unroll
    for (int off = 16; off; off >>= 1) {
        s  += __shfl_xor_sync(0xffffffffu, s,  off);
        sq += __shfl_xor_sync(0xffffffffu, sq, off);
    }
    __shared__ float red[16];
    int w = t >> 5, l = t & 31;
    if (l == 0) { red[w] = s; red[w + 8] = sq; }
    __syncthreads();
    s = 0.f; sq = 0.f;
    #pragma unroll
    for (int i = 0; i < 8; i++) { s += red[i]; sq += red[8 + i]; }

    const float inv = 1.0f / (float)D_;
    float mean = s * inv;
    float var  = sq * inv - mean * mean;
    float rs   = rsqrtf(var + 1e-5f);

    #pragma unroll
    for (int i = 0; i < 3; i++) {
        int c = t + i * 256;
        o[base + c] = __float2half_rn((vv[i] - mean) * rs * g[c] + b[c]);
    }
}

// ---------------------------------------------------------------------------
// Fused weight transpose + fp16 convert for all 4 weights.
// ---------------------------------------------------------------------------
__global__ void wconv_all(const float* __restrict__ wA, const float* __restrict__ wP,
                          const float* __restrict__ wF, const float* __restrict__ wO,
                          fp16* __restrict__ TA, fp16* __restrict__ TP,
                          fp16* __restrict__ TF, fp16* __restrict__ TO)
{
    int t = blockIdx.x;
    const float* W; fp16 *T; int K, N, nx;
    if (t < 1728)      { W = wA; T = TA; K = D_;  N = QKV_; nx = 72; }
    else if (t < 2304) { t -= 1728; W = wP; T = TP; K = D_;  N = D_;   nx = 24; }
    else if (t < 4608) { t -= 2304; W = wF; T = TF; K = D_;  N = DFF_; nx = 96; }
    else               { t -= 4608; W = wO; T = TO; K = DFF_; N = D_;  nx = 24; }
    int n0 = (t % nx) * 32, k0 = (t / nx) * 32;

    __shared__ float tile[32][33];
    int tx = threadIdx.x, ty = threadIdx.y;
    #pragma unroll
    for (int i = 0; i < 4; i++)
        tile[ty + i * 8][tx] = W[(size_t)(k0 + ty + i * 8) * N + n0 + tx];
    __syncthreads();
    #pragma unroll
    for (int i = 0; i < 4; i++) {
        float v = tile[tx][ty + i * 8];
        T[(size_t)(n0 + ty + i * 8) * K + k0 + tx] = __float2half_rn(v);
    }
}

// ---------------------------------------------------------------------------
// HMMA fp16 GEMM: C = A @ W^T, both single fp16, fp32 accum.
// CTA 128x128, BKC=32, 2 tiles/stage, 3-stage cp.async pipeline (60KB).
// SPLITK>1: blockIdx.z picks K slice; raw f32 partials.
// ---------------------------------------------------------------------------
#define BM 128
#define BN 128
#define BKC 32
#define LDT 40                         // padded row (fp16) = 80B
#define TILE_BYTES (BM * LDT * 2)      // 10240
#define STAGE_BYTES (2 * TILE_BYTES)   // 20480
#define NSTAGE 3
#define GEMM_SMEM (NSTAGE * STAGE_BYTES)   // 61440

template<int GELU, int OUTH, int SPLITK>
__global__ void __launch_bounds__(256)
gemm_mma(const fp16* __restrict__ A,
         const fp16* __restrict__ Bw,
         const float* __restrict__ bias,
         float* __restrict__ Cf, float* __restrict__ Cp1, float* __restrict__ Cp2,
         fp16* __restrict__ Ch,
         int K, int N)
{
    extern __shared__ char smem[];
    const uint32_t sbase = smem_to_u32(smem);

    const int tid  = threadIdx.x;
    const int lane = tid & 31;
    const int w    = tid >> 5;
    const int wr   = w & 3;
    const int wc   = w >> 2;
    const int bm   = blockIdx.x * BM;
    const int bn   = blockIdx.y * BN;
    const int Keff = K / SPLITK;
    const int kbase = (SPLITK > 1) ? (int)blockIdx.z * Keff : 0;

    float acc[2][8][4];
    #pragma unroll
    for (int i = 0; i < 2; i++)
        #pragma unroll
        for (int j = 0; j < 8; j++)
            #pragma unroll
            for (int q = 0; q < 4; q++) acc[i][j][q] = 0.f;

    const int NC = Keff / BKC;

    const int lrow = tid >> 1;
    const int lseg = (tid & 1) * 2;
    const uint32_t lsm = (uint32_t)(lrow * LDT + lseg * 8) * 2u;

    auto issue = [&](int c, int st) {
        int k0 = kbase + c * BKC;
        const fp16* sa = A  + (size_t)(bm + lrow) * K + k0 + lseg * 8;
        const fp16* sb = Bw + (size_t)(bn + lrow) * K + k0 + lseg * 8;
        uint32_t sbm = sbase + (uint32_t)st * STAGE_BYTES + lsm;
        cp_async16(sbm,                     sa);
        cp_async16(sbm + 16u,               sa + 8);
        cp_async16(sbm + TILE_BYTES,        sb);
        cp_async16(sbm + TILE_BYTES + 16u,  sb + 8);
    };

    issue(0, 0); cp_commit();
    if (NC > 1) { issue(1, 1); cp_commit(); }

    const uint32_t aoff = (uint32_t)((wr * 32 + (lane & 15)) * LDT + (lane >> 4) * 8) * 2u;
    const uint32_t boff = (uint32_t)((wc * 64 + (lane & 7) + ((lane >> 4) & 1) * 8) * LDT
                                     + ((lane >> 3) & 1) * 8) * 2u;

    int st = 0;
    for (int c = 0; c < NC; c++) {
        if (c == NC - 1) cp_wait<0>(); else cp_wait<1>();
        __syncthreads();
        if (c + 2 < NC) {
            int nst = st + 2; if (nst >= NSTAGE) nst -= NSTAGE;
            issue(c + 2, nst);
            cp_commit();
        }

        const uint32_t sst = sbase + (uint32_t)st * STAGE_BYTES;
        #pragma unroll
        for (int ks = 0; ks < 2; ks++) {
            const uint32_t ko = (uint32_t)(ks * 16) * 2u;
            uint32_t av[2][4], bv[4][4];
            #pragma unroll
            for (int mt = 0; mt < 2; mt++) {
                uint32_t ro = aoff + (uint32_t)(mt * 16 * LDT) * 2u + ko;
                ldmx4(av[mt], sst + ro);
            }
            #pragma unroll
            for (int np = 0; np < 4; np++) {
                uint32_t ro = boff + (uint32_t)(np * 16 * LDT) * 2u + ko;
                ldmx4(bv[np], sst + TILE_BYTES + ro);
            }
            #pragma unroll
            for (int mt = 0; mt < 2; mt++)
                #pragma unroll
                for (int nt = 0; nt < 8; nt++) {
                    const int np = nt >> 1, half = (nt & 1) * 2;
                    mma16816(acc[mt][nt], av[mt], bv[np][half], bv[np][half + 1]);
                }
        }
        if (++st == NSTAGE) st = 0;
    }

    // epilogue
    const int g  = lane >> 2;
    const int tg = lane & 3;
    float* Cpart = Cf;
    if (SPLITK > 1) Cpart = (blockIdx.z == 0) ? Cf : (blockIdx.z == 1 ? Cp1 : Cp2);
    #pragma unroll
    for (int mt = 0; mt < 2; mt++) {
        #pragma unroll
        for (int nt = 0; nt < 8; nt++) {
            int col = bn + wc * 64 + nt * 8 + tg * 2;
            float2 bvv = (SPLITK > 1) ? make_float2(0.f, 0.f)
                                      : *(const float2*)(bias + col);
            #pragma unroll
            for (int half = 0; half < 2; half++) {
                int row = bm + wr * 32 + mt * 16 + g + half * 8;
                float v0 = acc[mt][nt][half * 2 + 0] + bvv.x;
                float v1 = acc[mt][nt][half * 2 + 1] + bvv.y;
                size_t idx = (size_t)row * N + col;
                if (GELU) { v0 = gelu_tanh(v0); v1 = gelu_tanh(v1); }
                if (OUTH) {
                    *(__half2*)(Ch + idx) = __floats2half2_rn(v0, v1);
                } else {
                    *(float2*)(Cpart + idx) = make_float2(v0, v1);
                }
            }
        }
    }
}

// ---------------------------------------------------------------------------
// Split-K3 reduction: o = p0 + p1 + p2 + bias + res   (f32, 768 cols)
// ---------------------------------------------------------------------------
__global__ void addred3_kernel(const float* __restrict__ p0,
                               const float* __restrict__ p1,
                               const float* __restrict__ p2,
                               const float* __restrict__ bias,
                               const float* __restrict__ res,
                               float* __restrict__ o)
{
    int i = (blockIdx.x * 256 + threadIdx.x);
    int col4 = i % (D_ / 4);
    float4 a = ((const float4*)p0)[i];
    float4 b = ((const float4*)p1)[i];
    float4 c = ((const float4*)p2)[i];
    float4 d = ((const float4*)bias)[col4];
    float4 r = ((const float4*)res)[i];
    float4 v;
    v.x = a.x + b.x + c.x + d.x + r.x;
    v.y = a.y + b.y + c.y + d.y + r.y;
    v.z = a.z + b.z + c.z + d.z + r.z;
    v.w = a.w + b.w + c.w + d.w + r.w;
    ((float4*)o)[i] = v;
}

// ---------------------------------------------------------------------------
// FAVOR+ features. Thread owns one m (t&63) and 8 rows.
// ---------------------------------------------------------------------------
__global__ void phi_kernel(const float* __restrict__ qkv,
                           const float* __restrict__ wfeat,
                           float* __restrict__ phiq,
                           float* __restrict__ phik)
{
    const int sc = blockIdx.x;
    const int hy = blockIdx.y;
    const int b  = blockIdx.z;
    const int h  = hy % H_;
    const int qk = hy / H_;

    __shared__ float wfT[64][65];
    __shared__ float xs[32][64];
    __shared__ float sqs[32];

    const int t = threadIdx.x;

    #pragma unroll
    for (int i = 0; i < 16; i++) {
        int idx = t + i * 256;
        wfT[idx & 63][idx >> 6] = wfeat[idx];
    }

    const float scale = 0.3535533905932738f;
    const int s0   = sc * 32;
    const int col0 = qk * D_ + h * DH_;

    #pragma unroll
    for (int i = 0; i < 8; i++) {
        int idx = t + i * 256;
        int sl = idx >> 6, d = idx & 63;
        xs[sl][d] = qkv[(size_t)(b * S_ + s0 + sl) * QKV_ + col0 + d] * scale;
    }
    __syncthreads();

    {
        int sl = t >> 3, p = t & 7;
        float acc = 0.f;
        #pragma unroll
        for (int dd = 0; dd < 8; dd++) {
            float xv = xs[sl][p * 8 + dd];
            acc = fmaf(xv, xv, acc);
        }
        acc += __shfl_xor_sync(0xffffffffu, acc, 1);
        acc += __shfl_xor_sync(0xffffffffu, acc, 2);
        acc += __shfl_xor_sync(0xffffffffu, acc, 4);
        if (p == 0) sqs[sl] = 0.5f * acc;
    }
    __syncthreads();

    const int m   = t & 63;
    const int sl0 = t >> 6;          // 0..3
    float acc[8];
    #pragma unroll
    for (int j = 0; j < 8; j++) acc[j] = 0.f;

    #pragma unroll 8
    for (int d = 0; d < 64; d++) {
        float wf = wfT[d][m];
        #pragma unroll
        for (int j = 0; j < 8; j++)
            acc[j] = fmaf(xs[sl0 + 4 * j][d], wf, acc[j]);
    }

    float* dst = qk ? phik : phiq;
    #pragma unroll
    for (int j = 0; j < 8; j++) {
        int sl = sl0 + 4 * j;
        float ph = __expf(acc[j] - sqs[sl]) * 0.125f + 1e-6f;
        dst[(size_t)((b * H_ + h) * S_ + s0 + sl) * M_ + m] = ph;
    }
}

// ---------------------------------------------------------------------------
// Scan pass 1: per-(bh, chunk) totals of phik (x) v and phik.
// ---------------------------------------------------------------------------
__global__ void scan_tot_kernel(const float* __restrict__ qkv,
                                const float* __restrict__ phik,
                                float* __restrict__ kvt,
                                float* __restrict__ kst)
{
    const int bc = blockIdx.x;
    const int bh = bc / NCH;
    const int ch = bc % NCH;
    const int b  = bh / H_;
    const int h  = bh % H_;
    const int t  = threadIdx.x;
    const int d  = t >> 2;
    const int mg = t & 3;

    float kv[16], ks[16];
    #pragma unroll
    for (int i = 0; i < 16; i++) { kv[i] = 0.f; ks[i] = 0.f; }

    const int s0 = ch * CHL;
    const float* pk = phik + (size_t)bh * S_ * M_ + (size_t)s0 * M_ + mg * 16;
    const float* pv = qkv  + (size_t)(b * S_ + s0) * QKV_ + 2 * D_ + h * DH_ + d;

    for (int s = 0; s < CHL; s++) {
        const float4* pk4 = (const float4*)pk;
        float kr[16];
        ((float4*)kr)[0] = pk4[0]; ((float4*)kr)[1] = pk4[1];
        ((float4*)kr)[2] = pk4[2]; ((float4*)kr)[3] = pk4[3];
        float vv = *pv;
        #pragma unroll
        for (int i = 0; i < 16; i++) {
            kv[i] = fmaf(kr[i], vv, kv[i]);
            ks[i] += kr[i];
        }
        pk += M_; pv += QKV_;
    }

    size_t base = (size_t)bc * M_ + mg * 16;
    #pragma unroll
    for (int i = 0; i < 16; i++) {
        kvt[(base + i) * DH_ + d] = kv[i];
        if (d == 0) kst[base + i] = ks[i];
    }
}

// ---------------------------------------------------------------------------
// Scan prefix: in-place exclusive prefix over chunks per bh. grid = B*H.
// ---------------------------------------------------------------------------
__global__ void scan_pfx_kernel(float* __restrict__ kvt, float* __restrict__ kst)
{
    const int bh = blockIdx.x;
    const int t  = threadIdx.x;

    for (int e = t; e < M_ * DH_; e += 256) {
        float run = 0.f;
        #pragma unroll
        for (int ch = 0; ch < NCH; ch++) {
            size_t idx = ((size_t)(bh * NCH + ch)) * (M_ * DH_) + e;
            float v = kvt[idx];
            kvt[idx] = run;
            run += v;
        }
    }
    if (t < M_) {
        float run = 0.f;
        #pragma unroll
        for (int ch = 0; ch < NCH; ch++) {
            size_t idx = ((size_t)(bh * NCH + ch)) * M_ + t;
            float v = kst[idx];
            kst[idx] = run;
            run += v;
        }
    }
}

// ---------------------------------------------------------------------------
// Scan pass 2: local inclusive scan per (bh, chunk), seeded by exclusive
// prefix totals. Output fp16.
// ---------------------------------------------------------------------------
__global__ void scan_kernel(const float* __restrict__ qkv,
                            const float* __restrict__ phiq,
                            const float* __restrict__ phik,
                            const float* __restrict__ kvt,
                            const float* __restrict__ kst,
                            fp16* __restrict__ ao)
{
    const int bc = blockIdx.x;
    const int bh = bc / NCH;
    const int ch = bc % NCH;
    const int b  = bh / H_;
    const int h  = bh % H_;
    const int t  = threadIdx.x;
    const int d  = t >> 2;
    const int mg = t & 3;

    float kv[16], ks[16];
    size_t sbase = (size_t)bc * M_ + mg * 16;
    #pragma unroll
    for (int i = 0; i < 16; i++) {
        kv[i] = kvt[(sbase + i) * DH_ + d];
        ks[i] = kst[sbase + i];
    }

    const int s0 = ch * CHL;
    const float* pq = phiq + (size_t)bh * S_ * M_ + (size_t)s0 * M_ + mg * 16;
    const float* pk = phik + (size_t)bh * S_ * M_ + (size_t)s0 * M_ + mg * 16;
    const float* pv = qkv  + (size_t)(b * S_ + s0) * QKV_ + 2 * D_ + h * DH_ + d;
    size_t obase = (size_t)(b * S_ + s0) * D_ + h * DH_ + d;

    for (int s = 0; s < CHL; s++) {
        const float4* pk4 = (const float4*)pk;
        const float4* pq4 = (const float4*)pq;
        float kr[16], qr[16];
        ((float4*)kr)[0] = pk4[0]; ((float4*)kr)[1] = pk4[1];
        ((float4*)kr)[2] = pk4[2]; ((float4*)kr)[3] = pk4[3];
        ((float4*)qr)[0] = pq4[0]; ((float4*)qr)[1] = pq4[1];
        ((float4*)qr)[2] = pq4[2]; ((float4*)qr)[3] = pq4[3];
        float vv = *pv;

        float num = 0.f, den = 0.f;
        #pragma unroll
        for (int i = 0; i < 16; i++) {
            kv[i] = fmaf(kr[i], vv, kv[i]);
            ks[i] += kr[i];
            num = fmaf(qr[i], kv[i], num);
            den = fmaf(qr[i], ks[i], den);
        }
        num += __shfl_xor_sync(0xffffffffu, num, 1);
        den += __shfl_xor_sync(0xffffffffu, den, 1);
        num += __shfl_xor_sync(0xffffffffu, num, 2);
        den += __shfl_xor_sync(0xffffffffu, den, 2);

        if (mg == 0) ao[obase] = __float2half_rn(num / den);

        pq += M_; pk += M_; pv += QKV_; obase += D_;
    }
}

// ---------------------------------------------------------------------------
// Launch
// ---------------------------------------------------------------------------
extern "C" void kernel_launch(void* const* d_in, const int* in_sizes, int n_in,
                              void* d_out, int out_size)
{
    const float* x      = (const float*)d_in[0];
    const float* ln1_g  = (const float*)d_in[1];
    const float* ln1_b  = (const float*)d_in[2];
    const float* w_attn = (const float*)d_in[3];
    const float* b_attn = (const float*)d_in[4];
    const float* w_feat = (const float*)d_in[5];
    const float* w_proj = (const float*)d_in[6];
    const float* b_proj = (const float*)d_in[7];
    const float* ln2_g  = (const float*)d_in[8];
    const float* ln2_b  = (const float*)d_in[9];
    const float* w_fc   = (const float*)d_in[10];
    const float* b_fc   = (const float*)d_in[11];
    const float* w_out  = (const float*)d_in[12];
    const float* b_out  = (const float*)d_in[13];
    float* out = (float*)d_out;

    fp16 *a, *at, *hh, *ff, *wA, *wP, *wF, *wO;
    float *qkv, *phiq, *phik, *x1, *kvt, *kst, *sp0, *sp1, *sp2;
    cudaGetSymbolAddress((void**)&a,    g_a);
    cudaGetSymbolAddress((void**)&qkv,  g_qkv);
    cudaGetSymbolAddress((void**)&phiq, g_phiq);
    cudaGetSymbolAddress((void**)&phik, g_phik);
    cudaGetSymbolAddress((void**)&at,   g_at);
    cudaGetSymbolAddress((void**)&x1,   g_x1);
    cudaGetSymbolAddress((void**)&hh,   g_h);
    cudaGetSymbolAddress((void**)&ff,   g_ff);
    cudaGetSymbolAddress((void**)&sp0,  g_sp0);
    cudaGetSymbolAddress((void**)&sp1,  g_sp1);
    cudaGetSymbolAddress((void**)&sp2,  g_sp2);
    cudaGetSymbolAddress((void**)&kvt,  g_kvt);
    cudaGetSymbolAddress((void**)&kst,  g_kst);
    cudaGetSymbolAddress((void**)&wA,   g_wA);
    cudaGetSymbolAddress((void**)&wP,   g_wP);
    cudaGetSymbolAddress((void**)&wF,   g_wF);
    cudaGetSymbolAddress((void**)&wO,   g_wO);

    cudaFuncSetAttribute(gemm_mma<0,0,1>, cudaFuncAttributeMaxDynamicSharedMemorySize, GEMM_SMEM);
    cudaFuncSetAttribute(gemm_mma<0,0,3>, cudaFuncAttributeMaxDynamicSharedMemorySize, GEMM_SMEM);
    cudaFuncSetAttribute(gemm_mma<1,1,1>, cudaFuncAttributeMaxDynamicSharedMemorySize, GEMM_SMEM);

    // 0. fused weight transpose+convert
    wconv_all<<<6912, dim3(32, 8)>>>(w_attn, w_proj, w_fc, w_out, wA, wP, wF, wO);

    // 1. LN1 -> a (fp16)
    ln_kernel<<<NT_, 256>>>(x, ln1_g, ln1_b, a);

    // 2. qkv = a @ w_attn + b_attn   [2048 x 2304], f32 out
    gemm_mma<0,0,1><<<dim3(NT_/BM, QKV_/BN), 256, GEMM_SMEM>>>(
        a, wA, b_attn, qkv, nullptr, nullptr, nullptr, D_, QKV_);

    // 3. FAVOR+ features
    phi_kernel<<<dim3(S_/32, H_*2, B_), 256>>>(qkv, w_feat, phiq, phik);

    // 4. chunked causal scan
    scan_tot_kernel<<<B_*H_*NCH, 256>>>(qkv, phik, kvt, kst);
    scan_pfx_kernel<<<B_*H_, 256>>>(kvt, kst);
    scan_kernel<<<B_*H_*NCH, 256>>>(qkv, phiq, phik, kvt, kst, at);

    // 5. attn @ w_proj  (split-K3, reduce fused with LN2)
    gemm_mma<0,0,3><<<dim3(NT_/BM, D_/BN, 3), 256, GEMM_SMEM>>>(
        at, wP, b_proj, sp0, sp1, sp2, nullptr, D_, D_);

    // 6. fused: x1 = p0+p1+p2+bias+x ; h = LN2(x1) (fp16)
    addln_kernel<<<NT_, 256>>>(sp0, sp1, sp2, b_proj, x, ln2_g, ln2_b, x1, hh);

    // 7. ff = gelu(h @ w_fc + b_fc)   [2048 x 3072], fp16 out
    gemm_mma<1,1,1><<<dim3(NT_/BM, DFF_/BN), 256, GEMM_SMEM>>>(
        hh, wF, b_fc, nullptr, nullptr, nullptr, ff, D_, DFF_);

    // 8. out = x1 + ff @ w_out + b_out  (split-K3 + reduce)
    gemm_mma<0,0,3><<<dim3(NT_/BM, D_/BN, 3), 256, GEMM_SMEM>>>(
        ff, wO, b_out, sp0, sp1, sp2, nullptr, DFF_, D_);
    addred3_kernel<<<(NT_*D_/4)/256, 256>>>(sp0, sp1, sp2, b_out, x1, out);
}

// round 12
// speedup vs baseline: 2.3423x; 1.0881x over previous
#include <cuda_runtime.h>
#include <cuda_fp16.h>
#include <cstdint>

// ---------------------------------------------------------------------------
// Problem constants
// ---------------------------------------------------------------------------
#define B_  2
#define S_  1024
#define D_  768
#define H_  12
#define DH_ 64
#define M_  64
#define DFF_ 3072
#define NT_ (B_ * S_)          // 2048 tokens
#define QKV_ (3 * D_)          // 2304
#define NCH 32                 // scan chunks
#define CHL (S_ / NCH)         // 32 steps per chunk

typedef __half fp16;

// ---------------------------------------------------------------------------
// Scratch (__device__ globals; no allocation allowed)
// ---------------------------------------------------------------------------
__device__ fp16  g_a   [NT_ * D_];        // LN1 out (fp16)
__device__ fp16  g_qkv [NT_ * QKV_];      // qkv (fp16)
__device__ fp16  g_phiq[B_ * H_ * S_ * M_];
__device__ fp16  g_phik[B_ * H_ * S_ * M_];
__device__ fp16  g_at  [NT_ * D_];        // attention out (fp16)
__device__ float g_x1  [NT_ * D_];
__device__ fp16  g_h   [NT_ * D_];        // LN2 out (fp16)
__device__ fp16  g_ff  [NT_ * DFF_];      // gelu out (fp16)
// split-K partial buffers
__device__ float g_sp0 [NT_ * D_];
__device__ float g_sp1 [NT_ * D_];
__device__ float g_sp2 [NT_ * D_];
// scan chunk totals -> exclusive prefixes (fp32)
__device__ float g_kvt [B_ * H_ * NCH * M_ * DH_];
__device__ float g_kst [B_ * H_ * NCH * M_];
// transposed fp16 weights: Wt[n][k] = W[k][n]
__device__ fp16  g_wA [QKV_ * D_];
__device__ fp16  g_wP [D_ * D_];
__device__ fp16  g_wF [DFF_ * D_];
__device__ fp16  g_wO [D_ * DFF_];

// ---------------------------------------------------------------------------
// Small helpers
// ---------------------------------------------------------------------------
__device__ __forceinline__ uint32_t smem_to_u32(const void* p) {
    uint32_t a;
    asm("{ .reg .u64 t; cvta.to.shared.u64 t, %1; cvt.u32.u64 %0, t; }"
        : "=r"(a) : "l"(p));
    return a;
}

__device__ __forceinline__ float gelu_tanh(float x)
{
    float x3 = x * x * x;
    float u  = 0.7978845608028654f * (x + 0.044715f * x3);
    return 0.5f * x * (1.0f + tanhf(u));
}

__device__ __forceinline__ void cp_async16(uint32_t saddr, const void* gaddr) {
    asm volatile("cp.async.cg.shared.global [%0], [%1], 16;"
                 :: "r"(saddr), "l"(gaddr));
}
__device__ __forceinline__ void cp_commit() {
    asm volatile("cp.async.commit_group;");
}
template<int N>
__device__ __forceinline__ void cp_wait() {
    asm volatile("cp.async.wait_group %0;" :: "n"(N));
}

__device__ __forceinline__ void ldmx4(uint32_t* r, uint32_t addr) {
    asm volatile("ldmatrix.sync.aligned.m8n8.x4.shared.b16 {%0,%1,%2,%3}, [%4];"
                 : "=r"(r[0]), "=r"(r[1]), "=r"(r[2]), "=r"(r[3]) : "r"(addr));
}

// mma.sync m16n8k16 row.col f32 += f16*f16
__device__ __forceinline__ void mma16816(float* c, const uint32_t* a,
                                         uint32_t b0, uint32_t b1) {
    asm volatile(
        "mma.sync.aligned.m16n8k16.row.col.f32.f16.f16.f32 "
        "{%0,%1,%2,%3}, {%4,%5,%6,%7}, {%8,%9}, {%0,%1,%2,%3};"
        : "+f"(c[0]), "+f"(c[1]), "+f"(c[2]), "+f"(c[3])
        : "r"(a[0]), "r"(a[1]), "r"(a[2]), "r"(a[3]), "r"(b0), "r"(b1));
}

// load 16 consecutive fp16 -> 16 floats (32B, two uint4)
__device__ __forceinline__ void ld16h(float* o, const fp16* p) {
    uint4 u0 = ((const uint4*)p)[0];
    uint4 u1 = ((const uint4*)p)[1];
    const __half2* h0 = (const __half2*)&u0;
    const __half2* h1 = (const __half2*)&u1;
    #pragma unroll
    for (int i = 0; i < 4; i++) {
        float2 f = __half22float2(h0[i]); o[2*i]     = f.x; o[2*i + 1]     = f.y;
        float2 g = __half22float2(h1[i]); o[8 + 2*i] = g.x; o[8 + 2*i + 1] = g.y;
    }
}

// ---------------------------------------------------------------------------
// Fused prep: weight transpose+fp16 (blocks 0..6911) + LN1 (blocks 6912..8959)
// ---------------------------------------------------------------------------
__global__ void prep_kernel(const float* __restrict__ wA, const float* __restrict__ wP,
                            const float* __restrict__ wF, const float* __restrict__ wO,
                            fp16* __restrict__ TA, fp16* __restrict__ TP,
                            fp16* __restrict__ TF, fp16* __restrict__ TO,
                            const float* __restrict__ x,
                            const float* __restrict__ g1, const float* __restrict__ b1,
                            fp16* __restrict__ aout)
{
    int blk = blockIdx.x;
    int t = threadIdx.x;

    if (blk < 6912) {
        // weight transpose + convert
        const float* W; fp16 *T; int K, N, nx;
        int tt = blk;
        if (tt < 1728)      { W = wA; T = TA; K = D_;  N = QKV_; nx = 72; }
        else if (tt < 2304) { tt -= 1728; W = wP; T = TP; K = D_;  N = D_;   nx = 24; }
        else if (tt < 4608) { tt -= 2304; W = wF; T = TF; K = D_;  N = DFF_; nx = 96; }
        else                { tt -= 4608; W = wO; T = TO; K = DFF_; N = D_;  nx = 24; }
        int n0 = (tt % nx) * 32, k0 = (tt / nx) * 32;

        __shared__ float tile[32][33];
        int tx = t & 31, ty = t >> 5;
        #pragma unroll
        for (int i = 0; i < 4; i++)
            tile[ty + i * 8][tx] = W[(size_t)(k0 + ty + i * 8) * N + n0 + tx];
        __syncthreads();
        #pragma unroll
        for (int i = 0; i < 4; i++) {
            float v = tile[tx][ty + i * 8];
            T[(size_t)(n0 + ty + i * 8) * K + k0 + tx] = __float2half_rn(v);
        }
        return;
    }

    // LN1 on row = blk - 6912
    int row = blk - 6912;
    const float* xr = x + (size_t)row * D_;
    float v0 = xr[t], v1 = xr[t + 256], v2 = xr[t + 512];
    float s  = v0 + v1 + v2;
    float sq = v0 * v0 + v1 * v1 + v2 * v2;

    #pragma unroll
    for (int off = 16; off; off >>= 1) {
        s  += __shfl_xor_sync(0xffffffffu, s,  off);
        sq += __shfl_xor_sync(0xffffffffu, sq, off);
    }
    __shared__ float red[16];
    int w = t >> 5, l = t & 31;
    if (l == 0) { red[w] = s; red[w + 8] = sq; }
    __syncthreads();
    s = 0.f; sq = 0.f;
    #pragma unroll
    for (int i = 0; i < 8; i++) { s += red[i]; sq += red[8 + i]; }

    const float inv = 1.0f / (float)D_;
    float mean = s * inv;
    float var  = sq * inv - mean * mean;
    float rs   = rsqrtf(var + 1e-5f);

    size_t base = (size_t)row * D_;
    float vv[3] = {v0, v1, v2};
    #pragma unroll
    for (int i = 0; i < 3; i++) {
        int c = t + i * 256;
        aout[base + c] = __float2half_rn((vv[i] - mean) * rs * g1[c] + b1[c]);
    }
}

// ---------------------------------------------------------------------------
// Fused split-K3 reduce + residual + bias + LayerNorm -> x1 (f32) + h (fp16)
// ---------------------------------------------------------------------------
__global__ void addln_kernel(const float* __restrict__ p0,
                             const float* __restrict__ p1,
                             const float* __restrict__ p2,
                             const float* __restrict__ bias,
                             const float* __restrict__ res,
                             const float* __restrict__ g,
                             const float* __restrict__ b,
                             float* __restrict__ x1,
                             fp16* __restrict__ o)
{
    int row = blockIdx.x;
    int t   = threadIdx.x;
    size_t base = (size_t)row * D_;

    float vv[3];
    #pragma unroll
    for (int i = 0; i < 3; i++) {
        int c = t + i * 256;
        size_t idx = base + c;
        vv[i] = p0[idx] + p1[idx] + p2[idx] + bias[c] + res[idx];
        x1[idx] = vv[i];
    }

    float s  = vv[0] + vv[1] + vv[2];
    float sq = vv[0]*vv[0] + vv[1]*vv[1] + vv[2]*vv[2];
    #pragma unroll
    for (int off = 16; off; off >>= 1) {
        s  += __shfl_xor_sync(0xffffffffu, s,  off);
        sq += __shfl_xor_sync(0xffffffffu, sq, off);
    }
    __shared__ float red[16];
    int w = t >> 5, l = t & 31;
    if (l == 0) { red[w] = s; red[w + 8] = sq; }
    __syncthreads();
    s = 0.f; sq = 0.f;
    #pragma unroll
    for (int i = 0; i < 8; i++) { s += red[i]; sq += red[8 + i]; }

    const float inv = 1.0f / (float)D_;
    float mean = s * inv;
    float var  = sq * inv - mean * mean;
    float rs   = rsqrtf(var + 1e-5f);

    #pragma unroll
    for (int i = 0; i < 3; i++) {
        int c = t + i * 256;
        o[base + c] = __float2half_rn((vv[i] - mean) * rs * g[c] + b[c]);
    }
}

// ---------------------------------------------------------------------------
// HMMA fp16 GEMM: C = A @ W^T, fp32 accum.
// CTA 128x128, BKC=32, 2 tiles/stage, 3-stage cp.async pipeline (60KB).
// SPLITK>1: f32 partials. OUTH: fp16 output (with bias/gelu).
// ---------------------------------------------------------------------------
#define BM 128
#define BN 128
#define BKC 32
#define LDT 40                         // padded row (fp16) = 80B
#define TILE_BYTES (BM * LDT * 2)      // 10240
#define STAGE_BYTES (2 * TILE_BYTES)   // 20480
#define NSTAGE 3
#define GEMM_SMEM (NSTAGE * STAGE_BYTES)   // 61440

template<int GELU, int OUTH, int SPLITK>
__global__ void __launch_bounds__(256)
gemm_mma(const fp16* __restrict__ A,
         const fp16* __restrict__ Bw,
         const float* __restrict__ bias,
         float* __restrict__ Cf, float* __restrict__ Cp1, float* __restrict__ Cp2,
         fp16* __restrict__ Ch,
         int K, int N)
{
    extern __shared__ char smem[];
    const uint32_t sbase = smem_to_u32(smem);

    const int tid  = threadIdx.x;
    const int lane = tid & 31;
    const int w    = tid >> 5;
    const int wr   = w & 3;
    const int wc   = w >> 2;
    const int bm   = blockIdx.x * BM;
    const int bn   = blockIdx.y * BN;
    const int Keff = K / SPLITK;
    const int kbase = (SPLITK > 1) ? (int)blockIdx.z * Keff : 0;

    float acc[2][8][4];
    #pragma unroll
    for (int i = 0; i < 2; i++)
        #pragma unroll
        for (int j = 0; j < 8; j++)
            #pragma unroll
            for (int q = 0; q < 4; q++) acc[i][j][q] = 0.f;

    const int NC = Keff / BKC;

    const int lrow = tid >> 1;
    const int lseg = (tid & 1) * 2;
    const uint32_t lsm = (uint32_t)(lrow * LDT + lseg * 8) * 2u;

    auto issue = [&](int c, int st) {
        int k0 = kbase + c * BKC;
        const fp16* sa = A  + (size_t)(bm + lrow) * K + k0 + lseg * 8;
        const fp16* sb = Bw + (size_t)(bn + lrow) * K + k0 + lseg * 8;
        uint32_t sbm = sbase + (uint32_t)st * STAGE_BYTES + lsm;
        cp_async16(sbm,                     sa);
        cp_async16(sbm + 16u,               sa + 8);
        cp_async16(sbm + TILE_BYTES,        sb);
        cp_async16(sbm + TILE_BYTES + 16u,  sb + 8);
    };

    issue(0, 0); cp_commit();
    if (NC > 1) { issue(1, 1); cp_commit(); }

    const uint32_t aoff = (uint32_t)((wr * 32 + (lane & 15)) * LDT + (lane >> 4) * 8) * 2u;
    const uint32_t boff = (uint32_t)((wc * 64 + (lane & 7) + ((lane >> 4) & 1) * 8) * LDT
                                     + ((lane >> 3) & 1) * 8) * 2u;

    int st = 0;
    for (int c = 0; c < NC; c++) {
        if (c == NC - 1) cp_wait<0>(); else cp_wait<1>();
        __syncthreads();
        if (c + 2 < NC) {
            int nst = st + 2; if (nst >= NSTAGE) nst -= NSTAGE;
            issue(c + 2, nst);
            cp_commit();
        }

        const uint32_t sst = sbase + (uint32_t)st * STAGE_BYTES;
        #pragma unroll
        for (int ks = 0; ks < 2; ks++) {
            const uint32_t ko = (uint32_t)(ks * 16) * 2u;
            uint32_t av[2][4], bv[4][4];
            #pragma unroll
            for (int mt = 0; mt < 2; mt++) {
                uint32_t ro = aoff + (uint32_t)(mt * 16 * LDT) * 2u + ko;
                ldmx4(av[mt], sst + ro);
            }
            #pragma unroll
            for (int np = 0; np < 4; np++) {
                uint32_t ro = boff + (uint32_t)(np * 16 * LDT) * 2u + ko;
                ldmx4(bv[np], sst + TILE_BYTES + ro);
            }
            #pragma unroll
            for (int mt = 0; mt < 2; mt++)
                #pragma unroll
                for (int nt = 0; nt < 8; nt++) {
                    const int np = nt >> 1, half = (nt & 1) * 2;
                    mma16816(acc[mt][nt], av[mt], bv[np][half], bv[np][half + 1]);
                }
        }
        if (++st == NSTAGE) st = 0;
    }

    // epilogue
    const int g  = lane >> 2;
    const int tg = lane & 3;
    float* Cpart = Cf;
    if (SPLITK > 1) Cpart = (blockIdx.z == 0) ? Cf : (blockIdx.z == 1 ? Cp1 : Cp2);
    #pragma unroll
    for (int mt = 0; mt < 2; mt++) {
        #pragma unroll
        for (int nt = 0; nt < 8; nt++) {
            int col = bn + wc * 64 + nt * 8 + tg * 2;
            float2 bvv = (SPLITK > 1) ? make_float2(0.f, 0.f)
                                      : *(const float2*)(bias + col);
            #pragma unroll
            for (int half = 0; half < 2; half++) {
                int row = bm + wr * 32 + mt * 16 + g + half * 8;
                float v0 = acc[mt][nt][half * 2 + 0] + bvv.x;
                float v1 = acc[mt][nt][half * 2 + 1] + bvv.y;
                size_t idx = (size_t)row * N + col;
                if (GELU) { v0 = gelu_tanh(v0); v1 = gelu_tanh(v1); }
                if (OUTH) {
                    *(__half2*)(Ch + idx) = __floats2half2_rn(v0, v1);
                } else {
                    *(float2*)(Cpart + idx) = make_float2(v0, v1);
                }
            }
        }
    }
}

// ---------------------------------------------------------------------------
// Split-K3 reduction: o = p0 + p1 + p2 + bias + res   (f32, 768 cols)
// ---------------------------------------------------------------------------
__global__ void addred3_kernel(const float* __restrict__ p0,
                               const float* __restrict__ p1,
                               const float* __restrict__ p2,
                               const float* __restrict__ bias,
                               const float* __restrict__ res,
                               float* __restrict__ o)
{
    int i = (blockIdx.x * 256 + threadIdx.x);
    int col4 = i % (D_ / 4);
    float4 a = ((const float4*)p0)[i];
    float4 b = ((const float4*)p1)[i];
    float4 c = ((const float4*)p2)[i];
    float4 d = ((const float4*)bias)[col4];
    float4 r = ((const float4*)res)[i];
    float4 v;
    v.x = a.x + b.x + c.x + d.x + r.x;
    v.y = a.y + b.y + c.y + d.y + r.y;
    v.z = a.z + b.z + c.z + d.z + r.z;
    v.w = a.w + b.w + c.w + d.w + r.w;
    ((float4*)o)[i] = v;
}

// ---------------------------------------------------------------------------
// FAVOR+ features. qkv fp16 in, phi fp16 out. Thread owns one m + 8 rows.
// Inner loop float2 over d (halves LDS count).
// ---------------------------------------------------------------------------
__global__ void phi_kernel(const fp16* __restrict__ qkv,
                           const float* __restrict__ wfeat,
                           fp16* __restrict__ phiq,
                           fp16* __restrict__ phik)
{
    const int sc = blockIdx.x;
    const int hy = blockIdx.y;
    const int b  = blockIdx.z;
    const int h  = hy % H_;
    const int qk = hy / H_;

    __shared__ float wfT[64][65];     // [d][m]
    __shared__ float xs[32][64];
    __shared__ float sqs[32];

    const int t = threadIdx.x;

    #pragma unroll
    for (int i = 0; i < 16; i++) {
        int idx = t + i * 256;        // idx = m*64 + d
        wfT[idx & 63][idx >> 6] = wfeat[idx];
    }

    const float scale = 0.3535533905932738f;
    const int s0   = sc * 32;
    const int col0 = qk * D_ + h * DH_;

    // load 32x64 fp16 as half2 (1024 half2 / 256 thr = 4 iters)
    #pragma unroll
    for (int i = 0; i < 4; i++) {
        int idx = t + i * 256;
        int sl = idx >> 5, d2 = idx & 31;
        __half2 hv = ((const __half2*)(qkv + (size_t)(b * S_ + s0 + sl) * QKV_ + col0))[d2];
        float2 f = __half22float2(hv);
        xs[sl][2 * d2]     = f.x * scale;
        xs[sl][2 * d2 + 1] = f.y * scale;
    }
    __syncthreads();

    {
        int sl = t >> 3, p = t & 7;
        float acc = 0.f;
        #pragma unroll
        for (int dd = 0; dd < 8; dd++) {
            float xv = xs[sl][p * 8 + dd];
            acc = fmaf(xv, xv, acc);
        }
        acc += __shfl_xor_sync(0xffffffffu, acc, 1);
        acc += __shfl_xor_sync(0xffffffffu, acc, 2);
        acc += __shfl_xor_sync(0xffffffffu, acc, 4);
        if (p == 0) sqs[sl] = 0.5f * acc;
    }
    __syncthreads();

    const int m   = t & 63;
    const int sl0 = t >> 6;          // 0..3
    float acc[8];
    #pragma unroll
    for (int j = 0; j < 8; j++) acc[j] = 0.f;

    #pragma unroll 8
    for (int d = 0; d < 64; d += 2) {
        float wf0 = wfT[d][m];
        float wf1 = wfT[d + 1][m];
        #pragma unroll
        for (int j = 0; j < 8; j++) {
            float2 xv = *(const float2*)&xs[sl0 + 4 * j][d];
            acc[j] = fmaf(xv.x, wf0, acc[j]);
            acc[j] = fmaf(xv.y, wf1, acc[j]);
        }
    }

    fp16* dst = qk ? phik : phiq;
    #pragma unroll
    for (int j = 0; j < 8; j++) {
        int sl = sl0 + 4 * j;
        float ph = __expf(acc[j] - sqs[sl]) * 0.125f + 1e-6f;
        dst[(size_t)((b * H_ + h) * S_ + s0 + sl) * M_ + m] = __float2half_rn(ph);
    }
}

// ---------------------------------------------------------------------------
// Scan pass 1: per-(bh, chunk) totals of phik (x) v and phik.  fp16 inputs.
// ---------------------------------------------------------------------------
__global__ void scan_tot_kernel(const fp16* __restrict__ qkv,
                                const fp16* __restrict__ phik,
                                float* __restrict__ kvt,
                                float* __restrict__ kst)
{
    const int bc = blockIdx.x;
    const int bh = bc / NCH;
    const int ch = bc % NCH;
    const int b  = bh / H_;
    const int h  = bh % H_;
    const int t  = threadIdx.x;
    const int d  = t >> 2;
    const int mg = t & 3;

    float kv[16], ks[16];
    #pragma unroll
    for (int i = 0; i < 16; i++) { kv[i] = 0.f; ks[i] = 0.f; }

    const int s0 = ch * CHL;
    const fp16* pk = phik + (size_t)bh * S_ * M_ + (size_t)s0 * M_ + mg * 16;
    const fp16* pv = qkv  + (size_t)(b * S_ + s0) * QKV_ + 2 * D_ + h * DH_ + d;

    for (int s = 0; s < CHL; s++) {
        float kr[16];
        ld16h(kr, pk);
        float vv = __half2float(*pv);
        #pragma unroll
        for (int i = 0; i < 16; i++) {
            kv[i] = fmaf(kr[i], vv, kv[i]);
            ks[i] += kr[i];
        }
        pk += M_; pv += QKV_;
    }

    size_t base = (size_t)bc * M_ + mg * 16;
    #pragma unroll
    for (int i = 0; i < 16; i++) {
        kvt[(base + i) * DH_ + d] = kv[i];
        if (d == 0) kst[base + i] = ks[i];
    }
}

// ---------------------------------------------------------------------------
// Scan prefix: in-place exclusive prefix over chunks per bh. grid = B*H.
// ---------------------------------------------------------------------------
__global__ void scan_pfx_kernel(float* __restrict__ kvt, float* __restrict__ kst)
{
    const int bh = blockIdx.x;
    const int t  = threadIdx.x;

    for (int e = t; e < M_ * DH_; e += 256) {
        float run = 0.f;
        #pragma unroll
        for (int ch = 0; ch < NCH; ch++) {
            size_t idx = ((size_t)(bh * NCH + ch)) * (M_ * DH_) + e;
            float v = kvt[idx];
            kvt[idx] = run;
            run += v;
        }
    }
    if (t < M_) {
        float run = 0.f;
        #pragma unroll
        for (int ch = 0; ch < NCH; ch++) {
            size_t idx = ((size_t)(bh * NCH + ch)) * M_ + t;
            float v = kst[idx];
            kst[idx] = run;
            run += v;
        }
    }
}

// ---------------------------------------------------------------------------
// Scan pass 2: local inclusive scan per (bh, chunk), seeded by exclusive
// prefix totals. fp16 in/out.
// ---------------------------------------------------------------------------
__global__ void scan_kernel(const fp16* __restrict__ qkv,
                            const fp16* __restrict__ phiq,
                            const fp16* __restrict__ phik,
                            const float* __restrict__ kvt,
                            const float* __restrict__ kst,
                            fp16* __restrict__ ao)
{
    const int bc = blockIdx.x;
    const int bh = bc / NCH;
    const int ch = bc % NCH;
    const int b  = bh / H_;
    const int h  = bh % H_;
    const int t  = threadIdx.x;
    const int d  = t >> 2;
    const int mg = t & 3;

    float kv[16], ks[16];
    size_t sbase = (size_t)bc * M_ + mg * 16;
    #pragma unroll
    for (int i = 0; i < 16; i++) {
        kv[i] = kvt[(sbase + i) * DH_ + d];
        ks[i] = kst[sbase + i];
    }

    const int s0 = ch * CHL;
    const fp16* pq = phiq + (size_t)bh * S_ * M_ + (size_t)s0 * M_ + mg * 16;
    const fp16* pk = phik + (size_t)bh * S_ * M_ + (size_t)s0 * M_ + mg * 16;
    const fp16* pv = qkv  + (size_t)(b * S_ + s0) * QKV_ + 2 * D_ + h * DH_ + d;
    size_t obase = (size_t)(b * S_ + s0) * D_ + h * DH_ + d;

    for (int s = 0; s < CHL; s++) {
        float kr[16], qr[16];
        ld16h(kr, pk);
        ld16h(qr, pq);
        float vv = __half2float(*pv);

        float num = 0.f, den = 0.f;
        #pragma unroll
        for (int i = 0; i < 16; i++) {
            kv[i] = fmaf(kr[i], vv, kv[i]);
            ks[i] += kr[i];
            num = fmaf(qr[i], kv[i], num);
            den = fmaf(qr[i], ks[i], den);
        }
        num += __shfl_xor_sync(0xffffffffu, num, 1);
        den += __shfl_xor_sync(0xffffffffu, den, 1);
        num += __shfl_xor_sync(0xffffffffu, num, 2);
        den += __shfl_xor_sync(0xffffffffu, den, 2);

        if (mg == 0) ao[obase] = __float2half_rn(num / den);

        pq += M_; pk += M_; pv += QKV_; obase += D_;
    }
}

// ---------------------------------------------------------------------------
// Launch
// ---------------------------------------------------------------------------
extern "C" void kernel_launch(void* const* d_in, const int* in_sizes, int n_in,
                              void* d_out, int out_size)
{
    const float* x      = (const float*)d_in[0];
    const float* ln1_g  = (const float*)d_in[1];
    const float* ln1_b  = (const float*)d_in[2];
    const float* w_attn = (const float*)d_in[3];
    const float* b_attn = (const float*)d_in[4];
    const float* w_feat = (const float*)d_in[5];
    const float* w_proj = (const float*)d_in[6];
    const float* b_proj = (const float*)d_in[7];
    const float* ln2_g  = (const float*)d_in[8];
    const float* ln2_b  = (const float*)d_in[9];
    const float* w_fc   = (const float*)d_in[10];
    const float* b_fc   = (const float*)d_in[11];
    const float* w_out  = (const float*)d_in[12];
    const float* b_out  = (const float*)d_in[13];
    float* out = (float*)d_out;

    fp16 *a, *at, *hh, *ff, *wA, *wP, *wF, *wO, *qkvh, *phiq, *phik;
    float *x1, *kvt, *kst, *sp0, *sp1, *sp2;
    cudaGetSymbolAddress((void**)&a,    g_a);
    cudaGetSymbolAddress((void**)&qkvh, g_qkv);
    cudaGetSymbolAddress((void**)&phiq, g_phiq);
    cudaGetSymbolAddress((void**)&phik, g_phik);
    cudaGetSymbolAddress((void**)&at,   g_at);
    cudaGetSymbolAddress((void**)&x1,   g_x1);
    cudaGetSymbolAddress((void**)&hh,   g_h);
    cudaGetSymbolAddress((void**)&ff,   g_ff);
    cudaGetSymbolAddress((void**)&sp0,  g_sp0);
    cudaGetSymbolAddress((void**)&sp1,  g_sp1);
    cudaGetSymbolAddress((void**)&sp2,  g_sp2);
    cudaGetSymbolAddress((void**)&kvt,  g_kvt);
    cudaGetSymbolAddress((void**)&kst,  g_kst);
    cudaGetSymbolAddress((void**)&wA,   g_wA);
    cudaGetSymbolAddress((void**)&wP,   g_wP);
    cudaGetSymbolAddress((void**)&wF,   g_wF);
    cudaGetSymbolAddress((void**)&wO,   g_wO);

    cudaFuncSetAttribute(gemm_mma<0,1,1>, cudaFuncAttributeMaxDynamicSharedMemorySize, GEMM_SMEM);
    cudaFuncSetAttribute(gemm_mma<0,0,3>, cudaFuncAttributeMaxDynamicSharedMemorySize, GEMM_SMEM);
    cudaFuncSetAttribute(gemm_mma<1,1,1>, cudaFuncAttributeMaxDynamicSharedMemorySize, GEMM_SMEM);

    // 0. fused weight transpose+convert + LN1
    prep_kernel<<<6912 + NT_, 256>>>(w_attn, w_proj, w_fc, w_out,
                                     wA, wP, wF, wO, x, ln1_g, ln1_b, a);

    // 1. qkv = a @ w_attn + b_attn   [2048 x 2304], fp16 out
    gemm_mma<0,1,1><<<dim3(NT_/BM, QKV_/BN), 256, GEMM_SMEM>>>(
        a, wA, b_attn, nullptr, nullptr, nullptr, qkvh, D_, QKV_);

    // 2. FAVOR+ features (fp16 in/out)
    phi_kernel<<<dim3(S_/32, H_*2, B_), 256>>>(qkvh, w_feat, phiq, phik);

    // 3. chunked causal scan
    scan_tot_kernel<<<B_*H_*NCH, 256>>>(qkvh, phik, kvt, kst);
    scan_pfx_kernel<<<B_*H_, 256>>>(kvt, kst);
    scan_kernel<<<B_*H_*NCH, 256>>>(qkvh, phiq, phik, kvt, kst, at);

    // 4. attn @ w_proj  (split-K3, reduce fused with LN2)
    gemm_mma<0,0,3><<<dim3(NT_/BM, D_/BN, 3), 256, GEMM_SMEM>>>(
        at, wP, b_proj, sp0, sp1, sp2, nullptr, D_, D_);

    // 5. fused: x1 = p0+p1+p2+bias+x ; h = LN2(x1) (fp16)
    addln_kernel<<<NT_, 256>>>(sp0, sp1, sp2, b_proj, x, ln2_g, ln2_b, x1, hh);

    // 6. ff = gelu(h @ w_fc + b_fc)   [2048 x 3072], fp16 out
    gemm_mma<1,1,1><<<dim3(NT_/BM, DFF_/BN), 256, GEMM_SMEM>>>(
        hh, wF, b_fc, nullptr, nullptr, nullptr, ff, D_, DFF_);

    // 7. out = x1 + ff @ w_out + b_out  (split-K3 + reduce)
    gemm_mma<0,0,3><<<dim3(NT_/BM, D_/BN, 3), 256, GEMM_SMEM>>>(
        ff, wO, b_out, sp0, sp1, sp2, nullptr, DFF_, D_);
    addred3_kernel<<<(NT_*D_/4)/256, 256>>>(sp0, sp1, sp2, b_out, x1, out);
}

// round 14
// speedup vs baseline: 2.4189x; 1.0327x over previous
#include <cuda_runtime.h>
#include <cuda_fp16.h>
#include <cstdint>

// ---------------------------------------------------------------------------
// Problem constants
// ---------------------------------------------------------------------------
#define B_  2
#define S_  1024
#define D_  768
#define H_  12
#define DH_ 64
#define M_  64
#define DFF_ 3072
#define NT_ (B_ * S_)          // 2048 tokens
#define QKV_ (3 * D_)          // 2304
#define NCH 32                 // scan chunks (== S/32, matches phi block rows)
#define CHL (S_ / NCH)         // 32 steps per chunk

typedef __half fp16;

// ---------------------------------------------------------------------------
// Scratch (__device__ globals; no allocation allowed)
// ---------------------------------------------------------------------------
__device__ fp16  g_a   [NT_ * D_];        // LN1 out (fp16)
__device__ fp16  g_qkv [NT_ * QKV_];      // qkv (fp16)
__device__ fp16  g_phiq[B_ * H_ * S_ * M_];
__device__ fp16  g_phik[B_ * H_ * S_ * M_];
__device__ fp16  g_at  [NT_ * D_];        // attention out (fp16)
__device__ float g_x1  [NT_ * D_];
__device__ fp16  g_h   [NT_ * D_];        // LN2 out (fp16)
__device__ fp16  g_ff  [NT_ * DFF_];      // gelu out (fp16)
// split-K partial buffers
__device__ float g_sp0 [NT_ * D_];
__device__ float g_sp1 [NT_ * D_];
__device__ float g_sp2 [NT_ * D_];
// scan chunk totals -> exclusive prefixes (fp32)
__device__ float g_kvt [B_ * H_ * NCH * M_ * DH_];
__device__ float g_kst [B_ * H_ * NCH * M_];
// transposed fp16 weights: Wt[n][k] = W[k][n]
__device__ fp16  g_wA [QKV_ * D_];
__device__ fp16  g_wP [D_ * D_];
__device__ fp16  g_wF [DFF_ * D_];
__device__ fp16  g_wO [D_ * DFF_];

// ---------------------------------------------------------------------------
// Small helpers
// ---------------------------------------------------------------------------
__device__ __forceinline__ uint32_t smem_to_u32(const void* p) {
    uint32_t a;
    asm("{ .reg .u64 t; cvta.to.shared.u64 t, %1; cvt.u32.u64 %0, t; }"
        : "=r"(a) : "l"(p));
    return a;
}

__device__ __forceinline__ float gelu_tanh(float x)
{
    float x3 = x * x * x;
    float u  = 0.7978845608028654f * (x + 0.044715f * x3);
    return 0.5f * x * (1.0f + tanhf(u));
}

__device__ __forceinline__ void cp_async16(uint32_t saddr, const void* gaddr) {
    asm volatile("cp.async.cg.shared.global [%0], [%1], 16;"
                 :: "r"(saddr), "l"(gaddr));
}
__device__ __forceinline__ void cp_commit() {
    asm volatile("cp.async.commit_group;");
}
template<int N>
__device__ __forceinline__ void cp_wait() {
    asm volatile("cp.async.wait_group %0;" :: "n"(N));
}

__device__ __forceinline__ void ldmx4(uint32_t* r, uint32_t addr) {
    asm volatile("ldmatrix.sync.aligned.m8n8.x4.shared.b16 {%0,%1,%2,%3}, [%4];"
                 : "=r"(r[0]), "=r"(r[1]), "=r"(r[2]), "=r"(r[3]) : "r"(addr));
}

// mma.sync m16n8k16 row.col f32 += f16*f16
__device__ __forceinline__ void mma16816(float* c, const uint32_t* a,
                                         uint32_t b0, uint32_t b1) {
    asm volatile(
        "mma.sync.aligned.m16n8k16.row.col.f32.f16.f16.f32 "
        "{%0,%1,%2,%3}, {%4,%5,%6,%7}, {%8,%9}, {%0,%1,%2,%3};"
        : "+f"(c[0]), "+f"(c[1]), "+f"(c[2]), "+f"(c[3])
        : "r"(a[0]), "r"(a[1]), "r"(a[2]), "r"(a[3]), "r"(b0), "r"(b1));
}

// load 16 consecutive fp16 -> 16 floats (32B, two uint4)
__device__ __forceinline__ void ld16h(float* o, const fp16* p) {
    uint4 u0 = ((const uint4*)p)[0];
    uint4 u1 = ((const uint4*)p)[1];
    const __half2* h0 = (const __half2*)&u0;
    const __half2* h1 = (const __half2*)&u1;
    #pragma unroll
    for (int i = 0; i < 4; i++) {
        float2 f = __half22float2(h0[i]); o[2*i]     = f.x; o[2*i + 1]     = f.y;
        float2 g = __half22float2(h1[i]); o[8 + 2*i] = g.x; o[8 + 2*i + 1] = g.y;
    }
}

// ---------------------------------------------------------------------------
// Fused prep: weight transpose+fp16 (blocks 0..6911) + LN1 (blocks 6912..8959)
// ---------------------------------------------------------------------------
__global__ void prep_kernel(const float* __restrict__ wA, const float* __restrict__ wP,
                            const float* __restrict__ wF, const float* __restrict__ wO,
                            fp16* __restrict__ TA, fp16* __restrict__ TP,
                            fp16* __restrict__ TF, fp16* __restrict__ TO,
                            const float* __restrict__ x,
                            const float* __restrict__ g1, const float* __restrict__ b1,
                            fp16* __restrict__ aout)
{
    int blk = blockIdx.x;
    int t = threadIdx.x;

    if (blk < 6912) {
        const float* W; fp16 *T; int K, N, nx;
        int tt = blk;
        if (tt < 1728)      { W = wA; T = TA; K = D_;  N = QKV_; nx = 72; }
        else if (tt < 2304) { tt -= 1728; W = wP; T = TP; K = D_;  N = D_;   nx = 24; }
        else if (tt < 4608) { tt -= 2304; W = wF; T = TF; K = D_;  N = DFF_; nx = 96; }
        else                { tt -= 4608; W = wO; T = TO; K = DFF_; N = D_;  nx = 24; }
        int n0 = (tt % nx) * 32, k0 = (tt / nx) * 32;

        __shared__ float tile[32][33];
        int tx = t & 31, ty = t >> 5;
        #pragma unroll
        for (int i = 0; i < 4; i++)
            tile[ty + i * 8][tx] = W[(size_t)(k0 + ty + i * 8) * N + n0 + tx];
        __syncthreads();
        #pragma unroll
        for (int i = 0; i < 4; i++) {
            float v = tile[tx][ty + i * 8];
            T[(size_t)(n0 + ty + i * 8) * K + k0 + tx] = __float2half_rn(v);
        }
        return;
    }

    int row = blk - 6912;
    const float* xr = x + (size_t)row * D_;
    float v0 = xr[t], v1 = xr[t + 256], v2 = xr[t + 512];
    float s  = v0 + v1 + v2;
    float sq = v0 * v0 + v1 * v1 + v2 * v2;

    #pragma unroll
    for (int off = 16; off; off >>= 1) {
        s  += __shfl_xor_sync(0xffffffffu, s,  off);
        sq += __shfl_xor_sync(0xffffffffu, sq, off);
    }
    __shared__ float red[16];
    int w = t >> 5, l = t & 31;
    if (l == 0) { red[w] = s; red[w + 8] = sq; }
    __syncthreads();
    s = 0.f; sq = 0.f;
    #pragma unroll
    for (int i = 0; i < 8; i++) { s += red[i]; sq += red[8 + i]; }

    const float inv = 1.0f / (float)D_;
    float mean = s * inv;
    float var  = sq * inv - mean * mean;
    float rs   = rsqrtf(var + 1e-5f);

    size_t base = (size_t)row * D_;
    float vv[3] = {v0, v1, v2};
    #pragma unroll
    for (int i = 0; i < 3; i++) {
        int c = t + i * 256;
        aout[base + c] = __float2half_rn((vv[i] - mean) * rs * g1[c] + b1[c]);
    }
}

// ---------------------------------------------------------------------------
// Fused split-K3 reduce + residual + bias + LayerNorm -> x1 (f32) + h (fp16)
// ---------------------------------------------------------------------------
__global__ void addln_kernel(const float* __restrict__ p0,
                             const float* __restrict__ p1,
                             const float* __restrict__ p2,
                             const float* __restrict__ bias,
                             const float* __restrict__ res,
                             const float* __restrict__ g,
                             const float* __restrict__ b,
                             float* __restrict__ x1,
                             fp16* __restrict__ o)
{
    int row = blockIdx.x;
    int t   = threadIdx.x;
    size_t base = (size_t)row * D_;

    float vv[3];
    #pragma unroll
    for (int i = 0; i < 3; i++) {
        int c = t + i * 256;
        size_t idx = base + c;
        vv[i] = p0[idx] + p1[idx] + p2[idx] + bias[c] + res[idx];
        x1[idx] = vv[i];
    }

    float s  = vv[0] + vv[1] + vv[2];
    float sq = vv[0]*vv[0] + vv[1]*vv[1] + vv[2]*vv[2];
    #pragma unroll
    for (int off = 16; off; off >>= 1) {
        s  += __shfl_xor_sync(0xffffffffu, s,  off);
        sq += __shfl_xor_sync(0xffffffffu, sq, off);
    }
    __shared__ float red[16];
    int w = t >> 5, l = t & 31;
    if (l == 0) { red[w] = s; red[w + 8] = sq; }
    __syncthreads();
    s = 0.f; sq = 0.f;
    #pragma unroll
    for (int i = 0; i < 8; i++) { s += red[i]; sq += red[8 + i]; }

    const float inv = 1.0f / (float)D_;
    float mean = s * inv;
    float var  = sq * inv - mean * mean;
    float rs   = rsqrtf(var + 1e-5f);

    #pragma unroll
    for (int i = 0; i < 3; i++) {
        int c = t + i * 256;
        o[base + c] = __float2half_rn((vv[i] - mean) * rs * g[c] + b[c]);
    }
}

// ---------------------------------------------------------------------------
// HMMA fp16 GEMM: C = A @ W^T, fp32 accum.
// CTA 128x128, BKC=32, 2 tiles/stage, 3-stage cp.async pipeline (60KB).
// ---------------------------------------------------------------------------
#define BM 128
#define BN 128
#define BKC 32
#define LDT 40                         // padded row (fp16) = 80B
#define TILE_BYTES (BM * LDT * 2)      // 10240
#define STAGE_BYTES (2 * TILE_BYTES)   // 20480
#define NSTAGE 3
#define GEMM_SMEM (NSTAGE * STAGE_BYTES)   // 61440

template<int GELU, int OUTH, int SPLITK>
__global__ void __launch_bounds__(256)
gemm_mma(const fp16* __restrict__ A,
         const fp16* __restrict__ Bw,
         const float* __restrict__ bias,
         float* __restrict__ Cf, float* __restrict__ Cp1, float* __restrict__ Cp2,
         fp16* __restrict__ Ch,
         int K, int N)
{
    extern __shared__ char smem[];
    const uint32_t sbase = smem_to_u32(smem);

    const int tid  = threadIdx.x;
    const int lane = tid & 31;
    const int w    = tid >> 5;
    const int wr   = w & 3;
    const int wc   = w >> 2;
    const int bm   = blockIdx.x * BM;
    const int bn   = blockIdx.y * BN;
    const int Keff = K / SPLITK;
    const int kbase = (SPLITK > 1) ? (int)blockIdx.z * Keff : 0;

    float acc[2][8][4];
    #pragma unroll
    for (int i = 0; i < 2; i++)
        #pragma unroll
        for (int j = 0; j < 8; j++)
            #pragma unroll
            for (int q = 0; q < 4; q++) acc[i][j][q] = 0.f;

    const int NC = Keff / BKC;

    const int lrow = tid >> 1;
    const int lseg = (tid & 1) * 2;
    const uint32_t lsm = (uint32_t)(lrow * LDT + lseg * 8) * 2u;

    auto issue = [&](int c, int st) {
        int k0 = kbase + c * BKC;
        const fp16* sa = A  + (size_t)(bm + lrow) * K + k0 + lseg * 8;
        const fp16* sb = Bw + (size_t)(bn + lrow) * K + k0 + lseg * 8;
        uint32_t sbm = sbase + (uint32_t)st * STAGE_BYTES + lsm;
        cp_async16(sbm,                     sa);
        cp_async16(sbm + 16u,               sa + 8);
        cp_async16(sbm + TILE_BYTES,        sb);
        cp_async16(sbm + TILE_BYTES + 16u,  sb + 8);
    };

    issue(0, 0); cp_commit();
    if (NC > 1) { issue(1, 1); cp_commit(); }

    const uint32_t aoff = (uint32_t)((wr * 32 + (lane & 15)) * LDT + (lane >> 4) * 8) * 2u;
    const uint32_t boff = (uint32_t)((wc * 64 + (lane & 7) + ((lane >> 4) & 1) * 8) * LDT
                                     + ((lane >> 3) & 1) * 8) * 2u;

    int st = 0;
    for (int c = 0; c < NC; c++) {
        if (c == NC - 1) cp_wait<0>(); else cp_wait<1>();
        __syncthreads();
        if (c + 2 < NC) {
            int nst = st + 2; if (nst >= NSTAGE) nst -= NSTAGE;
            issue(c + 2, nst);
            cp_commit();
        }

        const uint32_t sst = sbase + (uint32_t)st * STAGE_BYTES;
        #pragma unroll
        for (int ks = 0; ks < 2; ks++) {
            const uint32_t ko = (uint32_t)(ks * 16) * 2u;
            uint32_t av[2][4], bv[4][4];
            #pragma unroll
            for (int mt = 0; mt < 2; mt++) {
                uint32_t ro = aoff + (uint32_t)(mt * 16 * LDT) * 2u + ko;
                ldmx4(av[mt], sst + ro);
            }
            #pragma unroll
            for (int np = 0; np < 4; np++) {
                uint32_t ro = boff + (uint32_t)(np * 16 * LDT) * 2u + ko;
                ldmx4(bv[np], sst + TILE_BYTES + ro);
            }
            #pragma unroll
            for (int mt = 0; mt < 2; mt++)
                #pragma unroll
                for (int nt = 0; nt < 8; nt++) {
                    const int np = nt >> 1, half = (nt & 1) * 2;
                    mma16816(acc[mt][nt], av[mt], bv[np][half], bv[np][half + 1]);
                }
        }
        if (++st == NSTAGE) st = 0;
    }

    // epilogue
    const int g  = lane >> 2;
    const int tg = lane & 3;
    float* Cpart = Cf;
    if (SPLITK > 1) Cpart = (blockIdx.z == 0) ? Cf : (blockIdx.z == 1 ? Cp1 : Cp2);
    #pragma unroll
    for (int mt = 0; mt < 2; mt++) {
        #pragma unroll
        for (int nt = 0; nt < 8; nt++) {
            int col = bn + wc * 64 + nt * 8 + tg * 2;
            float2 bvv = (SPLITK > 1) ? make_float2(0.f, 0.f)
                                      : *(const float2*)(bias + col);
            #pragma unroll
            for (int half = 0; half < 2; half++) {
                int row = bm + wr * 32 + mt * 16 + g + half * 8;
                float v0 = acc[mt][nt][half * 2 + 0] + bvv.x;
                float v1 = acc[mt][nt][half * 2 + 1] + bvv.y;
                size_t idx = (size_t)row * N + col;
                if (GELU) { v0 = gelu_tanh(v0); v1 = gelu_tanh(v1); }
                if (OUTH) {
                    *(__half2*)(Ch + idx) = __floats2half2_rn(v0, v1);
                } else {
                    *(float2*)(Cpart + idx) = make_float2(v0, v1);
                }
            }
        }
    }
}

// ---------------------------------------------------------------------------
// Split-K3 reduction: o = p0 + p1 + p2 + bias + res   (f32, 768 cols)
// ---------------------------------------------------------------------------
__global__ void addred3_kernel(const float* __restrict__ p0,
                               const float* __restrict__ p1,
                               const float* __restrict__ p2,
                               const float* __restrict__ bias,
                               const float* __restrict__ res,
                               float* __restrict__ o)
{
    int i = (blockIdx.x * 256 + threadIdx.x);
    int col4 = i % (D_ / 4);
    float4 a = ((const float4*)p0)[i];
    float4 b = ((const float4*)p1)[i];
    float4 c = ((const float4*)p2)[i];
    float4 d = ((const float4*)bias)[col4];
    float4 r = ((const float4*)res)[i];
    float4 v;
    v.x = a.x + b.x + c.x + d.x + r.x;
    v.y = a.y + b.y + c.y + d.y + r.y;
    v.z = a.z + b.z + c.z + d.z + r.z;
    v.w = a.w + b.w + c.w + d.w + r.w;
    ((float4*)o)[i] = v;
}

// ---------------------------------------------------------------------------
// FAVOR+ features + fused chunk totals (k side).
// Block covers 32 rows = one scan chunk. qk=1 blocks additionally compute
// kvt[m][d] = sum_s phik[s][m]*v[s][d] and kst[m] = sum_s phik[s][m]
// from smem-resident data (replaces scan_tot_kernel).
// ---------------------------------------------------------------------------
__global__ void phi_kernel(const fp16* __restrict__ qkv,
                           const float* __restrict__ wfeat,
                           fp16* __restrict__ phiq,
                           fp16* __restrict__ phik,
                           float* __restrict__ kvt,
                           float* __restrict__ kst)
{
    const int sc = blockIdx.x;            // chunk index (32 rows)
    const int hy = blockIdx.y;
    const int b  = blockIdx.z;
    const int h  = hy % H_;
    const int qk = hy / H_;

    __shared__ float wfT[64][65];         // [d][m]
    __shared__ float xs[32][64];
    __shared__ float sqs[32];
    __shared__ float phs[32][64];         // phik values (k blocks only)
    __shared__ __half2 vs[32][32];        // v rows (k blocks only)

    const int t = threadIdx.x;

    #pragma unroll
    for (int i = 0; i < 16; i++) {
        int idx = t + i * 256;            // idx = m*64 + d
        wfT[idx & 63][idx >> 6] = wfeat[idx];
    }

    const float scale = 0.3535533905932738f;
    const int s0   = sc * 32;
    const int col0 = qk * D_ + h * DH_;

    #pragma unroll
    for (int i = 0; i < 4; i++) {
        int idx = t + i * 256;
        int sl = idx >> 5, d2 = idx & 31;
        __half2 hv = ((const __half2*)(qkv + (size_t)(b * S_ + s0 + sl) * QKV_ + col0))[d2];
        float2 f = __half22float2(hv);
        xs[sl][2 * d2]     = f.x * scale;
        xs[sl][2 * d2 + 1] = f.y * scale;
    }
    if (qk) {
        const int colv = 2 * D_ + h * DH_;
        #pragma unroll
        for (int i = 0; i < 4; i++) {
            int idx = t + i * 256;
            int sl = idx >> 5, d2 = idx & 31;
            vs[sl][d2] = ((const __half2*)(qkv + (size_t)(b * S_ + s0 + sl) * QKV_ + colv))[d2];
        }
    }
    __syncthreads();

    {
        int sl = t >> 3, p = t & 7;
        float acc = 0.f;
        #pragma unroll
        for (int dd = 0; dd < 8; dd++) {
            float xv = xs[sl][p * 8 + dd];
            acc = fmaf(xv, xv, acc);
        }
        acc += __shfl_xor_sync(0xffffffffu, acc, 1);
        acc += __shfl_xor_sync(0xffffffffu, acc, 2);
        acc += __shfl_xor_sync(0xffffffffu, acc, 4);
        if (p == 0) sqs[sl] = 0.5f * acc;
    }
    __syncthreads();

    const int m   = t & 63;
    const int sl0 = t >> 6;          // 0..3
    float acc[8];
    #pragma unroll
    for (int j = 0; j < 8; j++) acc[j] = 0.f;

    #pragma unroll 8
    for (int d = 0; d < 64; d += 2) {
        float wf0 = wfT[d][m];
        float wf1 = wfT[d + 1][m];
        #pragma unroll
        for (int j = 0; j < 8; j++) {
            float2 xv = *(const float2*)&xs[sl0 + 4 * j][d];
            acc[j] = fmaf(xv.x, wf0, acc[j]);
            acc[j] = fmaf(xv.y, wf1, acc[j]);
        }
    }

    fp16* dst = qk ? phik : phiq;
    #pragma unroll
    for (int j = 0; j < 8; j++) {
        int sl = sl0 + 4 * j;
        float ph = __expf(acc[j] - sqs[sl]) * 0.125f + 1e-6f;
        dst[(size_t)((b * H_ + h) * S_ + s0 + sl) * M_ + m] = __float2half_rn(ph);
        if (qk) phs[sl][m] = ph;
    }

    if (!qk) return;

    __syncthreads();

    // chunk totals: thread (m = t&63, dg = t>>6) computes kvt[m][dg*16..+16), kst[m]
    const int dg = sl0;
    float kvacc[16];
    #pragma unroll
    for (int i = 0; i < 16; i++) kvacc[i] = 0.f;
    float ksacc = 0.f;

    #pragma unroll 4
    for (int sl = 0; sl < 32; sl++) {
        float p = phs[sl][m];
        ksacc += p;
        #pragma unroll
        for (int dd = 0; dd < 8; dd++) {
            float2 f = __half22float2(vs[sl][dg * 8 + dd]);
            kvacc[2 * dd]     = fmaf(p, f.x, kvacc[2 * dd]);
            kvacc[2 * dd + 1] = fmaf(p, f.y, kvacc[2 * dd + 1]);
        }
    }

    size_t base = ((size_t)((b * H_ + h) * NCH + sc) * M_ + m);
    #pragma unroll
    for (int i = 0; i < 16; i++)
        kvt[base * DH_ + dg * 16 + i] = kvacc[i];
    if (dg == 0) kst[base] = ksacc;
}

// ---------------------------------------------------------------------------
// Scan prefix: exclusive prefix over chunks. grid (B*H, 17):
// by<16 -> kvt element range, by==16 -> kst. One thread per element column.
// ---------------------------------------------------------------------------
__global__ void scan_pfx_kernel(float* __restrict__ kvt, float* __restrict__ kst)
{
    const int bh = blockIdx.x;
    const int by = blockIdx.y;
    const int t  = threadIdx.x;

    if (by < 16) {
        int e = by * 256 + t;             // 0..4095 of M*DH
        float run = 0.f;
        #pragma unroll
        for (int ch = 0; ch < NCH; ch++) {
            size_t idx = ((size_t)(bh * NCH + ch)) * (M_ * DH_) + e;
            float v = kvt[idx];
            kvt[idx] = run;
            run += v;
        }
    } else if (t < M_) {
        float run = 0.f;
        #pragma unroll
        for (int ch = 0; ch < NCH; ch++) {
            size_t idx = ((size_t)(bh * NCH + ch)) * M_ + t;
            float v = kst[idx];
            kst[idx] = run;
            run += v;
        }
    }
}

// ---------------------------------------------------------------------------
// Scan pass 2: local inclusive scan per (bh, chunk), seeded by exclusive
// prefix totals. fp16 in/out.
// ---------------------------------------------------------------------------
__global__ void scan_kernel(const fp16* __restrict__ qkv,
                            const fp16* __restrict__ phiq,
                            const fp16* __restrict__ phik,
                            const float* __restrict__ kvt,
                            const float* __restrict__ kst,
                            fp16* __restrict__ ao)
{
    const int bc = blockIdx.x;
    const int bh = bc / NCH;
    const int ch = bc % NCH;
    const int b  = bh / H_;
    const int h  = bh % H_;
    const int t  = threadIdx.x;
    const int d  = t >> 2;
    const int mg = t & 3;

    float kv[16], ks[16];
    size_t sbase = (size_t)bc * M_ + mg * 16;
    #pragma unroll
    for (int i = 0; i < 16; i++) {
        kv[i] = kvt[(sbase + i) * DH_ + d];
        ks[i] = kst[sbase + i];
    }

    const int s0 = ch * CHL;
    const fp16* pq = phiq + (size_t)bh * S_ * M_ + (size_t)s0 * M_ + mg * 16;
    const fp16* pk = phik + (size_t)bh * S_ * M_ + (size_t)s0 * M_ + mg * 16;
    const fp16* pv = qkv  + (size_t)(b * S_ + s0) * QKV_ + 2 * D_ + h * DH_ + d;
    size_t obase = (size_t)(b * S_ + s0) * D_ + h * DH_ + d;

    for (int s = 0; s < CHL; s++) {
        float kr[16], qr[16];
        ld16h(kr, pk);
        ld16h(qr, pq);
        float vv = __half2float(*pv);

        float num = 0.f, den = 0.f;
        #pragma unroll
        for (int i = 0; i < 16; i++) {
            kv[i] = fmaf(kr[i], vv, kv[i]);
            ks[i] += kr[i];
            num = fmaf(qr[i], kv[i], num);
            den = fmaf(qr[i], ks[i], den);
        }
        num += __shfl_xor_sync(0xffffffffu, num, 1);
        den += __shfl_xor_sync(0xffffffffu, den, 1);
        num += __shfl_xor_sync(0xffffffffu, num, 2);
        den += __shfl_xor_sync(0xffffffffu, den, 2);

        if (mg == 0) ao[obase] = __float2half_rn(num / den);

        pq += M_; pk += M_; pv += QKV_; obase += D_;
    }
}

// ---------------------------------------------------------------------------
// Launch
// ---------------------------------------------------------------------------
extern "C" void kernel_launch(void* const* d_in, const int* in_sizes, int n_in,
                              void* d_out, int out_size)
{
    const float* x      = (const float*)d_in[0];
    const float* ln1_g  = (const float*)d_in[1];
    const float* ln1_b  = (const float*)d_in[2];
    const float* w_attn = (const float*)d_in[3];
    const float* b_attn = (const float*)d_in[4];
    const float* w_feat = (const float*)d_in[5];
    const float* w_proj = (const float*)d_in[6];
    const float* b_proj = (const float*)d_in[7];
    const float* ln2_g  = (const float*)d_in[8];
    const float* ln2_b  = (const float*)d_in[9];
    const float* w_fc   = (const float*)d_in[10];
    const float* b_fc   = (const float*)d_in[11];
    const float* w_out  = (const float*)d_in[12];
    const float* b_out  = (const float*)d_in[13];
    float* out = (float*)d_out;

    fp16 *a, *at, *hh, *ff, *wA, *wP, *wF, *wO, *qkvh, *phiq, *phik;
    float *x1, *kvt, *kst, *sp0, *sp1, *sp2;
    cudaGetSymbolAddress((void**)&a,    g_a);
    cudaGetSymbolAddress((void**)&qkvh, g_qkv);
    cudaGetSymbolAddress((void**)&phiq, g_phiq);
    cudaGetSymbolAddress((void**)&phik, g_phik);
    cudaGetSymbolAddress((void**)&at,   g_at);
    cudaGetSymbolAddress((void**)&x1,   g_x1);
    cudaGetSymbolAddress((void**)&hh,   g_h);
    cudaGetSymbolAddress((void**)&ff,   g_ff);
    cudaGetSymbolAddress((void**)&sp0,  g_sp0);
    cudaGetSymbolAddress((void**)&sp1,  g_sp1);
    cudaGetSymbolAddress((void**)&sp2,  g_sp2);
    cudaGetSymbolAddress((void**)&kvt,  g_kvt);
    cudaGetSymbolAddress((void**)&kst,  g_kst);
    cudaGetSymbolAddress((void**)&wA,   g_wA);
    cudaGetSymbolAddress((void**)&wP,   g_wP);
    cudaGetSymbolAddress((void**)&wF,   g_wF);
    cudaGetSymbolAddress((void**)&wO,   g_wO);

    cudaFuncSetAttribute(gemm_mma<0,1,1>, cudaFuncAttributeMaxDynamicSharedMemorySize, GEMM_SMEM);
    cudaFuncSetAttribute(gemm_mma<0,0,3>, cudaFuncAttributeMaxDynamicSharedMemorySize, GEMM_SMEM);
    cudaFuncSetAttribute(gemm_mma<1,1,1>, cudaFuncAttributeMaxDynamicSharedMemorySize, GEMM_SMEM);

    // 0. fused weight transpose+convert + LN1
    prep_kernel<<<6912 + NT_, 256>>>(w_attn, w_proj, w_fc, w_out,
                                     wA, wP, wF, wO, x, ln1_g, ln1_b, a);

    // 1. qkv = a @ w_attn + b_attn   [2048 x 2304], fp16 out
    gemm_mma<0,1,1><<<dim3(NT_/BM, QKV_/BN), 256, GEMM_SMEM>>>(
        a, wA, b_attn, nullptr, nullptr, nullptr, qkvh, D_, QKV_);

    // 2. FAVOR+ features + fused chunk totals (k blocks)
    phi_kernel<<<dim3(S_/32, H_*2, B_), 256>>>(qkvh, w_feat, phiq, phik, kvt, kst);

    // 3. chunked causal scan (parallel prefix -> seeded local scan)
    scan_pfx_kernel<<<dim3(B_*H_, 17), 256>>>(kvt, kst);
    scan_kernel<<<B_*H_*NCH, 256>>>(qkvh, phiq, phik, kvt, kst, at);

    // 4. attn @ w_proj  (split-K3, reduce fused with LN2)
    gemm_mma<0,0,3><<<dim3(NT_/BM, D_/BN, 3), 256, GEMM_SMEM>>>(
        at, wP, b_proj, sp0, sp1, sp2, nullptr, D_, D_);

    // 5. fused: x1 = p0+p1+p2+bias+x ; h = LN2(x1) (fp16)
    addln_kernel<<<NT_, 256>>>(sp0, sp1, sp2, b_proj, x, ln2_g, ln2_b, x1, hh);

    // 6. ff = gelu(h @ w_fc + b_fc)   [2048 x 3072], fp16 out
    gemm_mma<1,1,1><<<dim3(NT_/BM, DFF_/BN), 256, GEMM_SMEM>>>(
        hh, wF, b_fc, nullptr, nullptr, nullptr, ff, D_, DFF_);

    // 7. out = x1 + ff @ w_out + b_out  (split-K3 + reduce)
    gemm_mma<0,0,3><<<dim3(NT_/BM, D_/BN, 3), 256, GEMM_SMEM>>>(
        ff, wO, b_out, sp0, sp1, sp2, nullptr, DFF_, D_);
    addred3_kernel<<<(NT_*D_/4)/256, 256>>>(sp0, sp1, sp2, b_out, x1, out);
}

// round 16
// speedup vs baseline: 2.4536x; 1.0143x over previous
#include <cuda_runtime.h>
#include <cuda_fp16.h>
#include <cstdint>

// ---------------------------------------------------------------------------
// Problem constants
// ---------------------------------------------------------------------------
#define B_  2
#define S_  1024
#define D_  768
#define H_  12
#define DH_ 64
#define M_  64
#define DFF_ 3072
#define NT_ (B_ * S_)          // 2048 tokens
#define QKV_ (3 * D_)          // 2304
#define NCH 32                 // scan chunks (== S/32, matches phi block rows)
#define CHL (S_ / NCH)         // 32 steps per chunk

typedef __half fp16;

// ---------------------------------------------------------------------------
// Scratch (__device__ globals; no allocation allowed)
// ---------------------------------------------------------------------------
__device__ fp16  g_a   [NT_ * D_];        // LN1 out (fp16)
__device__ fp16  g_qkv [NT_ * QKV_];      // qkv (fp16)
__device__ fp16  g_phiq[B_ * H_ * S_ * M_];
__device__ fp16  g_phik[B_ * H_ * S_ * M_];
__device__ fp16  g_at  [NT_ * D_];        // attention out (fp16)
__device__ float g_x1  [NT_ * D_];
__device__ fp16  g_h   [NT_ * D_];        // LN2 out (fp16)
__device__ fp16  g_ff  [NT_ * DFF_];      // gelu out (fp16)
// split-K partial buffers
__device__ float g_sp0 [NT_ * D_];
__device__ float g_sp1 [NT_ * D_];
__device__ float g_sp2 [NT_ * D_];
// scan chunk totals -> exclusive prefixes (fp32)
__device__ float g_kvt [B_ * H_ * NCH * M_ * DH_];
__device__ float g_kst [B_ * H_ * NCH * M_];
// transposed fp16 weights: Wt[n][k] = W[k][n]
__device__ fp16  g_wA [QKV_ * D_];
__device__ fp16  g_wP [D_ * D_];
__device__ fp16  g_wF [DFF_ * D_];
__device__ fp16  g_wO [D_ * DFF_];

// ---------------------------------------------------------------------------
// Small helpers
// ---------------------------------------------------------------------------
__device__ __forceinline__ uint32_t smem_to_u32(const void* p) {
    uint32_t a;
    asm("{ .reg .u64 t; cvta.to.shared.u64 t, %1; cvt.u32.u64 %0, t; }"
        : "=r"(a) : "l"(p));
    return a;
}

__device__ __forceinline__ float gelu_tanh(float x)
{
    float x3 = x * x * x;
    float u  = 0.7978845608028654f * (x + 0.044715f * x3);
    return 0.5f * x * (1.0f + tanhf(u));
}

__device__ __forceinline__ void cp_async16(uint32_t saddr, const void* gaddr) {
    asm volatile("cp.async.cg.shared.global [%0], [%1], 16;"
                 :: "r"(saddr), "l"(gaddr));
}
__device__ __forceinline__ void cp_commit() {
    asm volatile("cp.async.commit_group;");
}
template<int N>
__device__ __forceinline__ void cp_wait() {
    asm volatile("cp.async.wait_group %0;" :: "n"(N));
}

__device__ __forceinline__ void ldmx4(uint32_t* r, uint32_t addr) {
    asm volatile("ldmatrix.sync.aligned.m8n8.x4.shared.b16 {%0,%1,%2,%3}, [%4];"
                 : "=r"(r[0]), "=r"(r[1]), "=r"(r[2]), "=r"(r[3]) : "r"(addr));
}

// mma.sync m16n8k16 row.col f32 += f16*f16
__device__ __forceinline__ void mma16816(float* c, const uint32_t* a,
                                         uint32_t b0, uint32_t b1) {
    asm volatile(
        "mma.sync.aligned.m16n8k16.row.col.f32.f16.f16.f32 "
        "{%0,%1,%2,%3}, {%4,%5,%6,%7}, {%8,%9}, {%0,%1,%2,%3};"
        : "+f"(c[0]), "+f"(c[1]), "+f"(c[2]), "+f"(c[3])
        : "r"(a[0]), "r"(a[1]), "r"(a[2]), "r"(a[3]), "r"(b0), "r"(b1));
}

// load 16 consecutive fp16 -> 16 floats (32B, two uint4)
__device__ __forceinline__ void ld16h(float* o, const fp16* p) {
    uint4 u0 = ((const uint4*)p)[0];
    uint4 u1 = ((const uint4*)p)[1];
    const __half2* h0 = (const __half2*)&u0;
    const __half2* h1 = (const __half2*)&u1;
    #pragma unroll
    for (int i = 0; i < 4; i++) {
        float2 f = __half22float2(h0[i]); o[2*i]     = f.x; o[2*i + 1]     = f.y;
        float2 g = __half22float2(h1[i]); o[8 + 2*i] = g.x; o[8 + 2*i + 1] = g.y;
    }
}

// ---------------------------------------------------------------------------
// Fused prep: weight transpose+fp16 (blocks 0..6911) + LN1 (blocks 6912..8959)
// ---------------------------------------------------------------------------
__global__ void prep_kernel(const float* __restrict__ wA, const float* __restrict__ wP,
                            const float* __restrict__ wF, const float* __restrict__ wO,
                            fp16* __restrict__ TA, fp16* __restrict__ TP,
                            fp16* __restrict__ TF, fp16* __restrict__ TO,
                            const float* __restrict__ x,
                            const float* __restrict__ g1, const float* __restrict__ b1,
                            fp16* __restrict__ aout)
{
    int blk = blockIdx.x;
    int t = threadIdx.x;

    if (blk < 6912) {
        const float* W; fp16 *T; int K, N, nx;
        int tt = blk;
        if (tt < 1728)      { W = wA; T = TA; K = D_;  N = QKV_; nx = 72; }
        else if (tt < 2304) { tt -= 1728; W = wP; T = TP; K = D_;  N = D_;   nx = 24; }
        else if (tt < 4608) { tt -= 2304; W = wF; T = TF; K = D_;  N = DFF_; nx = 96; }
        else                { tt -= 4608; W = wO; T = TO; K = DFF_; N = D_;  nx = 24; }
        int n0 = (tt % nx) * 32, k0 = (tt / nx) * 32;

        __shared__ float tile[32][33];
        int tx = t & 31, ty = t >> 5;
        #pragma unroll
        for (int i = 0; i < 4; i++)
            tile[ty + i * 8][tx] = W[(size_t)(k0 + ty + i * 8) * N + n0 + tx];
        __syncthreads();
        #pragma unroll
        for (int i = 0; i < 4; i++) {
            float v = tile[tx][ty + i * 8];
            T[(size_t)(n0 + ty + i * 8) * K + k0 + tx] = __float2half_rn(v);
        }
        return;
    }

    int row = blk - 6912;
    const float* xr = x + (size_t)row * D_;
    float v0 = xr[t], v1 = xr[t + 256], v2 = xr[t + 512];
    float s  = v0 + v1 + v2;
    float sq = v0 * v0 + v1 * v1 + v2 * v2;

    #pragma unroll
    for (int off = 16; off; off >>= 1) {
        s  += __shfl_xor_sync(0xffffffffu, s,  off);
        sq += __shfl_xor_sync(0xffffffffu, sq, off);
    }
    __shared__ float red[16];
    int w = t >> 5, l = t & 31;
    if (l == 0) { red[w] = s; red[w + 8] = sq; }
    __syncthreads();
    s = 0.f; sq = 0.f;
    #pragma unroll
    for (int i = 0; i < 8; i++) { s += red[i]; sq += red[8 + i]; }

    const float inv = 1.0f / (float)D_;
    float mean = s * inv;
    float var  = sq * inv - mean * mean;
    float rs   = rsqrtf(var + 1e-5f);

    size_t base = (size_t)row * D_;
    float vv[3] = {v0, v1, v2};
    #pragma unroll
    for (int i = 0; i < 3; i++) {
        int c = t + i * 256;
        aout[base + c] = __float2half_rn((vv[i] - mean) * rs * g1[c] + b1[c]);
    }
}

// ---------------------------------------------------------------------------
// Fused split-K3 reduce + residual + bias + LayerNorm -> x1 (f32) + h (fp16)
// ---------------------------------------------------------------------------
__global__ void addln_kernel(const float* __restrict__ p0,
                             const float* __restrict__ p1,
                             const float* __restrict__ p2,
                             const float* __restrict__ bias,
                             const float* __restrict__ res,
                             const float* __restrict__ g,
                             const float* __restrict__ b,
                             float* __restrict__ x1,
                             fp16* __restrict__ o)
{
    int row = blockIdx.x;
    int t   = threadIdx.x;
    size_t base = (size_t)row * D_;

    float vv[3];
    #pragma unroll
    for (int i = 0; i < 3; i++) {
        int c = t + i * 256;
        size_t idx = base + c;
        vv[i] = p0[idx] + p1[idx] + p2[idx] + bias[c] + res[idx];
        x1[idx] = vv[i];
    }

    float s  = vv[0] + vv[1] + vv[2];
    float sq = vv[0]*vv[0] + vv[1]*vv[1] + vv[2]*vv[2];
    #pragma unroll
    for (int off = 16; off; off >>= 1) {
        s  += __shfl_xor_sync(0xffffffffu, s,  off);
        sq += __shfl_xor_sync(0xffffffffu, sq, off);
    }
    __shared__ float red[16];
    int w = t >> 5, l = t & 31;
    if (l == 0) { red[w] = s; red[w + 8] = sq; }
    __syncthreads();
    s = 0.f; sq = 0.f;
    #pragma unroll
    for (int i = 0; i < 8; i++) { s += red[i]; sq += red[8 + i]; }

    const float inv = 1.0f / (float)D_;
    float mean = s * inv;
    float var  = sq * inv - mean * mean;
    float rs   = rsqrtf(var + 1e-5f);

    #pragma unroll
    for (int i = 0; i < 3; i++) {
        int c = t + i * 256;
        o[base + c] = __float2half_rn((vv[i] - mean) * rs * g[c] + b[c]);
    }
}

// ---------------------------------------------------------------------------
// HMMA fp16 GEMM: C = A @ W^T, fp32 accum.
// CTA 128x128, BKC=32, 2 tiles/stage, 4-stage cp.async pipeline (80KB).
// ---------------------------------------------------------------------------
#define BM 128
#define BN 128
#define BKC 32
#define LDT 40                         // padded row (fp16) = 80B
#define TILE_BYTES (BM * LDT * 2)      // 10240
#define STAGE_BYTES (2 * TILE_BYTES)   // 20480
#define NSTAGE 4
#define GEMM_SMEM (NSTAGE * STAGE_BYTES)   // 81920

template<int GELU, int OUTH, int SPLITK>
__global__ void __launch_bounds__(256)
gemm_mma(const fp16* __restrict__ A,
         const fp16* __restrict__ Bw,
         const float* __restrict__ bias,
         float* __restrict__ Cf, float* __restrict__ Cp1, float* __restrict__ Cp2,
         fp16* __restrict__ Ch,
         int K, int N)
{
    extern __shared__ char smem[];
    const uint32_t sbase = smem_to_u32(smem);

    const int tid  = threadIdx.x;
    const int lane = tid & 31;
    const int w    = tid >> 5;
    const int wr   = w & 3;
    const int wc   = w >> 2;
    const int bm   = blockIdx.x * BM;
    const int bn   = blockIdx.y * BN;
    const int Keff = K / SPLITK;
    const int kbase = (SPLITK > 1) ? (int)blockIdx.z * Keff : 0;

    float acc[2][8][4];
    #pragma unroll
    for (int i = 0; i < 2; i++)
        #pragma unroll
        for (int j = 0; j < 8; j++)
            #pragma unroll
            for (int q = 0; q < 4; q++) acc[i][j][q] = 0.f;

    const int NC = Keff / BKC;

    const int lrow = tid >> 1;
    const int lseg = (tid & 1) * 2;
    const uint32_t lsm = (uint32_t)(lrow * LDT + lseg * 8) * 2u;

    auto issue = [&](int c, int st) {
        int k0 = kbase + c * BKC;
        const fp16* sa = A  + (size_t)(bm + lrow) * K + k0 + lseg * 8;
        const fp16* sb = Bw + (size_t)(bn + lrow) * K + k0 + lseg * 8;
        uint32_t sbm = sbase + (uint32_t)st * STAGE_BYTES + lsm;
        cp_async16(sbm,                     sa);
        cp_async16(sbm + 16u,               sa + 8);
        cp_async16(sbm + TILE_BYTES,        sb);
        cp_async16(sbm + TILE_BYTES + 16u,  sb + 8);
    };

    issue(0, 0); cp_commit();
    if (NC > 1) { issue(1, 1); cp_commit(); }
    if (NC > 2) { issue(2, 2); cp_commit(); }

    const uint32_t aoff = (uint32_t)((wr * 32 + (lane & 15)) * LDT + (lane >> 4) * 8) * 2u;
    const uint32_t boff = (uint32_t)((wc * 64 + (lane & 7) + ((lane >> 4) & 1) * 8) * LDT
                                     + ((lane >> 3) & 1) * 8) * 2u;

    int st = 0;
    for (int c = 0; c < NC; c++) {
        if (c + 2 < NC)      cp_wait<2>();
        else if (c + 1 < NC) cp_wait<1>();
        else                 cp_wait<0>();
        __syncthreads();
        if (c + 3 < NC) {
            int nst = st + 3; if (nst >= NSTAGE) nst -= NSTAGE;
            issue(c + 3, nst);
            cp_commit();
        }

        const uint32_t sst = sbase + (uint32_t)st * STAGE_BYTES;
        #pragma unroll
        for (int ks = 0; ks < 2; ks++) {
            const uint32_t ko = (uint32_t)(ks * 16) * 2u;
            uint32_t av[2][4], bv[4][4];
            #pragma unroll
            for (int mt = 0; mt < 2; mt++) {
                uint32_t ro = aoff + (uint32_t)(mt * 16 * LDT) * 2u + ko;
                ldmx4(av[mt], sst + ro);
            }
            #pragma unroll
            for (int np = 0; np < 4; np++) {
                uint32_t ro = boff + (uint32_t)(np * 16 * LDT) * 2u + ko;
                ldmx4(bv[np], sst + TILE_BYTES + ro);
            }
            #pragma unroll
            for (int mt = 0; mt < 2; mt++)
                #pragma unroll
                for (int nt = 0; nt < 8; nt++) {
                    const int np = nt >> 1, half = (nt & 1) * 2;
                    mma16816(acc[mt][nt], av[mt], bv[np][half], bv[np][half + 1]);
                }
        }
        if (++st == NSTAGE) st = 0;
    }

    // epilogue
    const int g  = lane >> 2;
    const int tg = lane & 3;
    float* Cpart = Cf;
    if (SPLITK > 1) Cpart = (blockIdx.z == 0) ? Cf : (blockIdx.z == 1 ? Cp1 : Cp2);
    #pragma unroll
    for (int mt = 0; mt < 2; mt++) {
        #pragma unroll
        for (int nt = 0; nt < 8; nt++) {
            int col = bn + wc * 64 + nt * 8 + tg * 2;
            float2 bvv = (SPLITK > 1) ? make_float2(0.f, 0.f)
                                      : *(const float2*)(bias + col);
            #pragma unroll
            for (int half = 0; half < 2; half++) {
                int row = bm + wr * 32 + mt * 16 + g + half * 8;
                float v0 = acc[mt][nt][half * 2 + 0] + bvv.x;
                float v1 = acc[mt][nt][half * 2 + 1] + bvv.y;
                size_t idx = (size_t)row * N + col;
                if (GELU) { v0 = gelu_tanh(v0); v1 = gelu_tanh(v1); }
                if (OUTH) {
                    *(__half2*)(Ch + idx) = __floats2half2_rn(v0, v1);
                } else {
                    *(float2*)(Cpart + idx) = make_float2(v0, v1);
                }
            }
        }
    }
}

// ---------------------------------------------------------------------------
// Split-K3 reduction: o = p0 + p1 + p2 + bias + res   (f32, 768 cols)
// ---------------------------------------------------------------------------
__global__ void addred3_kernel(const float* __restrict__ p0,
                               const float* __restrict__ p1,
                               const float* __restrict__ p2,
                               const float* __restrict__ bias,
                               const float* __restrict__ res,
                               float* __restrict__ o)
{
    int i = (blockIdx.x * 256 + threadIdx.x);
    int col4 = i % (D_ / 4);
    float4 a = ((const float4*)p0)[i];
    float4 b = ((const float4*)p1)[i];
    float4 c = ((const float4*)p2)[i];
    float4 d = ((const float4*)bias)[col4];
    float4 r = ((const float4*)res)[i];
    float4 v;
    v.x = a.x + b.x + c.x + d.x + r.x;
    v.y = a.y + b.y + c.y + d.y + r.y;
    v.z = a.z + b.z + c.z + d.z + r.z;
    v.w = a.w + b.w + c.w + d.w + r.w;
    ((float4*)o)[i] = v;
}

// ---------------------------------------------------------------------------
// FAVOR+ features via tensor cores + fused chunk totals (k side).
// Block covers 32 rows = one scan chunk. proj = xs @ (wfeat*scale)^T done
// with mma.sync. K=64 -> smem row stride 72 halves (64 data + 8 pad).
// qk=1 blocks also produce kvt/kst from smem-resident phi/v.
// ---------------------------------------------------------------------------
#define PLD 72   // phi smem row stride in halves (144B)

__global__ void phi_kernel(const fp16* __restrict__ qkv,
                           const float* __restrict__ wfeat,
                           fp16* __restrict__ phiq,
                           fp16* __restrict__ phik,
                           float* __restrict__ kvt,
                           float* __restrict__ kst)
{
    const int sc = blockIdx.x;            // chunk index (32 rows)
    const int hy = blockIdx.y;
    const int b  = blockIdx.z;
    const int h  = hy % H_;
    const int qk = hy / H_;

    __shared__ fp16  xsh[32 * PLD];       // A tile rows (32 x 64 data)
    __shared__ fp16  wfh[64 * PLD];       // B tile rows (64 x 64 data, *scale)
    __shared__ float sqs[32];
    __shared__ float phs[32][64];         // phik values (k blocks only)
    __shared__ __half2 vs[32][32];        // v rows (k blocks only)

    const int t    = threadIdx.x;
    const int lane = t & 31;
    const int w    = t >> 5;

    const float scale = 0.3535533905932738f;
    const int s0   = sc * 32;
    const int col0 = qk * D_ + h * DH_;

    // load wfeat (idx = m*64 + d) -> wfh[m][d] * scale, fp16
    #pragma unroll
    for (int i = 0; i < 16; i++) {
        int idx = t + i * 256;
        wfh[(idx >> 6) * PLD + (idx & 63)] = __float2half_rn(wfeat[idx] * scale);
    }

    // load xs raw fp16: 1024 half2
    #pragma unroll
    for (int i = 0; i < 4; i++) {
        int idx = t + i * 256;
        int sl = idx >> 5, d2 = idx & 31;
        __half2 hv = ((const __half2*)(qkv + (size_t)(b * S_ + s0 + sl) * QKV_ + col0))[d2];
        ((__half2*)(xsh + sl * PLD))[d2] = hv;
    }
    if (qk) {
        const int colv = 2 * D_ + h * DH_;
        #pragma unroll
        for (int i = 0; i < 4; i++) {
            int idx = t + i * 256;
            int sl = idx >> 5, d2 = idx & 31;
            vs[sl][d2] = ((const __half2*)(qkv + (size_t)(b * S_ + s0 + sl) * QKV_ + colv))[d2];
        }
    }
    __syncthreads();

    {   // sq = 0.5*scale^2*|x|^2 per row (8 lanes per row)
        int sl = t >> 3, p = t & 7;
        float acc = 0.f;
        #pragma unroll
        for (int dd = 0; dd < 8; dd++) {
            float xv = __half2float(xsh[sl * PLD + p * 8 + dd]);
            acc = fmaf(xv, xv, acc);
        }
        acc += __shfl_xor_sync(0xffffffffu, acc, 1);
        acc += __shfl_xor_sync(0xffffffffu, acc, 2);
        acc += __shfl_xor_sync(0xffffffffu, acc, 4);
        if (p == 0) sqs[sl] = 0.5f * scale * scale * acc;
    }
    __syncthreads();

    // MMA projection: warp w -> m-tile (w&1), 16-col band ((w>>1)*16)
    const int mt = w & 1;
    const int nb = (w >> 1) * 16;
    const uint32_t sA = smem_to_u32(xsh);
    const uint32_t sB = smem_to_u32(wfh);
    const uint32_t aoff = (uint32_t)((mt * 16 + (lane & 15)) * PLD + (lane >> 4) * 8) * 2u;
    const uint32_t boff = (uint32_t)((nb + (lane & 7) + ((lane >> 4) & 1) * 8) * PLD
                                     + ((lane >> 3) & 1) * 8) * 2u;

    float c0[4] = {0.f, 0.f, 0.f, 0.f}, c1[4] = {0.f, 0.f, 0.f, 0.f};
    #pragma unroll
    for (int ks = 0; ks < 4; ks++) {
        uint32_t av[4], bv[4];
        ldmx4(av, sA + aoff + (uint32_t)(ks * 16) * 2u);
        ldmx4(bv, sB + boff + (uint32_t)(ks * 16) * 2u);
        mma16816(c0, av, bv[0], bv[1]);
        mma16816(c1, av, bv[2], bv[3]);
    }

    // epilogue: exp(acc - sq)/8 + eps; write global phi (+ phs for k blocks)
    const int g  = lane >> 2;
    const int tg = lane & 3;
    fp16* dst = qk ? phik : phiq;
    #pragma unroll
    for (int nt = 0; nt < 2; nt++) {
        const float* cc = nt ? c1 : c0;
        int col = nb + nt * 8 + tg * 2;
        #pragma unroll
        for (int half = 0; half < 2; half++) {
            int row = mt * 16 + g + half * 8;
            float p0 = __expf(cc[half * 2]     - sqs[row]) * 0.125f + 1e-6f;
            float p1 = __expf(cc[half * 2 + 1] - sqs[row]) * 0.125f + 1e-6f;
            *(__half2*)(dst + (size_t)((b * H_ + h) * S_ + s0 + row) * M_ + col) =
                __floats2half2_rn(p0, p1);
            if (qk) { phs[row][col] = p0; phs[row][col + 1] = p1; }
        }
    }

    if (!qk) return;

    __syncthreads();

    // chunk totals: thread (m = t&63, dg = t>>6) computes kvt[m][dg*16..+16), kst[m]
    const int m  = t & 63;
    const int dg = t >> 6;
    float kvacc[16];
    #pragma unroll
    for (int i = 0; i < 16; i++) kvacc[i] = 0.f;
    float ksacc = 0.f;

    #pragma unroll 4
    for (int sl = 0; sl < 32; sl++) {
        float p = phs[sl][m];
        ksacc += p;
        #pragma unroll
        for (int dd = 0; dd < 8; dd++) {
            float2 f = __half22float2(vs[sl][dg * 8 + dd]);
            kvacc[2 * dd]     = fmaf(p, f.x, kvacc[2 * dd]);
            kvacc[2 * dd + 1] = fmaf(p, f.y, kvacc[2 * dd + 1]);
        }
    }

    size_t base = ((size_t)((b * H_ + h) * NCH + sc) * M_ + m);
    #pragma unroll
    for (int i = 0; i < 16; i++)
        kvt[base * DH_ + dg * 16 + i] = kvacc[i];
    if (dg == 0) kst[base] = ksacc;
}

// ---------------------------------------------------------------------------
// Scan prefix: exclusive prefix over chunks. grid (B*H, 5):
// by<4 -> kvt float4 columns, by==4 -> kst.
// ---------------------------------------------------------------------------
__global__ void scan_pfx_kernel(float* __restrict__ kvt, float* __restrict__ kst)
{
    const int bh = blockIdx.x;
    const int by = blockIdx.y;
    const int t  = threadIdx.x;

    if (by < 4) {
        int e = by * 256 + t;             // float4 index within 1024 per chunk
        float4 run = make_float4(0.f, 0.f, 0.f, 0.f);
        #pragma unroll
        for (int ch = 0; ch < NCH; ch++) {
            float4* p = (float4*)(kvt + ((size_t)(bh * NCH + ch)) * (M_ * DH_)) + e;
            float4 v = *p;
            *p = run;
            run.x += v.x; run.y += v.y; run.z += v.z; run.w += v.w;
        }
    } else if (t < M_) {
        float run = 0.f;
        #pragma unroll
        for (int ch = 0; ch < NCH; ch++) {
            size_t idx = ((size_t)(bh * NCH + ch)) * M_ + t;
            float v = kst[idx];
            kst[idx] = run;
            run += v;
        }
    }
}

// ---------------------------------------------------------------------------
// Scan pass 2: local inclusive scan per (bh, chunk), seeded by exclusive
// prefix totals. fp16 in/out.
// ---------------------------------------------------------------------------
__global__ void scan_kernel(const fp16* __restrict__ qkv,
                            const fp16* __restrict__ phiq,
                            const fp16* __restrict__ phik,
                            const float* __restrict__ kvt,
                            const float* __restrict__ kst,
                            fp16* __restrict__ ao)
{
    const int bc = blockIdx.x;
    const int bh = bc / NCH;
    const int ch = bc % NCH;
    const int b  = bh / H_;
    const int h  = bh % H_;
    const int t  = threadIdx.x;
    const int d  = t >> 2;
    const int mg = t & 3;

    float kv[16], ks[16];
    size_t sbase = (size_t)bc * M_ + mg * 16;
    #pragma unroll
    for (int i = 0; i < 16; i++) {
        kv[i] = kvt[(sbase + i) * DH_ + d];
        ks[i] = kst[sbase + i];
    }

    const int s0 = ch * CHL;
    const fp16* pq = phiq + (size_t)bh * S_ * M_ + (size_t)s0 * M_ + mg * 16;
    const fp16* pk = phik + (size_t)bh * S_ * M_ + (size_t)s0 * M_ + mg * 16;
    const fp16* pv = qkv  + (size_t)(b * S_ + s0) * QKV_ + 2 * D_ + h * DH_ + d;
    size_t obase = (size_t)(b * S_ + s0) * D_ + h * DH_ + d;

    for (int s = 0; s < CHL; s++) {
        float kr[16], qr[16];
        ld16h(kr, pk);
        ld16h(qr, pq);
        float vv = __half2float(*pv);

        float num = 0.f, den = 0.f;
        #pragma unroll
        for (int i = 0; i < 16; i++) {
            kv[i] = fmaf(kr[i], vv, kv[i]);
            ks[i] += kr[i];
            num = fmaf(qr[i], kv[i], num);
            den = fmaf(qr[i], ks[i], den);
        }
        num += __shfl_xor_sync(0xffffffffu, num, 1);
        den += __shfl_xor_sync(0xffffffffu, den, 1);
        num += __shfl_xor_sync(0xffffffffu, num, 2);
        den += __shfl_xor_sync(0xffffffffu, den, 2);

        if (mg == 0) ao[obase] = __float2half_rn(num / den);

        pq += M_; pk += M_; pv += QKV_; obase += D_;
    }
}

// ---------------------------------------------------------------------------
// Launch
// ---------------------------------------------------------------------------
extern "C" void kernel_launch(void* const* d_in, const int* in_sizes, int n_in,
                              void* d_out, int out_size)
{
    const float* x      = (const float*)d_in[0];
    const float* ln1_g  = (const float*)d_in[1];
    const float* ln1_b  = (const float*)d_in[2];
    const float* w_attn = (const float*)d_in[3];
    const float* b_attn = (const float*)d_in[4];
    const float* w_feat = (const float*)d_in[5];
    const float* w_proj = (const float*)d_in[6];
    const float* b_proj = (const float*)d_in[7];
    const float* ln2_g  = (const float*)d_in[8];
    const float* ln2_b  = (const float*)d_in[9];
    const float* w_fc   = (const float*)d_in[10];
    const float* b_fc   = (const float*)d_in[11];
    const float* w_out  = (const float*)d_in[12];
    const float* b_out  = (const float*)d_in[13];
    float* out = (float*)d_out;

    fp16 *a, *at, *hh, *ff, *wA, *wP, *wF, *wO, *qkvh, *phiq, *phik;
    float *x1, *kvt, *kst, *sp0, *sp1, *sp2;
    cudaGetSymbolAddress((void**)&a,    g_a);
    cudaGetSymbolAddress((void**)&qkvh, g_qkv);
    cudaGetSymbolAddress((void**)&phiq, g_phiq);
    cudaGetSymbolAddress((void**)&phik, g_phik);
    cudaGetSymbolAddress((void**)&at,   g_at);
    cudaGetSymbolAddress((void**)&x1,   g_x1);
    cudaGetSymbolAddress((void**)&hh,   g_h);
    cudaGetSymbolAddress((void**)&ff,   g_ff);
    cudaGetSymbolAddress((void**)&sp0,  g_sp0);
    cudaGetSymbolAddress((void**)&sp1,  g_sp1);
    cudaGetSymbolAddress((void**)&sp2,  g_sp2);
    cudaGetSymbolAddress((void**)&kvt,  g_kvt);
    cudaGetSymbolAddress((void**)&kst,  g_kst);
    cudaGetSymbolAddress((void**)&wA,   g_wA);
    cudaGetSymbolAddress((void**)&wP,   g_wP);
    cudaGetSymbolAddress((void**)&wF,   g_wF);
    cudaGetSymbolAddress((void**)&wO,   g_wO);

    cudaFuncSetAttribute(gemm_mma<0,1,1>, cudaFuncAttributeMaxDynamicSharedMemorySize, GEMM_SMEM);
    cudaFuncSetAttribute(gemm_mma<0,0,3>, cudaFuncAttributeMaxDynamicSharedMemorySize, GEMM_SMEM);
    cudaFuncSetAttribute(gemm_mma<1,1,1>, cudaFuncAttributeMaxDynamicSharedMemorySize, GEMM_SMEM);

    // 0. fused weight transpose+convert + LN1
    prep_kernel<<<6912 + NT_, 256>>>(w_attn, w_proj, w_fc, w_out,
                                     wA, wP, wF, wO, x, ln1_g, ln1_b, a);

    // 1. qkv = a @ w_attn + b_attn   [2048 x 2304], fp16 out
    gemm_mma<0,1,1><<<dim3(NT_/BM, QKV_/BN), 256, GEMM_SMEM>>>(
        a, wA, b_attn, nullptr, nullptr, nullptr, qkvh, D_, QKV_);

    // 2. FAVOR+ features (tensor-core) + fused chunk totals (k blocks)
    phi_kernel<<<dim3(S_/32, H_*2, B_), 256>>>(qkvh, w_feat, phiq, phik, kvt, kst);

    // 3. chunked causal scan (parallel prefix -> seeded local scan)
    scan_pfx_kernel<<<dim3(B_*H_, 5), 256>>>(kvt, kst);
    scan_kernel<<<B_*H_*NCH, 256>>>(qkvh, phiq, phik, kvt, kst, at);

    // 4. attn @ w_proj  (split-K3, reduce fused with LN2)
    gemm_mma<0,0,3><<<dim3(NT_/BM, D_/BN, 3), 256, GEMM_SMEM>>>(
        at, wP, b_proj, sp0, sp1, sp2, nullptr, D_, D_);

    // 5. fused: x1 = p0+p1+p2+bias+x ; h = LN2(x1) (fp16)
    addln_kernel<<<NT_, 256>>>(sp0, sp1, sp2, b_proj, x, ln2_g, ln2_b, x1, hh);

    // 6. ff = gelu(h @ w_fc + b_fc)   [2048 x 3072], fp16 out
    gemm_mma<1,1,1><<<dim3(NT_/BM, DFF_/BN), 256, GEMM_SMEM>>>(
        hh, wF, b_fc, nullptr, nullptr, nullptr, ff, D_, DFF_);

    // 7. out = x1 + ff @ w_out + b_out  (split-K3 + reduce)
    gemm_mma<0,0,3><<<dim3(NT_/BM, D_/BN, 3), 256, GEMM_SMEM>>>(
        ff, wO, b_out, sp0, sp1, sp2, nullptr, DFF_, D_);
    addred3_kernel<<<(NT_*D_/4)/256, 256>>>(sp0, sp1, sp2, b_out, x1, out);
}